// round 1
// baseline (speedup 1.0000x reference)
#include <cuda_runtime.h>
#include <math.h>

#define Bb   4
#define Dm   768
#define Tt   14
#define Np   196           // tokens per image (14*14)
#define Lp   256           // pixels per patch (16*16)
#define NH   12
#define HD   64
#define FFD  3072
#define BN   (Bb*Np)       // 784
#define HW   224
#define CHW  (HW*HW)       // 50176

// ---------------- scratch (no allocations allowed) ----------------
__device__ float g_q  [BN*Dm];        // token means (B*N, 768)
__device__ float g_qp [BN*Dm];        // q projection
__device__ float g_qkw[BN*NH*Dm];     // per-head folded query (scale folded in)
__device__ float g_avn[BN*NH*Dm];     // normalized attn-weighted kv
__device__ float g_ctx[BN*Dm];
__device__ float g_o1 [BN*Dm];
__device__ float g_h1 [BN*FFD];

// ---------------- kernel 1: token means ----------------
// block = (b, dd, t1); 224 threads; fully coalesced reads of x
__global__ void mean_kernel(const float* __restrict__ x) {
    int bid = blockIdx.x;
    int t1 = bid % Tt;
    int dd = (bid / Tt) % Dm;
    int b  = bid / (Tt * Dm);
    const float* xp = x + ((size_t)b*Dm + dd)*CHW + (size_t)t1*16*HW;
    int j = threadIdx.x;            // 0..223 (column)
    float s = 0.f;
    #pragma unroll
    for (int r = 0; r < 16; r++) s += xp[(size_t)r*HW + j];
    __shared__ float cs[224];
    cs[j] = s;
    __syncthreads();
    if (j < Tt) {
        float t = 0.f;
        #pragma unroll
        for (int k = 0; k < 16; k++) t += cs[j*16 + k];
        g_q[((size_t)b*Np + t1*Tt + j)*Dm + dd] = t * (1.0f/256.0f);
    }
}

// ---------------- generic fp32 GEMM: C[m,n] = alpha*sum_k A[m,k]*B(k,n) + bias[n] ----------------
// transB=1: B indexed [n*ldb + k]  (B is N x K row-major, i.e. C = A @ B^T)
// transB=0: B indexed [k*ldb + n]  (B is K x N row-major)
// 64x64 block tile, K-chunks of 16, 4x4 per thread, 256 threads.
__global__ void gemm64(const float* __restrict__ A, const float* __restrict__ Bm,
                       const float* __restrict__ bias, float* __restrict__ C,
                       int M, int N, int K, int lda, int ldb, int ldc,
                       float alpha, int transB, int silu)
{
    __shared__ float As[16][64];
    __shared__ float Bs[16][64];
    int m0 = blockIdx.y * 64, n0 = blockIdx.x * 64;
    int tid = threadIdx.x;
    int tm = tid >> 4, tn = tid & 15;
    float acc[4][4] = {};

    for (int k0 = 0; k0 < K; k0 += 16) {
        #pragma unroll
        for (int i = 0; i < 4; i++) {
            int e = tid + 256*i;         // 0..1023
            int mm = e >> 4, kk = e & 15;
            float v = 0.f;
            if (m0 + mm < M) v = A[(size_t)(m0+mm)*lda + k0 + kk];
            As[kk][mm] = v;
        }
        #pragma unroll
        for (int i = 0; i < 4; i++) {
            int e = tid + 256*i;
            float v = 0.f;
            int nn, kk;
            if (!transB) { kk = e >> 6; nn = e & 63; if (n0 + nn < N) v = Bm[(size_t)(k0+kk)*ldb + n0 + nn]; }
            else         { nn = e >> 4; kk = e & 15; if (n0 + nn < N) v = Bm[(size_t)(n0+nn)*ldb + k0 + kk]; }
            Bs[kk][nn] = v;
        }
        __syncthreads();
        #pragma unroll
        for (int kk = 0; kk < 16; kk++) {
            float a[4], bb[4];
            #pragma unroll
            for (int i = 0; i < 4; i++) a[i]  = As[kk][tm*4 + i];
            #pragma unroll
            for (int i = 0; i < 4; i++) bb[i] = Bs[kk][tn*4 + i];
            #pragma unroll
            for (int i = 0; i < 4; i++)
                #pragma unroll
                for (int j = 0; j < 4; j++) acc[i][j] += a[i]*bb[j];
        }
        __syncthreads();
    }
    #pragma unroll
    for (int i = 0; i < 4; i++) {
        int m = m0 + tm*4 + i;
        if (m >= M) continue;
        #pragma unroll
        for (int j = 0; j < 4; j++) {
            int n = n0 + tn*4 + j;
            if (n >= N) continue;
            float v = acc[i][j]*alpha + (bias ? bias[n] : 0.f);
            if (silu) v = v / (1.f + __expf(-v));
            C[(size_t)m*ldc + n] = v;
        }
    }
}

// ---------------- kernel 3: fused attention ----------------
// One CTA per token (b,n). Streams the 16x16x768 patch of x once.
// scores[h][l] = qkw[h] . kv[l]  (scale already folded into qkw)
// online (no-max) softmax: denom[h] += exp(s);  av[h] += exp(s)*kv[l]
// av accumulators live in registers (12 heads x 3 columns per thread).
__global__ void attn_kernel(const float* __restrict__ x) {
    extern __shared__ float sm[];
    float* qkw_s = sm;                  // 12*768 = 9216
    float* tile  = sm + 9216;           // 8*768  = 6144
    float* e_s   = tile + 6144;         // 12*8   = 96
    float* denom = e_s + 96;            // 12

    int bn = blockIdx.x;
    int b = bn / Np, n = bn % Np;
    int t1 = n / Tt, t2 = n % Tt;
    const float* xp = x + (size_t)b*Dm*CHW + (size_t)(t1*16)*HW + t2*16;

    int tid  = threadIdx.x;
    int lane = tid & 31, w = tid >> 5;

    for (int i = tid; i < NH*Dm; i += 256) qkw_s[i] = g_qkw[(size_t)bn*NH*Dm + i];
    if (tid < NH) denom[tid] = 0.f;

    float acc[NH][3];
    #pragma unroll
    for (int h = 0; h < NH; h++) { acc[h][0]=0.f; acc[h][1]=0.f; acc[h][2]=0.f; }

    for (int lc = 0; lc < 32; lc++) {
        __syncthreads();   // protect tile/e_s from previous iteration readers
        // load 8 kv rows (= 24 channels of the patch)
        #pragma unroll
        for (int i = 0; i < 24; i++) {
            int e  = tid + 256*i;             // 0..6143
            int r  = e / 768, cc = e - r*768;
            int flat = (lc*8 + r)*768 + cc;   // = dd*256 + g1*16 + g2
            int dd = flat >> 8;
            int g1 = (flat >> 4) & 15, g2 = flat & 15;
            tile[e] = xp[(size_t)dd*CHW + g1*HW + g2];
        }
        __syncthreads();
        // scores: warp w handles kv row w
        {
            float kvreg[24];
            #pragma unroll
            for (int i = 0; i < 24; i++) kvreg[i] = tile[w*768 + lane + 32*i];
            #pragma unroll
            for (int h = 0; h < NH; h++) {
                float s = 0.f;
                #pragma unroll
                for (int i = 0; i < 24; i++) s += qkw_s[h*768 + lane + 32*i] * kvreg[i];
                #pragma unroll
                for (int o = 16; o > 0; o >>= 1) s += __shfl_xor_sync(0xffffffffu, s, o);
                if (lane == 0) e_s[h*8 + w] = __expf(s);
            }
        }
        __syncthreads();
        // denominator accumulation
        if (tid < NH) {
            float d = 0.f;
            #pragma unroll
            for (int r = 0; r < 8; r++) d += e_s[tid*8 + r];
            denom[tid] += d;
        }
        // av accumulation: thread owns columns {tid, tid+256, tid+512}
        #pragma unroll
        for (int r = 0; r < 8; r++) {
            float v0 = tile[r*768 + tid];
            float v1 = tile[r*768 + tid + 256];
            float v2 = tile[r*768 + tid + 512];
            #pragma unroll
            for (int h = 0; h < NH; h++) {
                float e = e_s[h*8 + r];
                acc[h][0] += e*v0; acc[h][1] += e*v1; acc[h][2] += e*v2;
            }
        }
    }
    __syncthreads();
    #pragma unroll
    for (int h = 0; h < NH; h++) {
        float inv = 1.f / denom[h];
        size_t base = (size_t)bn*NH*Dm + h*768;
        g_avn[base + tid]       = acc[h][0]*inv;
        g_avn[base + tid + 256] = acc[h][1]*inv;
        g_avn[base + tid + 512] = acc[h][2]*inv;
    }
}

// ---------------- host orchestration ----------------
extern "C" void kernel_launch(void* const* d_in, const int* in_sizes, int n_in,
                              void* d_out, int out_size)
{
    const float* x     = (const float*)d_in[0];
    const float* w_in  = (const float*)d_in[1];
    const float* b_in  = (const float*)d_in[2];
    const float* w_out = (const float*)d_in[3];
    const float* b_out = (const float*)d_in[4];
    const float* w_fc1 = (const float*)d_in[5];
    const float* b_fc1 = (const float*)d_in[6];
    const float* w_fc2 = (const float*)d_in[7];
    const float* b_fc2 = (const float*)d_in[8];
    float* y = (float*)d_out;

    float *q, *qp, *qkw, *avn, *ctx, *o1, *h1;
    cudaGetSymbolAddress((void**)&q,   g_q);
    cudaGetSymbolAddress((void**)&qp,  g_qp);
    cudaGetSymbolAddress((void**)&qkw, g_qkw);
    cudaGetSymbolAddress((void**)&avn, g_avn);
    cudaGetSymbolAddress((void**)&ctx, g_ctx);
    cudaGetSymbolAddress((void**)&o1,  g_o1);
    cudaGetSymbolAddress((void**)&h1,  g_h1);

    // 1. token means
    mean_kernel<<<Bb*Dm*Tt, 224>>>(x);

    // 2. qp = q @ wq^T + bq          (784 x 768, K=768)
    {
        dim3 grid((Dm+63)/64, (BN+63)/64);
        gemm64<<<grid, 256>>>(q, w_in, b_in, qp,
                              BN, Dm, Dm, Dm, Dm, Dm, 1.f, 1, 0);
    }

    // 3. qkw[.,h,:] = (qp_h @ wk_h) * scale   (12 GEMMs: 784 x 768, K=64)
    {
        const float scale = 0.125f;   // 1/sqrt(64)
        dim3 grid((Dm+63)/64, (BN+63)/64);
        for (int h = 0; h < NH; h++) {
            gemm64<<<grid, 256>>>(qp + h*HD,
                                  w_in + (size_t)Dm*Dm + (size_t)h*HD*Dm,
                                  nullptr,
                                  qkw + h*Dm,
                                  BN, Dm, HD, Dm, Dm, NH*Dm, scale, 0, 0);
        }
    }

    // 4. fused attention (single pass over x)
    {
        static const size_t smem = (9216 + 6144 + 96 + 12) * sizeof(float);
        cudaFuncSetAttribute(attn_kernel, cudaFuncAttributeMaxDynamicSharedMemorySize, (int)smem);
        attn_kernel<<<BN, 256, smem>>>(x);
    }

    // 5. ctx_h = avn_h @ wv_h^T + bv_h   (12 GEMMs: 784 x 64, K=768)
    {
        dim3 grid(1, (BN+63)/64);
        for (int h = 0; h < NH; h++) {
            gemm64<<<grid, 256>>>(avn + h*Dm,
                                  w_in + (size_t)2*Dm*Dm + (size_t)h*HD*Dm,
                                  b_in + 2*Dm + h*HD,
                                  ctx + h*HD,
                                  BN, HD, Dm, NH*Dm, Dm, Dm, 1.f, 1, 0);
        }
    }

    // 6. o1 = ctx @ w_out^T + b_out
    {
        dim3 grid((Dm+63)/64, (BN+63)/64);
        gemm64<<<grid, 256>>>(ctx, w_out, b_out, o1,
                              BN, Dm, Dm, Dm, Dm, Dm, 1.f, 1, 0);
    }

    // 7. h1 = silu(o1 @ w_fc1^T + b_fc1)
    {
        dim3 grid((FFD+63)/64, (BN+63)/64);
        gemm64<<<grid, 256>>>(o1, w_fc1, b_fc1, h1,
                              BN, FFD, Dm, Dm, Dm, FFD, 1.f, 1, 1);
    }

    // 8. y = h1 @ w_fc2^T + b_fc2
    {
        dim3 grid((Dm+63)/64, (BN+63)/64);
        gemm64<<<grid, 256>>>(h1, w_fc2, b_fc2, y,
                              BN, Dm, FFD, FFD, FFD, Dm, 1.f, 1, 0);
    }
}

// round 2
// speedup vs baseline: 2.2365x; 2.2365x over previous
#include <cuda_runtime.h>
#include <math.h>

#define Bb   4
#define Dm   768
#define Tt   14
#define Np   196           // tokens per image (14*14)
#define NH   12
#define HD   64
#define FFD  3072
#define BN   (Bb*Np)       // 784
#define HW   224
#define CHW  (HW*HW)       // 50176

// ---------------- scratch (no allocations allowed) ----------------
__device__ float g_q  [BN*Dm];        // token means (B*N, 768)
__device__ float g_qp [BN*Dm];        // q projection
__device__ float g_qkw[BN*NH*Dm];     // per-head folded query (scale folded in)
__device__ float g_avn[BN*NH*Dm];     // normalized attn-weighted kv
__device__ float g_ctx[BN*Dm];
__device__ float g_o1 [BN*Dm];
__device__ float g_h1 [BN*FFD];

// ---------------- kernel 1: token means ----------------
__global__ void mean_kernel(const float* __restrict__ x) {
    int bid = blockIdx.x;
    int t1 = bid % Tt;
    int dd = (bid / Tt) % Dm;
    int b  = bid / (Tt * Dm);
    const float* xp = x + ((size_t)b*Dm + dd)*CHW + (size_t)t1*16*HW;
    int j = threadIdx.x;            // 0..223 (column)
    float s = 0.f;
    #pragma unroll
    for (int r = 0; r < 16; r++) s += xp[(size_t)r*HW + j];
    __shared__ float cs[224];
    cs[j] = s;
    __syncthreads();
    if (j < Tt) {
        float t = 0.f;
        #pragma unroll
        for (int k = 0; k < 16; k++) t += cs[j*16 + k];
        g_q[((size_t)b*Np + t1*Tt + j)*Dm + dd] = t * (1.0f/256.0f);
    }
}

// ---------------- batched fp32 GEMM ----------------
// C[m,n] = alpha * sum_k A[m,k] * B(k,n) + bias[n]   (per head-slice via blockIdx.z)
// transB=1: B indexed [n*ldb + k];  transB=0: B indexed [k*ldb + n]
// 128x64 tile, K-chunks of 16, 8x4 per thread, 256 threads, float4 loads.
__global__ __launch_bounds__(256) void gemm128(
    const float* __restrict__ A, const float* __restrict__ Bm,
    const float* __restrict__ bias, float* __restrict__ C,
    int M, int N, int K, int lda, int ldb, int ldc,
    int sA, int sB, int sBias, int sC,
    float alpha, int transB, int silu)
{
    int h = blockIdx.z;
    A += (size_t)h * sA;
    Bm += (size_t)h * sB;
    C += (size_t)h * sC;
    const float* biasp = bias ? bias + (size_t)h * sBias : nullptr;

    __shared__ float As[16][132];   // padded
    __shared__ float Bs[16][68];    // padded (68 % 4 == 0 keeps float4 stores aligned)

    int m0 = blockIdx.y * 128, n0 = blockIdx.x * 64;
    int tid = threadIdx.x;
    int tm = tid >> 4;              // 0..15 -> rows tm*8..tm*8+7
    int tn = tid & 15;              // 0..15 -> cols tn*4..tn*4+3
    float acc[8][4] = {};

    for (int k0 = 0; k0 < K; k0 += 16) {
        // stage A: 128 rows x 16 k  (512 float4, 2 per thread)
        #pragma unroll
        for (int i = 0; i < 2; i++) {
            int idx = tid + 256*i;
            int row = idx >> 2, seg = idx & 3;
            float4 v = make_float4(0.f, 0.f, 0.f, 0.f);
            if (m0 + row < M)
                v = *(const float4*)(A + (size_t)(m0+row)*lda + k0 + seg*4);
            As[seg*4+0][row] = v.x;
            As[seg*4+1][row] = v.y;
            As[seg*4+2][row] = v.z;
            As[seg*4+3][row] = v.w;
        }
        // stage B: 64 cols x 16 k
        if (!transB) {
            int kk = tid >> 4, sn = tid & 15;
            float4 v = make_float4(0.f, 0.f, 0.f, 0.f);
            if (n0 + sn*4 < N)
                v = *(const float4*)(Bm + (size_t)(k0+kk)*ldb + n0 + sn*4);
            *(float4*)&Bs[kk][sn*4] = v;
        } else {
            int nn = tid >> 2, seg = tid & 3;
            float4 v = make_float4(0.f, 0.f, 0.f, 0.f);
            if (n0 + nn < N)
                v = *(const float4*)(Bm + (size_t)(n0+nn)*ldb + k0 + seg*4);
            Bs[seg*4+0][nn] = v.x;
            Bs[seg*4+1][nn] = v.y;
            Bs[seg*4+2][nn] = v.z;
            Bs[seg*4+3][nn] = v.w;
        }
        __syncthreads();
        #pragma unroll
        for (int kk = 0; kk < 16; kk++) {
            float a[8], bb[4];
            #pragma unroll
            for (int i = 0; i < 8; i++) a[i] = As[kk][tm*8 + i];
            #pragma unroll
            for (int j = 0; j < 4; j++) bb[j] = Bs[kk][tn*4 + j];
            #pragma unroll
            for (int i = 0; i < 8; i++)
                #pragma unroll
                for (int j = 0; j < 4; j++) acc[i][j] += a[i]*bb[j];
        }
        __syncthreads();
    }

    float4 bv = make_float4(0.f, 0.f, 0.f, 0.f);
    if (biasp && n0 + tn*4 < N) bv = *(const float4*)(biasp + n0 + tn*4);
    #pragma unroll
    for (int i = 0; i < 8; i++) {
        int m = m0 + tm*8 + i;
        if (m >= M) continue;
        if (n0 + tn*4 >= N) continue;
        float4 o;
        o.x = acc[i][0]*alpha + bv.x;
        o.y = acc[i][1]*alpha + bv.y;
        o.z = acc[i][2]*alpha + bv.z;
        o.w = acc[i][3]*alpha + bv.w;
        if (silu) {
            o.x = o.x / (1.f + __expf(-o.x));
            o.y = o.y / (1.f + __expf(-o.y));
            o.z = o.z / (1.f + __expf(-o.z));
            o.w = o.w / (1.f + __expf(-o.w));
        }
        *(float4*)(C + (size_t)m*ldc + n0 + tn*4) = o;
    }
}

// ---------------- fused attention ----------------
// One CTA per token (b,n). Streams the 16x16x768 patch of x once.
__global__ void attn_kernel(const float* __restrict__ x) {
    extern __shared__ float sm[];
    float* qkw_s = sm;                  // 12*768 = 9216
    float* tile  = sm + 9216;           // 8*768  = 6144
    float* e_s   = tile + 6144;         // 12*8   = 96
    float* denom = e_s + 96;            // 12

    int bn = blockIdx.x;
    int b = bn / Np, n = bn % Np;
    int t1 = n / Tt, t2 = n % Tt;
    const float* xp = x + (size_t)b*Dm*CHW + (size_t)(t1*16)*HW + t2*16;

    int tid  = threadIdx.x;
    int lane = tid & 31, w = tid >> 5;

    for (int i = tid; i < NH*Dm; i += 256) qkw_s[i] = g_qkw[(size_t)bn*NH*Dm + i];
    if (tid < NH) denom[tid] = 0.f;

    float acc[NH][3];
    #pragma unroll
    for (int h = 0; h < NH; h++) { acc[h][0]=0.f; acc[h][1]=0.f; acc[h][2]=0.f; }

    for (int lc = 0; lc < 32; lc++) {
        __syncthreads();
        #pragma unroll
        for (int i = 0; i < 24; i++) {
            int e  = tid + 256*i;             // 0..6143
            int r  = e / 768, cc = e - r*768;
            int flat = (lc*8 + r)*768 + cc;   // = dd*256 + g1*16 + g2
            int dd = flat >> 8;
            int g1 = (flat >> 4) & 15, g2 = flat & 15;
            tile[e] = xp[(size_t)dd*CHW + g1*HW + g2];
        }
        __syncthreads();
        {
            float kvreg[24];
            #pragma unroll
            for (int i = 0; i < 24; i++) kvreg[i] = tile[w*768 + lane + 32*i];
            #pragma unroll
            for (int h = 0; h < NH; h++) {
                float s = 0.f;
                #pragma unroll
                for (int i = 0; i < 24; i++) s += qkw_s[h*768 + lane + 32*i] * kvreg[i];
                #pragma unroll
                for (int o = 16; o > 0; o >>= 1) s += __shfl_xor_sync(0xffffffffu, s, o);
                if (lane == 0) e_s[h*8 + w] = __expf(s);
            }
        }
        __syncthreads();
        if (tid < NH) {
            float d = 0.f;
            #pragma unroll
            for (int r = 0; r < 8; r++) d += e_s[tid*8 + r];
            denom[tid] += d;
        }
        #pragma unroll
        for (int r = 0; r < 8; r++) {
            float v0 = tile[r*768 + tid];
            float v1 = tile[r*768 + tid + 256];
            float v2 = tile[r*768 + tid + 512];
            #pragma unroll
            for (int h = 0; h < NH; h++) {
                float e = e_s[h*8 + r];
                acc[h][0] += e*v0; acc[h][1] += e*v1; acc[h][2] += e*v2;
            }
        }
    }
    __syncthreads();
    #pragma unroll
    for (int h = 0; h < NH; h++) {
        float inv = 1.f / denom[h];
        size_t base = (size_t)bn*NH*Dm + h*768;
        g_avn[base + tid]       = acc[h][0]*inv;
        g_avn[base + tid + 256] = acc[h][1]*inv;
        g_avn[base + tid + 512] = acc[h][2]*inv;
    }
}

// ---------------- host orchestration ----------------
extern "C" void kernel_launch(void* const* d_in, const int* in_sizes, int n_in,
                              void* d_out, int out_size)
{
    const float* x     = (const float*)d_in[0];
    const float* w_in  = (const float*)d_in[1];
    const float* b_in  = (const float*)d_in[2];
    const float* w_out = (const float*)d_in[3];
    const float* b_out = (const float*)d_in[4];
    const float* w_fc1 = (const float*)d_in[5];
    const float* b_fc1 = (const float*)d_in[6];
    const float* w_fc2 = (const float*)d_in[7];
    const float* b_fc2 = (const float*)d_in[8];
    float* y = (float*)d_out;

    float *q, *qp, *qkw, *avn, *ctx, *o1, *h1;
    cudaGetSymbolAddress((void**)&q,   g_q);
    cudaGetSymbolAddress((void**)&qp,  g_qp);
    cudaGetSymbolAddress((void**)&qkw, g_qkw);
    cudaGetSymbolAddress((void**)&avn, g_avn);
    cudaGetSymbolAddress((void**)&ctx, g_ctx);
    cudaGetSymbolAddress((void**)&o1,  g_o1);
    cudaGetSymbolAddress((void**)&h1,  g_h1);

    // 1. token means
    mean_kernel<<<Bb*Dm*Tt, 224>>>(x);

    // 2. qp = q @ wq^T + bq          (784 x 768, K=768)
    gemm128<<<dim3(12, 7, 1), 256>>>(q, w_in, b_in, qp,
        BN, Dm, Dm, Dm, Dm, Dm, 0, 0, 0, 0, 1.f, 1, 0);

    // 3. qkw[.,h,:] = (qp_h @ wk_h) * scale   (batched over h: 784 x 768, K=64)
    gemm128<<<dim3(12, 7, NH), 256>>>(qp, w_in + (size_t)Dm*Dm, nullptr, qkw,
        BN, Dm, HD, Dm, Dm, NH*Dm,
        HD, HD*Dm, 0, Dm, 0.125f, 0, 0);

    // 4. fused attention (single pass over x)
    {
        static const size_t smem = (9216 + 6144 + 96 + 12) * sizeof(float);
        cudaFuncSetAttribute(attn_kernel, cudaFuncAttributeMaxDynamicSharedMemorySize, (int)smem);
        attn_kernel<<<BN, 256, smem>>>(x);
    }

    // 5. ctx_h = avn_h @ wv_h^T + bv_h   (batched over h: 784 x 64, K=768)
    gemm128<<<dim3(1, 7, NH), 256>>>(avn, w_in + (size_t)2*Dm*Dm, b_in + 2*Dm, ctx,
        BN, HD, Dm, NH*Dm, Dm, Dm,
        Dm, HD*Dm, HD, HD, 1.f, 1, 0);

    // 6. o1 = ctx @ w_out^T + b_out
    gemm128<<<dim3(12, 7, 1), 256>>>(ctx, w_out, b_out, o1,
        BN, Dm, Dm, Dm, Dm, Dm, 0, 0, 0, 0, 1.f, 1, 0);

    // 7. h1 = silu(o1 @ w_fc1^T + b_fc1)
    gemm128<<<dim3(48, 7, 1), 256>>>(o1, w_fc1, b_fc1, h1,
        BN, FFD, Dm, Dm, Dm, FFD, 0, 0, 0, 0, 1.f, 1, 1);

    // 8. y = h1 @ w_fc2^T + b_fc2
    gemm128<<<dim3(12, 7, 1), 256>>>(h1, w_fc2, b_fc2, y,
        BN, Dm, FFD, FFD, FFD, Dm, 0, 0, 0, 0, 1.f, 1, 0);
}

// round 3
// speedup vs baseline: 2.9721x; 1.3289x over previous
#include <cuda_runtime.h>
#include <math.h>
#include <stdint.h>

#define Bb   4
#define Dm   768
#define Tt   14
#define Np   196
#define NH   12
#define HD   64
#define FFD  3072
#define BN   (Bb*Np)       // 784
#define HW   224
#define CHW  (HW*HW)       // 50176

// ---------------- scratch ----------------
__device__ float g_q  [BN*Dm];
__device__ float g_qp [BN*Dm];
__device__ float g_qkw[BN*NH*Dm];
__device__ float g_avn[BN*NH*Dm];
__device__ float g_ctx[BN*Dm];
__device__ float g_o1 [BN*Dm];
__device__ float g_h1 [BN*FFD];
__device__ float g_part[4*BN*Dm];      // split-K partials (max KS=4, N=768)

// ---------------- kernel 1: token means ----------------
__global__ void mean_kernel(const float* __restrict__ x) {
    int bid = blockIdx.x;
    int t1 = bid % Tt;
    int dd = (bid / Tt) % Dm;
    int b  = bid / (Tt * Dm);
    const float* xp = x + ((size_t)b*Dm + dd)*CHW + (size_t)t1*16*HW;
    int j = threadIdx.x;
    float s = 0.f;
    #pragma unroll
    for (int r = 0; r < 16; r++) s += xp[(size_t)r*HW + j];
    __shared__ float cs[224];
    cs[j] = s;
    __syncthreads();
    if (j < Tt) {
        float t = 0.f;
        #pragma unroll
        for (int k = 0; k < 16; k++) t += cs[j*16 + k];
        g_q[((size_t)b*Np + t1*Tt + j)*Dm + dd] = t * (1.0f/256.0f);
    }
}

// ---------------- 64x64 SIMT GEMM, 128 threads, 4x8 micro, split-K/head via z ----------------
// C[m,n] = alpha * sum_k A[m,k]*B(k,n) (+ bias[n], optional silu, only when KS==1)
// z = h*KS + ks.  A += h*sAh + ks*Ksub;  B += h*sBh + ks*Ksub*(transB?1:ldb);
// C += h*sCh + ks*sCk.
template<bool TRANSB>
__global__ __launch_bounds__(128) void gemm64(
    const float* __restrict__ A, const float* __restrict__ Bm,
    const float* __restrict__ bias, float* __restrict__ C,
    int M, int N, int Ksub, int lda, int ldb, int ldc,
    int KS, int sAh, int sBh, int sCh, int sCk,
    float alpha, int silu)
{
    int z = blockIdx.z;
    int h = z / KS, ks = z - h*KS;
    A += (size_t)h*sAh + (size_t)ks*Ksub;
    Bm += (size_t)h*sBh + (TRANSB ? (size_t)ks*Ksub : (size_t)ks*Ksub*ldb);
    C += (size_t)h*sCh + (size_t)ks*sCk;

    __shared__ float As[16][68];
    __shared__ float Bs[16][68];

    int m0 = blockIdx.y*64, n0 = blockIdx.x*64;
    int tid = threadIdx.x;
    int tm = tid >> 3;        // 0..15 -> rows tm*4..+3
    int tn = tid & 7;         // 0..7  -> cols tn*8..+7
    float acc[4][8] = {};

    for (int k0 = 0; k0 < Ksub; k0 += 16) {
        #pragma unroll
        for (int i = 0; i < 2; i++) {
            int idx = tid + 128*i;          // 0..255
            int row = idx >> 2, seg = idx & 3;
            float4 v = make_float4(0.f,0.f,0.f,0.f);
            if (m0 + row < M) v = *(const float4*)(A + (size_t)(m0+row)*lda + k0 + seg*4);
            As[seg*4+0][row] = v.x; As[seg*4+1][row] = v.y;
            As[seg*4+2][row] = v.z; As[seg*4+3][row] = v.w;
        }
        #pragma unroll
        for (int i = 0; i < 2; i++) {
            int idx = tid + 128*i;
            if (TRANSB) {
                int row = idx >> 2, seg = idx & 3;    // row = n index
                float4 v = make_float4(0.f,0.f,0.f,0.f);
                if (n0 + row < N) v = *(const float4*)(Bm + (size_t)(n0+row)*ldb + k0 + seg*4);
                Bs[seg*4+0][row] = v.x; Bs[seg*4+1][row] = v.y;
                Bs[seg*4+2][row] = v.z; Bs[seg*4+3][row] = v.w;
            } else {
                int kk = idx >> 4, sn = idx & 15;
                float4 v = make_float4(0.f,0.f,0.f,0.f);
                if (n0 + sn*4 < N) v = *(const float4*)(Bm + (size_t)(k0+kk)*ldb + n0 + sn*4);
                *(float4*)&Bs[kk][sn*4] = v;
            }
        }
        __syncthreads();
        #pragma unroll
        for (int kk = 0; kk < 16; kk++) {
            float4 a  = *(const float4*)&As[kk][tm*4];
            float4 b0 = *(const float4*)&Bs[kk][tn*8];
            float4 b1 = *(const float4*)&Bs[kk][tn*8+4];
            float av[4] = {a.x, a.y, a.z, a.w};
            float bv[8] = {b0.x,b0.y,b0.z,b0.w,b1.x,b1.y,b1.z,b1.w};
            #pragma unroll
            for (int i = 0; i < 4; i++)
                #pragma unroll
                for (int j = 0; j < 8; j++) acc[i][j] += av[i]*bv[j];
        }
        __syncthreads();
    }

    float bvv[8] = {};
    if (bias) {
        float4 c0 = *(const float4*)(bias + n0 + tn*8);
        float4 c1 = *(const float4*)(bias + n0 + tn*8 + 4);
        bvv[0]=c0.x; bvv[1]=c0.y; bvv[2]=c0.z; bvv[3]=c0.w;
        bvv[4]=c1.x; bvv[5]=c1.y; bvv[6]=c1.z; bvv[7]=c1.w;
    }
    #pragma unroll
    for (int i = 0; i < 4; i++) {
        int m = m0 + tm*4 + i;
        if (m >= M) continue;
        float o[8];
        #pragma unroll
        for (int j = 0; j < 8; j++) {
            float v = acc[i][j]*alpha + bvv[j];
            if (silu) v = v / (1.f + __expf(-v));
            o[j] = v;
        }
        *(float4*)(C + (size_t)m*ldc + n0 + tn*8)     = make_float4(o[0],o[1],o[2],o[3]);
        *(float4*)(C + (size_t)m*ldc + n0 + tn*8 + 4) = make_float4(o[4],o[5],o[6],o[7]);
    }
}

// ---------------- split-K reduce (+bias, +silu) ----------------
__global__ void reduce_add(const float* __restrict__ parts, const float* __restrict__ bias,
                           float* __restrict__ out, int total, int ncols, int KS,
                           int silu, int partStride)
{
    int i = (blockIdx.x*256 + threadIdx.x)*4;
    if (i >= total) return;
    float4 s = *(const float4*)(parts + i);
    for (int ks = 1; ks < KS; ks++) {
        float4 p = *(const float4*)(parts + (size_t)ks*partStride + i);
        s.x += p.x; s.y += p.y; s.z += p.z; s.w += p.w;
    }
    int col = i % ncols;
    float4 bv = *(const float4*)(bias + col);
    s.x += bv.x; s.y += bv.y; s.z += bv.z; s.w += bv.w;
    if (silu) {
        s.x = s.x/(1.f+__expf(-s.x)); s.y = s.y/(1.f+__expf(-s.y));
        s.z = s.z/(1.f+__expf(-s.z)); s.w = s.w/(1.f+__expf(-s.w));
    }
    *(float4*)(out + i) = s;
}

// ---------------- fused attention v2 ----------------
// 384 threads = 12 warps = 12 heads. qkw in registers. cp.async double-buffered tiles.
__device__ __forceinline__ void cp_async16(uint32_t dst, const void* src) {
    asm volatile("cp.async.cg.shared.global [%0], [%1], 16;" :: "r"(dst), "l"(src));
}

__global__ __launch_bounds__(384) void attn2(const float* __restrict__ x) {
    extern __shared__ float sm[];
    float* tile0 = sm;                 // 16*768 = 12288
    float* tile1 = sm + 12288;
    float* e_s   = sm + 24576;         // [r][12] : 192
    float* den_s = sm + 24768;         // 12

    int bn = blockIdx.x;
    int b = bn / Np, n = bn % Np;
    int t1 = n / Tt, t2 = n % Tt;
    const float* xp = x + (size_t)b*Dm*CHW + (size_t)(t1*16)*HW + t2*16;

    int tid = threadIdx.x, lane = tid & 31, w = tid >> 5;

    float4 qk[6];
    #pragma unroll
    for (int i = 0; i < 6; i++)
        qk[i] = *(const float4*)(g_qkw + (size_t)bn*(NH*Dm) + w*768 + lane*4 + 128*i);

    float acc[NH][2];
    #pragma unroll
    for (int h = 0; h < NH; h++) { acc[h][0] = 0.f; acc[h][1] = 0.f; }
    float denr = 0.f;

    uint32_t s0 = (uint32_t)__cvta_generic_to_shared(tile0);
    uint32_t s1 = (uint32_t)__cvta_generic_to_shared(tile1);

    // prefetch lc=0 into tile0
    {
        #pragma unroll
        for (int j = 0; j < 8; j++) {
            int chunk = tid + 384*j;
            int flat = chunk*4;
            int dd = flat >> 8, g1 = (flat >> 4) & 15, g2 = flat & 15;
            cp_async16(s0 + (uint32_t)(chunk*16), xp + (size_t)dd*CHW + g1*HW + g2);
        }
        asm volatile("cp.async.commit_group;");
    }

    for (int lc = 0; lc < 16; lc++) {
        float*  cur  = (lc & 1) ? tile1 : tile0;
        uint32_t nxt = (lc & 1) ? s0 : s1;
        if (lc < 15) {
            #pragma unroll
            for (int j = 0; j < 8; j++) {
                int chunk = tid + 384*j;
                int flat = (lc+1)*12288 + chunk*4;
                int dd = flat >> 8, g1 = (flat >> 4) & 15, g2 = flat & 15;
                cp_async16(nxt + (uint32_t)(chunk*16), xp + (size_t)dd*CHW + g1*HW + g2);
            }
            asm volatile("cp.async.commit_group;");
            asm volatile("cp.async.wait_group 1;");
        } else {
            asm volatile("cp.async.wait_group 0;");
        }
        __syncthreads();

        // scores: warp w = head w, 16 rows
        #pragma unroll 4
        for (int r = 0; r < 16; r++) {
            const float* row = cur + r*768 + lane*4;
            float s = 0.f;
            #pragma unroll
            for (int i = 0; i < 6; i++) {
                float4 t = *(const float4*)(row + 128*i);
                s += qk[i].x*t.x + qk[i].y*t.y + qk[i].z*t.z + qk[i].w*t.w;
            }
            s += __shfl_xor_sync(0xffffffffu, s, 16);
            s += __shfl_xor_sync(0xffffffffu, s, 8);
            s += __shfl_xor_sync(0xffffffffu, s, 4);
            s += __shfl_xor_sync(0xffffffffu, s, 2);
            s += __shfl_xor_sync(0xffffffffu, s, 1);
            float e = __expf(s);
            denr += e;
            if (lane == 0) e_s[r*12 + w] = e;
        }
        __syncthreads();

        // av: thread owns cols {tid*2, tid*2+1}
        #pragma unroll 4
        for (int r = 0; r < 16; r++) {
            float2 v = *(const float2*)(cur + r*768 + tid*2);
            float4 e0 = *(const float4*)(e_s + r*12);
            float4 e1 = *(const float4*)(e_s + r*12 + 4);
            float4 e2 = *(const float4*)(e_s + r*12 + 8);
            acc[0][0]  += e0.x*v.x;  acc[0][1]  += e0.x*v.y;
            acc[1][0]  += e0.y*v.x;  acc[1][1]  += e0.y*v.y;
            acc[2][0]  += e0.z*v.x;  acc[2][1]  += e0.z*v.y;
            acc[3][0]  += e0.w*v.x;  acc[3][1]  += e0.w*v.y;
            acc[4][0]  += e1.x*v.x;  acc[4][1]  += e1.x*v.y;
            acc[5][0]  += e1.y*v.x;  acc[5][1]  += e1.y*v.y;
            acc[6][0]  += e1.z*v.x;  acc[6][1]  += e1.z*v.y;
            acc[7][0]  += e1.w*v.x;  acc[7][1]  += e1.w*v.y;
            acc[8][0]  += e2.x*v.x;  acc[8][1]  += e2.x*v.y;
            acc[9][0]  += e2.y*v.x;  acc[9][1]  += e2.y*v.y;
            acc[10][0] += e2.z*v.x;  acc[10][1] += e2.z*v.y;
            acc[11][0] += e2.w*v.x;  acc[11][1] += e2.w*v.y;
        }
        __syncthreads();
    }

    if (lane == 0) den_s[w] = denr;
    __syncthreads();
    float4 d0 = *(const float4*)(den_s);
    float4 d1 = *(const float4*)(den_s + 4);
    float4 d2 = *(const float4*)(den_s + 8);
    float inv[NH] = {1.f/d0.x, 1.f/d0.y, 1.f/d0.z, 1.f/d0.w,
                     1.f/d1.x, 1.f/d1.y, 1.f/d1.z, 1.f/d1.w,
                     1.f/d2.x, 1.f/d2.y, 1.f/d2.z, 1.f/d2.w};
    #pragma unroll
    for (int h = 0; h < NH; h++) {
        float2 o = make_float2(acc[h][0]*inv[h], acc[h][1]*inv[h]);
        *(float2*)(g_avn + (size_t)bn*(NH*Dm) + h*768 + tid*2) = o;
    }
}

// ---------------- host ----------------
extern "C" void kernel_launch(void* const* d_in, const int* in_sizes, int n_in,
                              void* d_out, int out_size)
{
    const float* x     = (const float*)d_in[0];
    const float* w_in  = (const float*)d_in[1];
    const float* b_in  = (const float*)d_in[2];
    const float* w_out = (const float*)d_in[3];
    const float* b_out = (const float*)d_in[4];
    const float* w_fc1 = (const float*)d_in[5];
    const float* b_fc1 = (const float*)d_in[6];
    const float* w_fc2 = (const float*)d_in[7];
    const float* b_fc2 = (const float*)d_in[8];
    float* y = (float*)d_out;

    float *q, *qp, *qkw, *avn, *ctx, *o1, *h1, *part;
    cudaGetSymbolAddress((void**)&q,    g_q);
    cudaGetSymbolAddress((void**)&qp,   g_qp);
    cudaGetSymbolAddress((void**)&qkw,  g_qkw);
    cudaGetSymbolAddress((void**)&avn,  g_avn);
    cudaGetSymbolAddress((void**)&ctx,  g_ctx);
    cudaGetSymbolAddress((void**)&o1,   g_o1);
    cudaGetSymbolAddress((void**)&h1,   g_h1);
    cudaGetSymbolAddress((void**)&part, g_part);

    const int PS = BN*Dm;          // part stride 784*768
    const int redGrid = (PS/4 + 255)/256;

    // 1. token means
    mean_kernel<<<Bb*Dm*Tt, 224>>>(x);

    // 2. qp = q @ wq^T (+b in reduce)   KS=2
    gemm64<true><<<dim3(12,13,2), 128>>>(q, w_in, nullptr, part,
        BN, Dm, Dm/2, Dm, Dm, Dm, 2, 0,0,0, PS, 1.f, 0);
    reduce_add<<<redGrid, 256>>>(part, b_in, qp, PS, Dm, 2, 0, PS);

    // 3. qkw (batched heads, K=64, KS=1, scale folded)
    gemm64<false><<<dim3(12,13,NH), 128>>>(qp, w_in + (size_t)Dm*Dm, nullptr, qkw,
        BN, Dm, HD, Dm, Dm, NH*Dm, 1, HD, HD*Dm, Dm, 0, 0.125f, 0);

    // 4. fused attention
    {
        static const size_t smem = (24576 + 192 + 12 + 4) * sizeof(float);
        cudaFuncSetAttribute(attn2, cudaFuncAttributeMaxDynamicSharedMemorySize, (int)smem);
        attn2<<<BN, 384, smem>>>(x);
    }

    // 5. ctx (batched heads, KS=2)
    gemm64<true><<<dim3(1,13,NH*2), 128>>>(avn, w_in + (size_t)2*Dm*Dm, nullptr, part,
        BN, HD, Dm/2, NH*Dm, Dm, Dm, 2, Dm, HD*Dm, HD, PS, 1.f, 0);
    reduce_add<<<redGrid, 256>>>(part, b_in + 2*Dm, ctx, PS, Dm, 2, 0, PS);

    // 6. o1 = ctx @ w_out^T (+b)  KS=2
    gemm64<true><<<dim3(12,13,2), 128>>>(ctx, w_out, nullptr, part,
        BN, Dm, Dm/2, Dm, Dm, Dm, 2, 0,0,0, PS, 1.f, 0);
    reduce_add<<<redGrid, 256>>>(part, b_out, o1, PS, Dm, 2, 0, PS);

    // 7. h1 = silu(o1 @ w_fc1^T + b)   KS=1 (624 blocks)
    gemm64<true><<<dim3(48,13,1), 128>>>(o1, w_fc1, b_fc1, h1,
        BN, FFD, Dm, Dm, Dm, FFD, 1, 0,0,0, 0, 1.f, 1);

    // 8. y = h1 @ w_fc2^T (+b)   KS=4
    gemm64<true><<<dim3(12,13,4), 128>>>(h1, w_fc2, nullptr, part,
        BN, Dm, FFD/4, FFD, FFD, Dm, 4, 0,0,0, PS, 1.f, 0);
    reduce_add<<<redGrid, 256>>>(part, b_fc2, y, PS, Dm, 4, 0, PS);
}

// round 4
// speedup vs baseline: 3.4152x; 1.1491x over previous
#include <cuda_runtime.h>
#include <math.h>
#include <stdint.h>
#include <mma.h>

using namespace nvcuda;

#define Bb   4
#define Dm   768
#define Tt   14
#define Np   196
#define NH   12
#define HD   64
#define FFD  3072
#define BN   (Bb*Np)       // 784
#define HW   224
#define CHW  (HW*HW)       // 50176

// ---------------- scratch ----------------
__device__ float g_q  [BN*Dm];
__device__ float g_qp [BN*Dm];
__device__ float g_qkw[BN*NH*Dm];
__device__ float g_avn[BN*NH*Dm];
__device__ float g_ctx[BN*Dm];
__device__ float g_o1 [BN*Dm];
__device__ float g_h1 [BN*FFD];

// ---------------- kernel 1: token means ----------------
__global__ void mean_kernel(const float* __restrict__ x) {
    int bid = blockIdx.x;
    int t1 = bid % Tt;
    int dd = (bid / Tt) % Dm;
    int b  = bid / (Tt * Dm);
    const float* xp = x + ((size_t)b*Dm + dd)*CHW + (size_t)t1*16*HW;
    int j = threadIdx.x;
    float s = 0.f;
    #pragma unroll
    for (int r = 0; r < 16; r++) s += xp[(size_t)r*HW + j];
    __shared__ float cs[224];
    cs[j] = s;
    __syncthreads();
    if (j < Tt) {
        float t = 0.f;
        #pragma unroll
        for (int k = 0; k < 16; k++) t += cs[j*16 + k];
        g_q[((size_t)b*Np + t1*Tt + j)*Dm + dd] = t * (1.0f/256.0f);
    }
}

// ---------------- tf32 tensor-core GEMM ----------------
// C[m,n] = gamma * (sum_k A[m,k]*B(k,n) + bias[n]), optional silu.
// TRANSB=1: B(k,n) = Bm[n*ldb + k]  (N x K row-major, C = A @ B^T)
// TRANSB=0: B(k,n) = Bm[k*ldb + n]  (K x N row-major)
// blockIdx.z = head slice: A += h*sAh, Bm += h*sBh, C += h*sCh, bias += h*sBiasH.
// 64x64 CTA tile, BK=32, 256 threads = 8 warps in 4(M) x 2(N), warp tile 16x32.
template<bool TRANSB>
__global__ __launch_bounds__(256) void gemm_tc(
    const float* __restrict__ A, const float* __restrict__ Bm,
    const float* __restrict__ bias, float* __restrict__ C,
    int M, int N, int K, int lda, int ldb, int ldc,
    int sAh, int sBh, int sCh, int sBiasH,
    float gamma, int silu)
{
    int h = blockIdx.z;
    A  += (size_t)h * sAh;
    Bm += (size_t)h * sBh;
    C  += (size_t)h * sCh;
    const float* biasp = bias ? bias + (size_t)h * sBiasH : nullptr;

    __shared__ float sbuf[4608];                       // 18 KB
    float (*As)[36]  = (float(*)[36])sbuf;             // 64 x 36
    float (*BsT)[36] = (float(*)[36])(sbuf + 2304);    // TRANSB=1: Bs[n][k] 64 x 36
    float (*BsR)[68] = (float(*)[68])(sbuf + 2304);    // TRANSB=0: Bs[k][n] 32 x 68
    float (*Cs)[68]  = (float(*)[68])sbuf;             // 64 x 68 epilogue staging

    int m0 = blockIdx.y * 64, n0 = blockIdx.x * 64;
    int tid = threadIdx.x;
    int warpId = tid >> 5;
    int wm = warpId >> 1;            // 0..3
    int wn = warpId & 1;             // 0..1

    wmma::fragment<wmma::accumulator, 16, 16, 8, float> cf[2];
    wmma::fill_fragment(cf[0], 0.f);
    wmma::fill_fragment(cf[1], 0.f);

    for (int k0 = 0; k0 < K; k0 += 32) {
        // stage A: 64 rows x 32 k  (512 float4)
        #pragma unroll
        for (int i = 0; i < 2; i++) {
            int idx = tid + 256*i;           // 0..511
            int row = idx >> 3, seg = idx & 7;
            float4 v = make_float4(0.f,0.f,0.f,0.f);
            if (m0 + row < M) v = *(const float4*)(A + (size_t)(m0+row)*lda + k0 + seg*4);
            *(float4*)&As[row][seg*4] = v;
        }
        // stage B
        if (TRANSB) {
            #pragma unroll
            for (int i = 0; i < 2; i++) {
                int idx = tid + 256*i;
                int nn = idx >> 3, seg = idx & 7;
                float4 v = make_float4(0.f,0.f,0.f,0.f);
                if (n0 + nn < N) v = *(const float4*)(Bm + (size_t)(n0+nn)*ldb + k0 + seg*4);
                *(float4*)&BsT[nn][seg*4] = v;
            }
        } else {
            #pragma unroll
            for (int i = 0; i < 2; i++) {
                int idx = tid + 256*i;       // 0..511 -> 32 k-rows x 16 segs
                int kk = idx >> 4, seg = idx & 15;
                float4 v = make_float4(0.f,0.f,0.f,0.f);
                if (n0 + seg*4 < N) v = *(const float4*)(Bm + (size_t)(k0+kk)*ldb + n0 + seg*4);
                *(float4*)&BsR[kk][seg*4] = v;
            }
        }
        __syncthreads();

        #pragma unroll
        for (int ks = 0; ks < 4; ks++) {
            wmma::fragment<wmma::matrix_a, 16, 16, 8, wmma::precision::tf32, wmma::row_major> af;
            wmma::load_matrix_sync(af, &As[wm*16][ks*8], 36);
            #pragma unroll
            for (int e = 0; e < af.num_elements; e++) af.x[e] = wmma::__float_to_tf32(af.x[e]);
            #pragma unroll
            for (int j = 0; j < 2; j++) {
                if (TRANSB) {
                    wmma::fragment<wmma::matrix_b, 16, 16, 8, wmma::precision::tf32, wmma::col_major> bf;
                    wmma::load_matrix_sync(bf, &BsT[wn*32 + j*16][ks*8], 36);
                    #pragma unroll
                    for (int e = 0; e < bf.num_elements; e++) bf.x[e] = wmma::__float_to_tf32(bf.x[e]);
                    wmma::mma_sync(cf[j], af, bf, cf[j]);
                } else {
                    wmma::fragment<wmma::matrix_b, 16, 16, 8, wmma::precision::tf32, wmma::row_major> bf;
                    wmma::load_matrix_sync(bf, &BsR[ks*8][wn*32 + j*16], 68);
                    #pragma unroll
                    for (int e = 0; e < bf.num_elements; e++) bf.x[e] = wmma::__float_to_tf32(bf.x[e]);
                    wmma::mma_sync(cf[j], af, bf, cf[j]);
                }
            }
        }
        __syncthreads();
    }

    // epilogue: stage to shared, fused bias/scale/silu, float4 stores
    wmma::store_matrix_sync(&Cs[wm*16][wn*32],      cf[0], 68, wmma::mem_row_major);
    wmma::store_matrix_sync(&Cs[wm*16][wn*32 + 16], cf[1], 68, wmma::mem_row_major);
    __syncthreads();

    #pragma unroll
    for (int i = 0; i < 4; i++) {
        int e = tid + 256*i;                 // 0..1023 -> 64 rows x 16 segs
        int row = e >> 4, seg = e & 15;
        int m = m0 + row, nbase = n0 + seg*4;
        if (m >= M || nbase >= N) continue;
        float4 v = *(const float4*)&Cs[row][seg*4];
        if (biasp) {
            float4 bv = *(const float4*)(biasp + nbase);
            v.x += bv.x; v.y += bv.y; v.z += bv.z; v.w += bv.w;
        }
        v.x *= gamma; v.y *= gamma; v.z *= gamma; v.w *= gamma;
        if (silu) {
            v.x = v.x/(1.f+__expf(-v.x)); v.y = v.y/(1.f+__expf(-v.y));
            v.z = v.z/(1.f+__expf(-v.z)); v.w = v.w/(1.f+__expf(-v.w));
        }
        *(float4*)(C + (size_t)m*ldc + nbase) = v;
    }
}

// ---------------- fused attention (unchanged from R3) ----------------
__device__ __forceinline__ void cp_async16(uint32_t dst, const void* src) {
    asm volatile("cp.async.cg.shared.global [%0], [%1], 16;" :: "r"(dst), "l"(src));
}

__global__ __launch_bounds__(384) void attn2(const float* __restrict__ x) {
    extern __shared__ float sm[];
    float* tile0 = sm;                 // 16*768
    float* tile1 = sm + 12288;
    float* e_s   = sm + 24576;         // [r][12]
    float* den_s = sm + 24768;

    int bn = blockIdx.x;
    int b = bn / Np, n = bn % Np;
    int t1 = n / Tt, t2 = n % Tt;
    const float* xp = x + (size_t)b*Dm*CHW + (size_t)(t1*16)*HW + t2*16;

    int tid = threadIdx.x, lane = tid & 31, w = tid >> 5;

    float4 qk[6];
    #pragma unroll
    for (int i = 0; i < 6; i++)
        qk[i] = *(const float4*)(g_qkw + (size_t)bn*(NH*Dm) + w*768 + lane*4 + 128*i);

    float acc[NH][2];
    #pragma unroll
    for (int h = 0; h < NH; h++) { acc[h][0] = 0.f; acc[h][1] = 0.f; }
    float denr = 0.f;

    uint32_t s0 = (uint32_t)__cvta_generic_to_shared(tile0);
    uint32_t s1 = (uint32_t)__cvta_generic_to_shared(tile1);

    {
        #pragma unroll
        for (int j = 0; j < 8; j++) {
            int chunk = tid + 384*j;
            int flat = chunk*4;
            int dd = flat >> 8, g1 = (flat >> 4) & 15, g2 = flat & 15;
            cp_async16(s0 + (uint32_t)(chunk*16), xp + (size_t)dd*CHW + g1*HW + g2);
        }
        asm volatile("cp.async.commit_group;");
    }

    for (int lc = 0; lc < 16; lc++) {
        float*  cur  = (lc & 1) ? tile1 : tile0;
        uint32_t nxt = (lc & 1) ? s0 : s1;
        if (lc < 15) {
            #pragma unroll
            for (int j = 0; j < 8; j++) {
                int chunk = tid + 384*j;
                int flat = (lc+1)*12288 + chunk*4;
                int dd = flat >> 8, g1 = (flat >> 4) & 15, g2 = flat & 15;
                cp_async16(nxt + (uint32_t)(chunk*16), xp + (size_t)dd*CHW + g1*HW + g2);
            }
            asm volatile("cp.async.commit_group;");
            asm volatile("cp.async.wait_group 1;");
        } else {
            asm volatile("cp.async.wait_group 0;");
        }
        __syncthreads();

        #pragma unroll 4
        for (int r = 0; r < 16; r++) {
            const float* row = cur + r*768 + lane*4;
            float s = 0.f;
            #pragma unroll
            for (int i = 0; i < 6; i++) {
                float4 t = *(const float4*)(row + 128*i);
                s += qk[i].x*t.x + qk[i].y*t.y + qk[i].z*t.z + qk[i].w*t.w;
            }
            s += __shfl_xor_sync(0xffffffffu, s, 16);
            s += __shfl_xor_sync(0xffffffffu, s, 8);
            s += __shfl_xor_sync(0xffffffffu, s, 4);
            s += __shfl_xor_sync(0xffffffffu, s, 2);
            s += __shfl_xor_sync(0xffffffffu, s, 1);
            float e = __expf(s);
            denr += e;
            if (lane == 0) e_s[r*12 + w] = e;
        }
        __syncthreads();

        #pragma unroll 4
        for (int r = 0; r < 16; r++) {
            float2 v = *(const float2*)(cur + r*768 + tid*2);
            float4 e0 = *(const float4*)(e_s + r*12);
            float4 e1 = *(const float4*)(e_s + r*12 + 4);
            float4 e2 = *(const float4*)(e_s + r*12 + 8);
            acc[0][0]  += e0.x*v.x;  acc[0][1]  += e0.x*v.y;
            acc[1][0]  += e0.y*v.x;  acc[1][1]  += e0.y*v.y;
            acc[2][0]  += e0.z*v.x;  acc[2][1]  += e0.z*v.y;
            acc[3][0]  += e0.w*v.x;  acc[3][1]  += e0.w*v.y;
            acc[4][0]  += e1.x*v.x;  acc[4][1]  += e1.x*v.y;
            acc[5][0]  += e1.y*v.x;  acc[5][1]  += e1.y*v.y;
            acc[6][0]  += e1.z*v.x;  acc[6][1]  += e1.z*v.y;
            acc[7][0]  += e1.w*v.x;  acc[7][1]  += e1.w*v.y;
            acc[8][0]  += e2.x*v.x;  acc[8][1]  += e2.x*v.y;
            acc[9][0]  += e2.y*v.x;  acc[9][1]  += e2.y*v.y;
            acc[10][0] += e2.z*v.x;  acc[10][1] += e2.z*v.y;
            acc[11][0] += e2.w*v.x;  acc[11][1] += e2.w*v.y;
        }
        __syncthreads();
    }

    if (lane == 0) den_s[w] = denr;
    __syncthreads();
    float4 d0 = *(const float4*)(den_s);
    float4 d1 = *(const float4*)(den_s + 4);
    float4 d2 = *(const float4*)(den_s + 8);
    float inv[NH] = {1.f/d0.x, 1.f/d0.y, 1.f/d0.z, 1.f/d0.w,
                     1.f/d1.x, 1.f/d1.y, 1.f/d1.z, 1.f/d1.w,
                     1.f/d2.x, 1.f/d2.y, 1.f/d2.z, 1.f/d2.w};
    #pragma unroll
    for (int h = 0; h < NH; h++) {
        float2 o = make_float2(acc[h][0]*inv[h], acc[h][1]*inv[h]);
        *(float2*)(g_avn + (size_t)bn*(NH*Dm) + h*768 + tid*2) = o;
    }
}

// ---------------- host ----------------
extern "C" void kernel_launch(void* const* d_in, const int* in_sizes, int n_in,
                              void* d_out, int out_size)
{
    const float* x     = (const float*)d_in[0];
    const float* w_in  = (const float*)d_in[1];
    const float* b_in  = (const float*)d_in[2];
    const float* w_out = (const float*)d_in[3];
    const float* b_out = (const float*)d_in[4];
    const float* w_fc1 = (const float*)d_in[5];
    const float* b_fc1 = (const float*)d_in[6];
    const float* w_fc2 = (const float*)d_in[7];
    const float* b_fc2 = (const float*)d_in[8];
    float* y = (float*)d_out;

    float *q, *qp, *qkw, *avn, *ctx, *o1, *h1;
    cudaGetSymbolAddress((void**)&q,   g_q);
    cudaGetSymbolAddress((void**)&qp,  g_qp);
    cudaGetSymbolAddress((void**)&qkw, g_qkw);
    cudaGetSymbolAddress((void**)&avn, g_avn);
    cudaGetSymbolAddress((void**)&ctx, g_ctx);
    cudaGetSymbolAddress((void**)&o1,  g_o1);
    cudaGetSymbolAddress((void**)&h1,  g_h1);

    // 1. token means
    mean_kernel<<<Bb*Dm*Tt, 224>>>(x);

    // 2. qp = (q @ wq^T + bq) * 0.125   (scale folded here; qkw stays pure GEMM)
    gemm_tc<true><<<dim3(12,13,1), 256>>>(q, w_in, b_in, qp,
        BN, Dm, Dm, Dm, Dm, Dm, 0,0,0,0, 0.125f, 0);

    // 3. qkw[.,h,:] = qp_h @ wk_h   (batched heads, K=64)
    gemm_tc<false><<<dim3(12,13,NH), 256>>>(qp, w_in + (size_t)Dm*Dm, nullptr, qkw,
        BN, Dm, HD, Dm, Dm, NH*Dm, HD, HD*Dm, Dm, 0, 1.f, 0);

    // 4. fused attention
    {
        static const size_t smem = (24576 + 192 + 12 + 4) * sizeof(float);
        cudaFuncSetAttribute(attn2, cudaFuncAttributeMaxDynamicSharedMemorySize, (int)smem);
        attn2<<<BN, 384, smem>>>(x);
    }

    // 5. ctx_h = avn_h @ wv_h^T + bv_h   (batched heads)
    gemm_tc<true><<<dim3(1,13,NH), 256>>>(avn, w_in + (size_t)2*Dm*Dm, b_in + 2*Dm, ctx,
        BN, HD, Dm, NH*Dm, Dm, Dm, Dm, HD*Dm, HD, HD, 1.f, 0);

    // 6. o1 = ctx @ w_out^T + b_out
    gemm_tc<true><<<dim3(12,13,1), 256>>>(ctx, w_out, b_out, o1,
        BN, Dm, Dm, Dm, Dm, Dm, 0,0,0,0, 1.f, 0);

    // 7. h1 = silu(o1 @ w_fc1^T + b_fc1)
    gemm_tc<true><<<dim3(48,13,1), 256>>>(o1, w_fc1, b_fc1, h1,
        BN, FFD, Dm, Dm, Dm, FFD, 0,0,0,0, 1.f, 1);

    // 8. y = h1 @ w_fc2^T + b_fc2
    gemm_tc<true><<<dim3(12,13,1), 256>>>(h1, w_fc2, b_fc2, y,
        BN, Dm, FFD, FFD, FFD, Dm, 0,0,0,0, 1.f, 0);
}

// round 5
// speedup vs baseline: 3.5253x; 1.0322x over previous
#include <cuda_runtime.h>
#include <math.h>
#include <stdint.h>
#include <mma.h>

using namespace nvcuda;

#define Bb   4
#define Dm   768
#define Tt   14
#define Np   196
#define NH   12
#define HD   64
#define FFD  3072
#define BN   (Bb*Np)       // 784
#define HW   224
#define CHW  (HW*HW)       // 50176

// ---------------- scratch ----------------
__device__ float g_q  [BN*Dm];
__device__ float g_qp [BN*Dm];
__device__ float g_qkw[BN*NH*Dm];
__device__ float g_avn[BN*NH*Dm];
__device__ float g_ctx[BN*Dm];
__device__ float g_o1 [BN*Dm];
__device__ float g_h1 [BN*FFD];

__device__ __forceinline__ void cp_async16(uint32_t dst, const void* src) {
    asm volatile("cp.async.cg.shared.global [%0], [%1], 16;" :: "r"(dst), "l"(src));
}

// ---------------- kernel 1: token means ----------------
__global__ void mean_kernel(const float* __restrict__ x) {
    int bid = blockIdx.x;
    int t1 = bid % Tt;
    int dd = (bid / Tt) % Dm;
    int b  = bid / (Tt * Dm);
    const float* xp = x + ((size_t)b*Dm + dd)*CHW + (size_t)t1*16*HW;
    int j = threadIdx.x;
    float s = 0.f;
    #pragma unroll
    for (int r = 0; r < 16; r++) s += xp[(size_t)r*HW + j];
    __shared__ float cs[224];
    cs[j] = s;
    __syncthreads();
    if (j < Tt) {
        float t = 0.f;
        #pragma unroll
        for (int k = 0; k < 16; k++) t += cs[j*16 + k];
        g_q[((size_t)b*Np + t1*Tt + j)*Dm + dd] = t * (1.0f/256.0f);
    }
}

// ---------------- tf32 tensor-core GEMM, cp.async double-buffered ----------------
// C[m,n] = gamma * (sum_k A[m,k]*B(k,n) + bias[n]), optional silu.
// TRANSB=1: B(k,n)=Bm[n*ldb+k];  TRANSB=0: B(k,n)=Bm[k*ldb+n]
// blockIdx.z = head slice. 64x64 tile, BK=32, 256 thr = 8 warps (4M x 2N), warp 16x32.
template<bool TRANSB>
__global__ __launch_bounds__(256) void gemm_tc(
    const float* __restrict__ A, const float* __restrict__ Bm,
    const float* __restrict__ bias, float* __restrict__ C,
    int M, int N, int K, int lda, int ldb, int ldc,
    int sAh, int sBh, int sCh, int sBiasH,
    float gamma, int silu)
{
    int h = blockIdx.z;
    A  += (size_t)h * sAh;
    Bm += (size_t)h * sBh;
    C  += (size_t)h * sCh;
    const float* biasp = bias ? bias + (size_t)h * sBiasH : nullptr;

    __shared__ float sbuf[2*4608];   // stage s: A at s*4608 (64x36), B at s*4608+2304
    uint32_t sb = (uint32_t)__cvta_generic_to_shared(sbuf);

    int m0 = blockIdx.y * 64, n0 = blockIdx.x * 64;
    int tid = threadIdx.x;
    int warpId = tid >> 5;
    int wm = warpId >> 1;
    int wn = warpId & 1;

    wmma::fragment<wmma::accumulator, 16, 16, 8, float> cf[2];
    wmma::fill_fragment(cf[0], 0.f);
    wmma::fill_fragment(cf[1], 0.f);

    const int nk = K >> 5;

    auto issue = [&](int it, int s) {
        int k0 = it * 32;
        uint32_t base = sb + (uint32_t)(s*4608*4);
        // A: 64 rows x 32 k
        #pragma unroll
        for (int i = 0; i < 2; i++) {
            int idx = tid + 256*i;
            int row = idx >> 3, seg = idx & 7;
            int m = m0 + row; if (m >= M) m = M - 1;   // clamp: garbage rows unused
            cp_async16(base + (uint32_t)((row*36 + seg*4)*4),
                       A + (size_t)m*lda + k0 + seg*4);
        }
        uint32_t bbase = base + 2304*4;
        if (TRANSB) {
            #pragma unroll
            for (int i = 0; i < 2; i++) {
                int idx = tid + 256*i;
                int nn = idx >> 3, seg = idx & 7;
                int ng = n0 + nn; if (ng >= N) ng = N - 1;
                cp_async16(bbase + (uint32_t)((nn*36 + seg*4)*4),
                           Bm + (size_t)ng*ldb + k0 + seg*4);
            }
        } else {
            #pragma unroll
            for (int i = 0; i < 2; i++) {
                int idx = tid + 256*i;
                int kk = idx >> 4, seg = idx & 15;
                int nb = n0 + seg*4; if (nb >= N) nb = 0;
                cp_async16(bbase + (uint32_t)((kk*68 + seg*4)*4),
                           Bm + (size_t)(k0+kk)*ldb + nb);
            }
        }
        asm volatile("cp.async.commit_group;");
    };

    issue(0, 0);

    for (int it = 0; it < nk; it++) {
        int s = it & 1;
        if (it + 1 < nk) {
            issue(it+1, s^1);
            asm volatile("cp.async.wait_group 1;");
        } else {
            asm volatile("cp.async.wait_group 0;");
        }
        __syncthreads();

        float (*As)[36]  = (float(*)[36])(sbuf + s*4608);
        float (*BsT)[36] = (float(*)[36])(sbuf + s*4608 + 2304);
        float (*BsR)[68] = (float(*)[68])(sbuf + s*4608 + 2304);

        #pragma unroll
        for (int ks = 0; ks < 4; ks++) {
            wmma::fragment<wmma::matrix_a, 16, 16, 8, wmma::precision::tf32, wmma::row_major> af;
            wmma::load_matrix_sync(af, &As[wm*16][ks*8], 36);
            #pragma unroll
            for (int e = 0; e < af.num_elements; e++) af.x[e] = wmma::__float_to_tf32(af.x[e]);
            #pragma unroll
            for (int j = 0; j < 2; j++) {
                if (TRANSB) {
                    wmma::fragment<wmma::matrix_b, 16, 16, 8, wmma::precision::tf32, wmma::col_major> bf;
                    wmma::load_matrix_sync(bf, &BsT[wn*32 + j*16][ks*8], 36);
                    #pragma unroll
                    for (int e = 0; e < bf.num_elements; e++) bf.x[e] = wmma::__float_to_tf32(bf.x[e]);
                    wmma::mma_sync(cf[j], af, bf, cf[j]);
                } else {
                    wmma::fragment<wmma::matrix_b, 16, 16, 8, wmma::precision::tf32, wmma::row_major> bf;
                    wmma::load_matrix_sync(bf, &BsR[ks*8][wn*32 + j*16], 68);
                    #pragma unroll
                    for (int e = 0; e < bf.num_elements; e++) bf.x[e] = wmma::__float_to_tf32(bf.x[e]);
                    wmma::mma_sync(cf[j], af, bf, cf[j]);
                }
            }
        }
        __syncthreads();
    }

    // epilogue via shared staging (reuse stage 0)
    float (*Cs)[68] = (float(*)[68])sbuf;
    wmma::store_matrix_sync(&Cs[wm*16][wn*32],      cf[0], 68, wmma::mem_row_major);
    wmma::store_matrix_sync(&Cs[wm*16][wn*32 + 16], cf[1], 68, wmma::mem_row_major);
    __syncthreads();

    #pragma unroll
    for (int i = 0; i < 4; i++) {
        int e = tid + 256*i;
        int row = e >> 4, seg = e & 15;
        int m = m0 + row, nbase = n0 + seg*4;
        if (m >= M || nbase >= N) continue;
        float4 v = *(const float4*)&Cs[row][seg*4];
        if (biasp) {
            float4 bv = *(const float4*)(biasp + nbase);
            v.x += bv.x; v.y += bv.y; v.z += bv.z; v.w += bv.w;
        }
        v.x *= gamma; v.y *= gamma; v.z *= gamma; v.w *= gamma;
        if (silu) {
            v.x = v.x/(1.f+__expf(-v.x)); v.y = v.y/(1.f+__expf(-v.y));
            v.z = v.z/(1.f+__expf(-v.z)); v.w = v.w/(1.f+__expf(-v.w));
        }
        *(float4*)(C + (size_t)m*ldc + nbase) = v;
    }
}

// ---------------- fused attention v3: 8-row chunks, 4 CTAs/SM ----------------
__global__ __launch_bounds__(384) void attn3(const float* __restrict__ x) {
    extern __shared__ float sm[];
    float* tile0 = sm;                 // 8*768 = 6144
    float* tile1 = sm + 6144;
    float* e_s   = sm + 12288;         // [r][12] : 96
    float* den_s = sm + 12384;         // 12

    int bn = blockIdx.x;
    int b = bn / Np, n = bn % Np;
    int t1 = n / Tt, t2 = n % Tt;
    const float* xp = x + (size_t)b*Dm*CHW + (size_t)(t1*16)*HW + t2*16;

    int tid = threadIdx.x, lane = tid & 31, w = tid >> 5;

    float4 qk[6];
    #pragma unroll
    for (int i = 0; i < 6; i++)
        qk[i] = *(const float4*)(g_qkw + (size_t)bn*(NH*Dm) + w*768 + lane*4 + 128*i);

    float acc[NH][2];
    #pragma unroll
    for (int h = 0; h < NH; h++) { acc[h][0] = 0.f; acc[h][1] = 0.f; }
    float denr = 0.f;

    uint32_t s0 = (uint32_t)__cvta_generic_to_shared(tile0);
    uint32_t s1 = (uint32_t)__cvta_generic_to_shared(tile1);

    // prefetch chunk 0 (1536 x 16B, 4 per thread)
    {
        #pragma unroll
        for (int j = 0; j < 4; j++) {
            int chunk = tid + 384*j;
            int flat = chunk*4;
            int dd = flat >> 8, g1 = (flat >> 4) & 15, g2 = flat & 15;
            cp_async16(s0 + (uint32_t)(chunk*16), xp + (size_t)dd*CHW + g1*HW + g2);
        }
        asm volatile("cp.async.commit_group;");
    }

    for (int lc = 0; lc < 32; lc++) {
        float*  cur  = (lc & 1) ? tile1 : tile0;
        uint32_t nxt = (lc & 1) ? s0 : s1;
        if (lc < 31) {
            #pragma unroll
            for (int j = 0; j < 4; j++) {
                int chunk = tid + 384*j;
                int flat = (lc+1)*6144 + chunk*4;
                int dd = flat >> 8, g1 = (flat >> 4) & 15, g2 = flat & 15;
                cp_async16(nxt + (uint32_t)(chunk*16), xp + (size_t)dd*CHW + g1*HW + g2);
            }
            asm volatile("cp.async.commit_group;");
            asm volatile("cp.async.wait_group 1;");
        } else {
            asm volatile("cp.async.wait_group 0;");
        }
        __syncthreads();

        // scores: warp w = head w, 8 rows
        #pragma unroll
        for (int r = 0; r < 8; r++) {
            const float* row = cur + r*768 + lane*4;
            float s = 0.f;
            #pragma unroll
            for (int i = 0; i < 6; i++) {
                float4 t = *(const float4*)(row + 128*i);
                s += qk[i].x*t.x + qk[i].y*t.y + qk[i].z*t.z + qk[i].w*t.w;
            }
            s += __shfl_xor_sync(0xffffffffu, s, 16);
            s += __shfl_xor_sync(0xffffffffu, s, 8);
            s += __shfl_xor_sync(0xffffffffu, s, 4);
            s += __shfl_xor_sync(0xffffffffu, s, 2);
            s += __shfl_xor_sync(0xffffffffu, s, 1);
            float e = __expf(s);
            denr += e;
            if (lane == 0) e_s[r*12 + w] = e;
        }
        __syncthreads();

        // av: thread owns cols {tid*2, tid*2+1}; e_s reads are warp-broadcast
        #pragma unroll
        for (int r = 0; r < 8; r++) {
            float2 v = *(const float2*)(cur + r*768 + tid*2);
            float4 e0 = *(const float4*)(e_s + r*12);
            float4 e1 = *(const float4*)(e_s + r*12 + 4);
            float4 e2 = *(const float4*)(e_s + r*12 + 8);
            acc[0][0]  += e0.x*v.x;  acc[0][1]  += e0.x*v.y;
            acc[1][0]  += e0.y*v.x;  acc[1][1]  += e0.y*v.y;
            acc[2][0]  += e0.z*v.x;  acc[2][1]  += e0.z*v.y;
            acc[3][0]  += e0.w*v.x;  acc[3][1]  += e0.w*v.y;
            acc[4][0]  += e1.x*v.x;  acc[4][1]  += e1.x*v.y;
            acc[5][0]  += e1.y*v.x;  acc[5][1]  += e1.y*v.y;
            acc[6][0]  += e1.z*v.x;  acc[6][1]  += e1.z*v.y;
            acc[7][0]  += e1.w*v.x;  acc[7][1]  += e1.w*v.y;
            acc[8][0]  += e2.x*v.x;  acc[8][1]  += e2.x*v.y;
            acc[9][0]  += e2.y*v.x;  acc[9][1]  += e2.y*v.y;
            acc[10][0] += e2.z*v.x;  acc[10][1] += e2.z*v.y;
            acc[11][0] += e2.w*v.x;  acc[11][1] += e2.w*v.y;
        }
        __syncthreads();
    }

    if (lane == 0) den_s[w] = denr;
    __syncthreads();
    float4 d0 = *(const float4*)(den_s);
    float4 d1 = *(const float4*)(den_s + 4);
    float4 d2 = *(const float4*)(den_s + 8);
    float inv[NH] = {1.f/d0.x, 1.f/d0.y, 1.f/d0.z, 1.f/d0.w,
                     1.f/d1.x, 1.f/d1.y, 1.f/d1.z, 1.f/d1.w,
                     1.f/d2.x, 1.f/d2.y, 1.f/d2.z, 1.f/d2.w};
    #pragma unroll
    for (int h = 0; h < NH; h++) {
        float2 o = make_float2(acc[h][0]*inv[h], acc[h][1]*inv[h]);
        *(float2*)(g_avn + (size_t)bn*(NH*Dm) + h*768 + tid*2) = o;
    }
}

// ---------------- host ----------------
extern "C" void kernel_launch(void* const* d_in, const int* in_sizes, int n_in,
                              void* d_out, int out_size)
{
    const float* x     = (const float*)d_in[0];
    const float* w_in  = (const float*)d_in[1];
    const float* b_in  = (const float*)d_in[2];
    const float* w_out = (const float*)d_in[3];
    const float* b_out = (const float*)d_in[4];
    const float* w_fc1 = (const float*)d_in[5];
    const float* b_fc1 = (const float*)d_in[6];
    const float* w_fc2 = (const float*)d_in[7];
    const float* b_fc2 = (const float*)d_in[8];
    float* y = (float*)d_out;

    float *q, *qp, *qkw, *avn, *ctx, *o1, *h1;
    cudaGetSymbolAddress((void**)&q,   g_q);
    cudaGetSymbolAddress((void**)&qp,  g_qp);
    cudaGetSymbolAddress((void**)&qkw, g_qkw);
    cudaGetSymbolAddress((void**)&avn, g_avn);
    cudaGetSymbolAddress((void**)&ctx, g_ctx);
    cudaGetSymbolAddress((void**)&o1,  g_o1);
    cudaGetSymbolAddress((void**)&h1,  g_h1);

    // 1. token means
    mean_kernel<<<Bb*Dm*Tt, 224>>>(x);

    // 2. qp = (q @ wq^T + bq) * 0.125
    gemm_tc<true><<<dim3(12,13,1), 256>>>(q, w_in, b_in, qp,
        BN, Dm, Dm, Dm, Dm, Dm, 0,0,0,0, 0.125f, 0);

    // 3. qkw[.,h,:] = qp_h @ wk_h   (batched heads, K=64)
    gemm_tc<false><<<dim3(12,13,NH), 256>>>(qp, w_in + (size_t)Dm*Dm, nullptr, qkw,
        BN, Dm, HD, Dm, Dm, NH*Dm, HD, HD*Dm, Dm, 0, 1.f, 0);

    // 4. fused attention
    {
        static const size_t smem = (12288 + 96 + 12) * sizeof(float);
        cudaFuncSetAttribute(attn3, cudaFuncAttributeMaxDynamicSharedMemorySize, (int)smem);
        attn3<<<BN, 384, smem>>>(x);
    }

    // 5. ctx_h = avn_h @ wv_h^T + bv_h   (batched heads)
    gemm_tc<true><<<dim3(1,13,NH), 256>>>(avn, w_in + (size_t)2*Dm*Dm, b_in + 2*Dm, ctx,
        BN, HD, Dm, NH*Dm, Dm, Dm, Dm, HD*Dm, HD, HD, 1.f, 0);

    // 6. o1 = ctx @ w_out^T + b_out
    gemm_tc<true><<<dim3(12,13,1), 256>>>(ctx, w_out, b_out, o1,
        BN, Dm, Dm, Dm, Dm, Dm, 0,0,0,0, 1.f, 0);

    // 7. h1 = silu(o1 @ w_fc1^T + b_fc1)
    gemm_tc<true><<<dim3(48,13,1), 256>>>(o1, w_fc1, b_fc1, h1,
        BN, FFD, Dm, Dm, Dm, FFD, 0,0,0,0, 1.f, 1);

    // 8. y = h1 @ w_fc2^T + b_fc2
    gemm_tc<true><<<dim3(12,13,1), 256>>>(h1, w_fc2, b_fc2, y,
        BN, Dm, FFD, FFD, FFD, Dm, 0,0,0,0, 1.f, 0);
}

// round 6
// speedup vs baseline: 3.7817x; 1.0727x over previous
#include <cuda_runtime.h>
#include <math.h>
#include <stdint.h>
#include <mma.h>

using namespace nvcuda;

#define Bb   4
#define Dm   768
#define Tt   14
#define Np   196
#define NH   12
#define HD   64
#define FFD  3072
#define BN   (Bb*Np)       // 784
#define HW   224
#define CHW  (HW*HW)       // 50176

// ---------------- scratch ----------------
__device__ float g_q  [BN*Dm];
__device__ float g_qp [BN*Dm];
__device__ float g_qkw[BN*NH*Dm];
__device__ float g_avn[BN*NH*Dm];
__device__ float g_ctx[BN*Dm];
__device__ float g_o1 [BN*Dm];
__device__ float g_h1 [BN*FFD];

__device__ __forceinline__ void cp_async16(uint32_t dst, const void* src) {
    asm volatile("cp.async.cg.shared.global [%0], [%1], 16;" :: "r"(dst), "l"(src));
}

// ---------------- kernel 1: token means ----------------
__global__ void mean_kernel(const float* __restrict__ x) {
    int bid = blockIdx.x;
    int t1 = bid % Tt;
    int dd = (bid / Tt) % Dm;
    int b  = bid / (Tt * Dm);
    const float* xp = x + ((size_t)b*Dm + dd)*CHW + (size_t)t1*16*HW;
    int j = threadIdx.x;
    float s = 0.f;
    #pragma unroll
    for (int r = 0; r < 16; r++) s += xp[(size_t)r*HW + j];
    __shared__ float cs[224];
    cs[j] = s;
    __syncthreads();
    if (j < Tt) {
        float t = 0.f;
        #pragma unroll
        for (int k = 0; k < 16; k++) t += cs[j*16 + k];
        g_q[((size_t)b*Np + t1*Tt + j)*Dm + dd] = t * (1.0f/256.0f);
    }
}

// ---------------- tf32 tensor-core GEMM, cp.async double-buffered (unchanged) ----------------
template<bool TRANSB>
__global__ __launch_bounds__(256) void gemm_tc(
    const float* __restrict__ A, const float* __restrict__ Bm,
    const float* __restrict__ bias, float* __restrict__ C,
    int M, int N, int K, int lda, int ldb, int ldc,
    int sAh, int sBh, int sCh, int sBiasH,
    float gamma, int silu)
{
    int h = blockIdx.z;
    A  += (size_t)h * sAh;
    Bm += (size_t)h * sBh;
    C  += (size_t)h * sCh;
    const float* biasp = bias ? bias + (size_t)h * sBiasH : nullptr;

    __shared__ float sbuf[2*4608];
    uint32_t sb = (uint32_t)__cvta_generic_to_shared(sbuf);

    int m0 = blockIdx.y * 64, n0 = blockIdx.x * 64;
    int tid = threadIdx.x;
    int warpId = tid >> 5;
    int wm = warpId >> 1;
    int wn = warpId & 1;

    wmma::fragment<wmma::accumulator, 16, 16, 8, float> cf[2];
    wmma::fill_fragment(cf[0], 0.f);
    wmma::fill_fragment(cf[1], 0.f);

    const int nk = K >> 5;

    auto issue = [&](int it, int s) {
        int k0 = it * 32;
        uint32_t base = sb + (uint32_t)(s*4608*4);
        #pragma unroll
        for (int i = 0; i < 2; i++) {
            int idx = tid + 256*i;
            int row = idx >> 3, seg = idx & 7;
            int m = m0 + row; if (m >= M) m = M - 1;
            cp_async16(base + (uint32_t)((row*36 + seg*4)*4),
                       A + (size_t)m*lda + k0 + seg*4);
        }
        uint32_t bbase = base + 2304*4;
        if (TRANSB) {
            #pragma unroll
            for (int i = 0; i < 2; i++) {
                int idx = tid + 256*i;
                int nn = idx >> 3, seg = idx & 7;
                int ng = n0 + nn; if (ng >= N) ng = N - 1;
                cp_async16(bbase + (uint32_t)((nn*36 + seg*4)*4),
                           Bm + (size_t)ng*ldb + k0 + seg*4);
            }
        } else {
            #pragma unroll
            for (int i = 0; i < 2; i++) {
                int idx = tid + 256*i;
                int kk = idx >> 4, seg = idx & 15;
                int nb = n0 + seg*4; if (nb >= N) nb = 0;
                cp_async16(bbase + (uint32_t)((kk*68 + seg*4)*4),
                           Bm + (size_t)(k0+kk)*ldb + nb);
            }
        }
        asm volatile("cp.async.commit_group;");
    };

    issue(0, 0);

    for (int it = 0; it < nk; it++) {
        int s = it & 1;
        if (it + 1 < nk) {
            issue(it+1, s^1);
            asm volatile("cp.async.wait_group 1;");
        } else {
            asm volatile("cp.async.wait_group 0;");
        }
        __syncthreads();

        float (*As)[36]  = (float(*)[36])(sbuf + s*4608);
        float (*BsT)[36] = (float(*)[36])(sbuf + s*4608 + 2304);
        float (*BsR)[68] = (float(*)[68])(sbuf + s*4608 + 2304);

        #pragma unroll
        for (int ks = 0; ks < 4; ks++) {
            wmma::fragment<wmma::matrix_a, 16, 16, 8, wmma::precision::tf32, wmma::row_major> af;
            wmma::load_matrix_sync(af, &As[wm*16][ks*8], 36);
            #pragma unroll
            for (int e = 0; e < af.num_elements; e++) af.x[e] = wmma::__float_to_tf32(af.x[e]);
            #pragma unroll
            for (int j = 0; j < 2; j++) {
                if (TRANSB) {
                    wmma::fragment<wmma::matrix_b, 16, 16, 8, wmma::precision::tf32, wmma::col_major> bf;
                    wmma::load_matrix_sync(bf, &BsT[wn*32 + j*16][ks*8], 36);
                    #pragma unroll
                    for (int e = 0; e < bf.num_elements; e++) bf.x[e] = wmma::__float_to_tf32(bf.x[e]);
                    wmma::mma_sync(cf[j], af, bf, cf[j]);
                } else {
                    wmma::fragment<wmma::matrix_b, 16, 16, 8, wmma::precision::tf32, wmma::row_major> bf;
                    wmma::load_matrix_sync(bf, &BsR[ks*8][wn*32 + j*16], 68);
                    #pragma unroll
                    for (int e = 0; e < bf.num_elements; e++) bf.x[e] = wmma::__float_to_tf32(bf.x[e]);
                    wmma::mma_sync(cf[j], af, bf, cf[j]);
                }
            }
        }
        __syncthreads();
    }

    float (*Cs)[68] = (float(*)[68])sbuf;
    wmma::store_matrix_sync(&Cs[wm*16][wn*32],      cf[0], 68, wmma::mem_row_major);
    wmma::store_matrix_sync(&Cs[wm*16][wn*32 + 16], cf[1], 68, wmma::mem_row_major);
    __syncthreads();

    #pragma unroll
    for (int i = 0; i < 4; i++) {
        int e = tid + 256*i;
        int row = e >> 4, seg = e & 15;
        int m = m0 + row, nbase = n0 + seg*4;
        if (m >= M || nbase >= N) continue;
        float4 v = *(const float4*)&Cs[row][seg*4];
        if (biasp) {
            float4 bv = *(const float4*)(biasp + nbase);
            v.x += bv.x; v.y += bv.y; v.z += bv.z; v.w += bv.w;
        }
        v.x *= gamma; v.y *= gamma; v.z *= gamma; v.w *= gamma;
        if (silu) {
            v.x = v.x/(1.f+__expf(-v.x)); v.y = v.y/(1.f+__expf(-v.y));
            v.z = v.z/(1.f+__expf(-v.z)); v.w = v.w/(1.f+__expf(-v.w));
        }
        *(float4*)(C + (size_t)m*ldc + nbase) = v;
    }
}

// ---------------- fused attention v4: tensor-core scores, 2 CTAs/SM ----------------
// smem: qkw_s 16x768 (12288) | tile 16x768 (12288) | Dpart 12x256 (3072) | e_s 192 | denom 16
__global__ __launch_bounds__(384, 2) void attn4(const float* __restrict__ x) {
    extern __shared__ float sm[];
    float* qkw_s = sm;                  // padded to 16 heads for B-fragment reads
    float* tile  = sm + 12288;
    float* Dpart = sm + 24576;
    float* e_s   = sm + 27648;          // [r][h] r<16, h<12
    float* denom = sm + 27840;

    int bn = blockIdx.x;
    int b = bn / Np, n = bn % Np;
    int t1 = n / Tt, t2 = n % Tt;
    const float* xp = x + (size_t)b*Dm*CHW + (size_t)(t1*16)*HW + t2*16;

    int tid = threadIdx.x, w = tid >> 5;

    // load qkw (12x768) into smem, zero pad heads 12..15
    {
        const float4* src = (const float4*)(g_qkw + (size_t)bn*(NH*Dm));
        #pragma unroll
        for (int i = 0; i < 6; i++)
            *(float4*)(qkw_s + (tid + 384*i)*4) = src[tid + 384*i];
        #pragma unroll
        for (int i = 0; i < 8; i++) qkw_s[9216 + tid + 384*i] = 0.f;
    }
    if (tid < NH) denom[tid] = 0.f;

    float acc[NH][2];
    #pragma unroll
    for (int h = 0; h < NH; h++) { acc[h][0] = 0.f; acc[h][1] = 0.f; }

    uint32_t st = (uint32_t)__cvta_generic_to_shared(tile);
    __syncthreads();

    for (int lc = 0; lc < 16; lc++) {
        // fill tile: 16 kv rows = 3072 float4
        #pragma unroll
        for (int j = 0; j < 8; j++) {
            int chunk = tid + 384*j;
            int flat = lc*12288 + chunk*4;
            int dd = flat >> 8, g1 = (flat >> 4) & 15, g2 = flat & 15;
            cp_async16(st + (uint32_t)(chunk*16), xp + (size_t)dd*CHW + g1*HW + g2);
        }
        asm volatile("cp.async.commit_group;");
        asm volatile("cp.async.wait_group 0;");
        __syncthreads();

        // scores via wmma: warp w handles k-slice [64w, 64w+64)
        {
            wmma::fragment<wmma::accumulator, 16, 16, 8, float> d;
            wmma::fill_fragment(d, 0.f);
            #pragma unroll
            for (int ks = 0; ks < 8; ks++) {
                int k = w*64 + ks*8;
                wmma::fragment<wmma::matrix_a, 16, 16, 8, wmma::precision::tf32, wmma::row_major> af;
                wmma::load_matrix_sync(af, tile + k, 768);
                #pragma unroll
                for (int e = 0; e < af.num_elements; e++) af.x[e] = wmma::__float_to_tf32(af.x[e]);
                wmma::fragment<wmma::matrix_b, 16, 16, 8, wmma::precision::tf32, wmma::col_major> bf;
                wmma::load_matrix_sync(bf, qkw_s + k, 768);
                #pragma unroll
                for (int e = 0; e < bf.num_elements; e++) bf.x[e] = wmma::__float_to_tf32(bf.x[e]);
                wmma::mma_sync(d, af, bf, d);
            }
            wmma::store_matrix_sync(Dpart + w*256, d, 16, wmma::mem_row_major);
        }
        __syncthreads();

        // reduce partials + exp
        if (tid < 192) {
            int r = tid / 12, h = tid - r*12;
            float s = 0.f;
            #pragma unroll
            for (int w2 = 0; w2 < 12; w2++) s += Dpart[w2*256 + r*16 + h];
            e_s[r*12 + h] = __expf(s);
        }
        __syncthreads();

        // denom (12 threads) + av accumulation (all threads)
        if (tid < NH) {
            float dsum = 0.f;
            #pragma unroll
            for (int r = 0; r < 16; r++) dsum += e_s[r*12 + tid];
            denom[tid] += dsum;
        }
        #pragma unroll
        for (int r = 0; r < 16; r++) {
            float2 v = *(const float2*)(tile + r*768 + tid*2);
            float4 e0 = *(const float4*)(e_s + r*12);
            float4 e1 = *(const float4*)(e_s + r*12 + 4);
            float4 e2 = *(const float4*)(e_s + r*12 + 8);
            acc[0][0]  += e0.x*v.x;  acc[0][1]  += e0.x*v.y;
            acc[1][0]  += e0.y*v.x;  acc[1][1]  += e0.y*v.y;
            acc[2][0]  += e0.z*v.x;  acc[2][1]  += e0.z*v.y;
            acc[3][0]  += e0.w*v.x;  acc[3][1]  += e0.w*v.y;
            acc[4][0]  += e1.x*v.x;  acc[4][1]  += e1.x*v.y;
            acc[5][0]  += e1.y*v.x;  acc[5][1]  += e1.y*v.y;
            acc[6][0]  += e1.z*v.x;  acc[6][1]  += e1.z*v.y;
            acc[7][0]  += e1.w*v.x;  acc[7][1]  += e1.w*v.y;
            acc[8][0]  += e2.x*v.x;  acc[8][1]  += e2.x*v.y;
            acc[9][0]  += e2.y*v.x;  acc[9][1]  += e2.y*v.y;
            acc[10][0] += e2.z*v.x;  acc[10][1] += e2.z*v.y;
            acc[11][0] += e2.w*v.x;  acc[11][1] += e2.w*v.y;
        }
        __syncthreads();
    }

    // normalize + write
    __syncthreads();
    float4 d0 = *(const float4*)(denom);
    float4 d1 = *(const float4*)(denom + 4);
    float4 d2 = *(const float4*)(denom + 8);
    float inv[NH] = {1.f/d0.x, 1.f/d0.y, 1.f/d0.z, 1.f/d0.w,
                     1.f/d1.x, 1.f/d1.y, 1.f/d1.z, 1.f/d1.w,
                     1.f/d2.x, 1.f/d2.y, 1.f/d2.z, 1.f/d2.w};
    #pragma unroll
    for (int h = 0; h < NH; h++) {
        float2 o = make_float2(acc[h][0]*inv[h], acc[h][1]*inv[h]);
        *(float2*)(g_avn + (size_t)bn*(NH*Dm) + h*768 + tid*2) = o;
    }
}

// ---------------- host ----------------
extern "C" void kernel_launch(void* const* d_in, const int* in_sizes, int n_in,
                              void* d_out, int out_size)
{
    const float* x     = (const float*)d_in[0];
    const float* w_in  = (const float*)d_in[1];
    const float* b_in  = (const float*)d_in[2];
    const float* w_out = (const float*)d_in[3];
    const float* b_out = (const float*)d_in[4];
    const float* w_fc1 = (const float*)d_in[5];
    const float* b_fc1 = (const float*)d_in[6];
    const float* w_fc2 = (const float*)d_in[7];
    const float* b_fc2 = (const float*)d_in[8];
    float* y = (float*)d_out;

    float *q, *qp, *qkw, *avn, *ctx, *o1, *h1;
    cudaGetSymbolAddress((void**)&q,   g_q);
    cudaGetSymbolAddress((void**)&qp,  g_qp);
    cudaGetSymbolAddress((void**)&qkw, g_qkw);
    cudaGetSymbolAddress((void**)&avn, g_avn);
    cudaGetSymbolAddress((void**)&ctx, g_ctx);
    cudaGetSymbolAddress((void**)&o1,  g_o1);
    cudaGetSymbolAddress((void**)&h1,  g_h1);

    // 1. token means
    mean_kernel<<<Bb*Dm*Tt, 224>>>(x);

    // 2. qp = (q @ wq^T + bq) * 0.125
    gemm_tc<true><<<dim3(12,13,1), 256>>>(q, w_in, b_in, qp,
        BN, Dm, Dm, Dm, Dm, Dm, 0,0,0,0, 0.125f, 0);

    // 3. qkw[.,h,:] = qp_h @ wk_h   (batched heads, K=64)
    gemm_tc<false><<<dim3(12,13,NH), 256>>>(qp, w_in + (size_t)Dm*Dm, nullptr, qkw,
        BN, Dm, HD, Dm, Dm, NH*Dm, HD, HD*Dm, Dm, 0, 1.f, 0);

    // 4. fused attention (tensor-core scores)
    {
        static const size_t smem = (12288 + 12288 + 3072 + 192 + 16) * sizeof(float);
        cudaFuncSetAttribute(attn4, cudaFuncAttributeMaxDynamicSharedMemorySize, (int)smem);
        attn4<<<BN, 384, smem>>>(x);
    }

    // 5. ctx_h = avn_h @ wv_h^T + bv_h   (batched heads)
    gemm_tc<true><<<dim3(1,13,NH), 256>>>(avn, w_in + (size_t)2*Dm*Dm, b_in + 2*Dm, ctx,
        BN, HD, Dm, NH*Dm, Dm, Dm, Dm, HD*Dm, HD, HD, 1.f, 0);

    // 6. o1 = ctx @ w_out^T + b_out
    gemm_tc<true><<<dim3(12,13,1), 256>>>(ctx, w_out, b_out, o1,
        BN, Dm, Dm, Dm, Dm, Dm, 0,0,0,0, 1.f, 0);

    // 7. h1 = silu(o1 @ w_fc1^T + b_fc1)
    gemm_tc<true><<<dim3(48,13,1), 256>>>(o1, w_fc1, b_fc1, h1,
        BN, FFD, Dm, Dm, Dm, FFD, 0,0,0,0, 1.f, 1);

    // 8. y = h1 @ w_fc2^T + b_fc2
    gemm_tc<true><<<dim3(12,13,1), 256>>>(h1, w_fc2, b_fc2, y,
        BN, Dm, FFD, FFD, FFD, Dm, 0,0,0,0, 1.f, 0);
}

// round 7
// speedup vs baseline: 4.6334x; 1.2252x over previous
#include <cuda_runtime.h>
#include <math.h>
#include <stdint.h>
#include <mma.h>

using namespace nvcuda;

#define Bb   4
#define Dm   768
#define Tt   14
#define Np   196
#define NH   12
#define HD   64
#define FFD  3072
#define BN   (Bb*Np)       // 784
#define HW   224
#define CHW  (HW*HW)       // 50176

#define TLD  772           // padded tile/qkw row stride (772 % 32 == 4, 16B-aligned rows)
#define DLD  20            // Dpart leading dim

// ---------------- scratch ----------------
__device__ float g_q  [BN*Dm];
__device__ float g_qp [BN*Dm];
__device__ float g_qkw[BN*NH*Dm];
__device__ float g_avn[BN*NH*Dm];
__device__ float g_ctx[BN*Dm];
__device__ float g_o1 [BN*Dm];
__device__ float g_h1 [BN*FFD];

__device__ __forceinline__ void cp_async16(uint32_t dst, const void* src) {
    asm volatile("cp.async.cg.shared.global [%0], [%1], 16;" :: "r"(dst), "l"(src));
}

// ---------------- kernel 1: token means ----------------
__global__ void mean_kernel(const float* __restrict__ x) {
    int bid = blockIdx.x;
    int t1 = bid % Tt;
    int dd = (bid / Tt) % Dm;
    int b  = bid / (Tt * Dm);
    const float* xp = x + ((size_t)b*Dm + dd)*CHW + (size_t)t1*16*HW;
    int j = threadIdx.x;
    float s = 0.f;
    #pragma unroll
    for (int r = 0; r < 16; r++) s += xp[(size_t)r*HW + j];
    __shared__ float cs[224];
    cs[j] = s;
    __syncthreads();
    if (j < Tt) {
        float t = 0.f;
        #pragma unroll
        for (int k = 0; k < 16; k++) t += cs[j*16 + k];
        g_q[((size_t)b*Np + t1*Tt + j)*Dm + dd] = t * (1.0f/256.0f);
    }
}

// ---------------- tf32 tensor-core GEMM, cp.async double-buffered (unchanged) ----------------
template<bool TRANSB>
__global__ __launch_bounds__(256) void gemm_tc(
    const float* __restrict__ A, const float* __restrict__ Bm,
    const float* __restrict__ bias, float* __restrict__ C,
    int M, int N, int K, int lda, int ldb, int ldc,
    int sAh, int sBh, int sCh, int sBiasH,
    float gamma, int silu)
{
    int h = blockIdx.z;
    A  += (size_t)h * sAh;
    Bm += (size_t)h * sBh;
    C  += (size_t)h * sCh;
    const float* biasp = bias ? bias + (size_t)h * sBiasH : nullptr;

    __shared__ float sbuf[2*4608];
    uint32_t sb = (uint32_t)__cvta_generic_to_shared(sbuf);

    int m0 = blockIdx.y * 64, n0 = blockIdx.x * 64;
    int tid = threadIdx.x;
    int warpId = tid >> 5;
    int wm = warpId >> 1;
    int wn = warpId & 1;

    wmma::fragment<wmma::accumulator, 16, 16, 8, float> cf[2];
    wmma::fill_fragment(cf[0], 0.f);
    wmma::fill_fragment(cf[1], 0.f);

    const int nk = K >> 5;

    auto issue = [&](int it, int s) {
        int k0 = it * 32;
        uint32_t base = sb + (uint32_t)(s*4608*4);
        #pragma unroll
        for (int i = 0; i < 2; i++) {
            int idx = tid + 256*i;
            int row = idx >> 3, seg = idx & 7;
            int m = m0 + row; if (m >= M) m = M - 1;
            cp_async16(base + (uint32_t)((row*36 + seg*4)*4),
                       A + (size_t)m*lda + k0 + seg*4);
        }
        uint32_t bbase = base + 2304*4;
        if (TRANSB) {
            #pragma unroll
            for (int i = 0; i < 2; i++) {
                int idx = tid + 256*i;
                int nn = idx >> 3, seg = idx & 7;
                int ng = n0 + nn; if (ng >= N) ng = N - 1;
                cp_async16(bbase + (uint32_t)((nn*36 + seg*4)*4),
                           Bm + (size_t)ng*ldb + k0 + seg*4);
            }
        } else {
            #pragma unroll
            for (int i = 0; i < 2; i++) {
                int idx = tid + 256*i;
                int kk = idx >> 4, seg = idx & 15;
                int nb = n0 + seg*4; if (nb >= N) nb = 0;
                cp_async16(bbase + (uint32_t)((kk*68 + seg*4)*4),
                           Bm + (size_t)(k0+kk)*ldb + nb);
            }
        }
        asm volatile("cp.async.commit_group;");
    };

    issue(0, 0);

    for (int it = 0; it < nk; it++) {
        int s = it & 1;
        if (it + 1 < nk) {
            issue(it+1, s^1);
            asm volatile("cp.async.wait_group 1;");
        } else {
            asm volatile("cp.async.wait_group 0;");
        }
        __syncthreads();

        float (*As)[36]  = (float(*)[36])(sbuf + s*4608);
        float (*BsT)[36] = (float(*)[36])(sbuf + s*4608 + 2304);
        float (*BsR)[68] = (float(*)[68])(sbuf + s*4608 + 2304);

        #pragma unroll
        for (int ks = 0; ks < 4; ks++) {
            wmma::fragment<wmma::matrix_a, 16, 16, 8, wmma::precision::tf32, wmma::row_major> af;
            wmma::load_matrix_sync(af, &As[wm*16][ks*8], 36);
            #pragma unroll
            for (int e = 0; e < af.num_elements; e++) af.x[e] = wmma::__float_to_tf32(af.x[e]);
            #pragma unroll
            for (int j = 0; j < 2; j++) {
                if (TRANSB) {
                    wmma::fragment<wmma::matrix_b, 16, 16, 8, wmma::precision::tf32, wmma::col_major> bf;
                    wmma::load_matrix_sync(bf, &BsT[wn*32 + j*16][ks*8], 36);
                    #pragma unroll
                    for (int e = 0; e < bf.num_elements; e++) bf.x[e] = wmma::__float_to_tf32(bf.x[e]);
                    wmma::mma_sync(cf[j], af, bf, cf[j]);
                } else {
                    wmma::fragment<wmma::matrix_b, 16, 16, 8, wmma::precision::tf32, wmma::row_major> bf;
                    wmma::load_matrix_sync(bf, &BsR[ks*8][wn*32 + j*16], 68);
                    #pragma unroll
                    for (int e = 0; e < bf.num_elements; e++) bf.x[e] = wmma::__float_to_tf32(bf.x[e]);
                    wmma::mma_sync(cf[j], af, bf, cf[j]);
                }
            }
        }
        __syncthreads();
    }

    float (*Cs)[68] = (float(*)[68])sbuf;
    wmma::store_matrix_sync(&Cs[wm*16][wn*32],      cf[0], 68, wmma::mem_row_major);
    wmma::store_matrix_sync(&Cs[wm*16][wn*32 + 16], cf[1], 68, wmma::mem_row_major);
    __syncthreads();

    #pragma unroll
    for (int i = 0; i < 4; i++) {
        int e = tid + 256*i;
        int row = e >> 4, seg = e & 15;
        int m = m0 + row, nbase = n0 + seg*4;
        if (m >= M || nbase >= N) continue;
        float4 v = *(const float4*)&Cs[row][seg*4];
        if (biasp) {
            float4 bv = *(const float4*)(biasp + nbase);
            v.x += bv.x; v.y += bv.y; v.z += bv.z; v.w += bv.w;
        }
        v.x *= gamma; v.y *= gamma; v.z *= gamma; v.w *= gamma;
        if (silu) {
            v.x = v.x/(1.f+__expf(-v.x)); v.y = v.y/(1.f+__expf(-v.y));
            v.z = v.z/(1.f+__expf(-v.z)); v.w = v.w/(1.f+__expf(-v.w));
        }
        *(float4*)(C + (size_t)m*ldc + nbase) = v;
    }
}

// ---------------- fused attention v5: bank-conflict-free strides ----------------
// smem (floats): qkw_s 12*772=9264 | tile 16*772=12352 | Dpart 12*16*20=3840 | e_s 192 | denom 16
// Total 25664 floats = 102,656 B -> 2 CTAs/SM.
__global__ __launch_bounds__(384, 2) void attn5(const float* __restrict__ x) {
    extern __shared__ float sm[];
    float* qkw_s = sm;                  // col-major per head: qkw_s[h*TLD + k]
    float* tile  = sm + 9264;           // [r][TLD]
    float* Dpart = sm + 21616;          // [w][16][DLD]
    float* e_s   = sm + 25456;          // [r][12]
    float* denom = sm + 25648;          // 16

    int bn = blockIdx.x;
    int b = bn / Np, n = bn % Np;
    int t1 = n / Tt, t2 = n % Tt;
    const float* xp = x + (size_t)b*Dm*CHW + (size_t)(t1*16)*HW + t2*16;

    int tid = threadIdx.x, w = tid >> 5;
    uint32_t st = (uint32_t)__cvta_generic_to_shared(tile);

    // issue chunk 0 fill first (overlaps qkw staging)
    #pragma unroll
    for (int j = 0; j < 8; j++) {
        int chunk = tid + 384*j;             // 0..3071
        int idx16 = chunk*4;
        int r = idx16 / 768, cc = idx16 - r*768;
        int dd = idx16 >> 8, g1 = (idx16 >> 4) & 15, g2 = idx16 & 15;
        cp_async16(st + (uint32_t)((r*TLD + cc)*4), xp + (size_t)dd*CHW + g1*HW + g2);
    }
    asm volatile("cp.async.commit_group;");

    // stage qkw: 12 heads x 768, padded stride
    {
        const float4* src = (const float4*)(g_qkw + (size_t)bn*(NH*Dm));
        #pragma unroll
        for (int i = 0; i < 6; i++) {
            int idx = tid + 384*i;           // 0..2303 float4s
            int h = idx / 192, rem = idx - h*192;
            *(float4*)(qkw_s + h*TLD + rem*4) = src[idx];
        }
    }
    if (tid < NH) denom[tid] = 0.f;

    float acc[NH][2];
    #pragma unroll
    for (int h = 0; h < NH; h++) { acc[h][0] = 0.f; acc[h][1] = 0.f; }

    for (int lc = 0; lc < 16; lc++) {
        asm volatile("cp.async.wait_group 0;");
        __syncthreads();

        // scores via wmma: warp w handles k-slice [64w, 64w+64)
        {
            wmma::fragment<wmma::accumulator, 16, 16, 8, float> d;
            wmma::fill_fragment(d, 0.f);
            #pragma unroll
            for (int ks = 0; ks < 8; ks++) {
                int k = w*64 + ks*8;
                wmma::fragment<wmma::matrix_a, 16, 16, 8, wmma::precision::tf32, wmma::row_major> af;
                wmma::load_matrix_sync(af, tile + k, TLD);
                #pragma unroll
                for (int e = 0; e < af.num_elements; e++) af.x[e] = wmma::__float_to_tf32(af.x[e]);
                // B reads 16 head-columns; cols 12..15 alias into tile (defined, never used)
                wmma::fragment<wmma::matrix_b, 16, 16, 8, wmma::precision::tf32, wmma::col_major> bf;
                wmma::load_matrix_sync(bf, qkw_s + k, TLD);
                #pragma unroll
                for (int e = 0; e < bf.num_elements; e++) bf.x[e] = wmma::__float_to_tf32(bf.x[e]);
                wmma::mma_sync(d, af, bf, d);
            }
            wmma::store_matrix_sync(Dpart + w*16*DLD, d, DLD, wmma::mem_row_major);
        }
        __syncthreads();

        // reduce partials + exp
        if (tid < 192) {
            int r = tid / 12, h = tid - r*12;
            float s = 0.f;
            #pragma unroll
            for (int w2 = 0; w2 < 12; w2++) s += Dpart[w2*16*DLD + r*DLD + h];
            e_s[r*12 + h] = __expf(s);
        }
        __syncthreads();

        if (tid < NH) {
            float dsum = 0.f;
            #pragma unroll
            for (int r = 0; r < 16; r++) dsum += e_s[r*12 + tid];
            denom[tid] += dsum;
        }
        // av accumulation: thread owns cols {tid*2, tid*2+1}
        #pragma unroll
        for (int r = 0; r < 16; r++) {
            float2 v = *(const float2*)(tile + r*TLD + tid*2);
            float4 e0 = *(const float4*)(e_s + r*12);
            float4 e1 = *(const float4*)(e_s + r*12 + 4);
            float4 e2 = *(const float4*)(e_s + r*12 + 8);
            acc[0][0]  += e0.x*v.x;  acc[0][1]  += e0.x*v.y;
            acc[1][0]  += e0.y*v.x;  acc[1][1]  += e0.y*v.y;
            acc[2][0]  += e0.z*v.x;  acc[2][1]  += e0.z*v.y;
            acc[3][0]  += e0.w*v.x;  acc[3][1]  += e0.w*v.y;
            acc[4][0]  += e1.x*v.x;  acc[4][1]  += e1.x*v.y;
            acc[5][0]  += e1.y*v.x;  acc[5][1]  += e1.y*v.y;
            acc[6][0]  += e1.z*v.x;  acc[6][1]  += e1.z*v.y;
            acc[7][0]  += e1.w*v.x;  acc[7][1]  += e1.w*v.y;
            acc[8][0]  += e2.x*v.x;  acc[8][1]  += e2.x*v.y;
            acc[9][0]  += e2.y*v.x;  acc[9][1]  += e2.y*v.y;
            acc[10][0] += e2.z*v.x;  acc[10][1] += e2.z*v.y;
            acc[11][0] += e2.w*v.x;  acc[11][1] += e2.w*v.y;
        }
        __syncthreads();

        // issue next chunk fill
        if (lc < 15) {
            #pragma unroll
            for (int j = 0; j < 8; j++) {
                int chunk = tid + 384*j;
                int idx16 = chunk*4;
                int r = idx16 / 768, cc = idx16 - r*768;
                int flat = (lc+1)*12288 + idx16;
                int dd = flat >> 8, g1 = (flat >> 4) & 15, g2 = flat & 15;
                cp_async16(st + (uint32_t)((r*TLD + cc)*4), xp + (size_t)dd*CHW + g1*HW + g2);
            }
            asm volatile("cp.async.commit_group;");
        }
    }

    __syncthreads();
    float4 d0 = *(const float4*)(denom);
    float4 d1 = *(const float4*)(denom + 4);
    float4 d2 = *(const float4*)(denom + 8);
    float inv[NH] = {1.f/d0.x, 1.f/d0.y, 1.f/d0.z, 1.f/d0.w,
                     1.f/d1.x, 1.f/d1.y, 1.f/d1.z, 1.f/d1.w,
                     1.f/d2.x, 1.f/d2.y, 1.f/d2.z, 1.f/d2.w};
    #pragma unroll
    for (int h = 0; h < NH; h++) {
        float2 o = make_float2(acc[h][0]*inv[h], acc[h][1]*inv[h]);
        *(float2*)(g_avn + (size_t)bn*(NH*Dm) + h*768 + tid*2) = o;
    }
}

// ---------------- host ----------------
extern "C" void kernel_launch(void* const* d_in, const int* in_sizes, int n_in,
                              void* d_out, int out_size)
{
    const float* x     = (const float*)d_in[0];
    const float* w_in  = (const float*)d_in[1];
    const float* b_in  = (const float*)d_in[2];
    const float* w_out = (const float*)d_in[3];
    const float* b_out = (const float*)d_in[4];
    const float* w_fc1 = (const float*)d_in[5];
    const float* b_fc1 = (const float*)d_in[6];
    const float* w_fc2 = (const float*)d_in[7];
    const float* b_fc2 = (const float*)d_in[8];
    float* y = (float*)d_out;

    float *q, *qp, *qkw, *avn, *ctx, *o1, *h1;
    cudaGetSymbolAddress((void**)&q,   g_q);
    cudaGetSymbolAddress((void**)&qp,  g_qp);
    cudaGetSymbolAddress((void**)&qkw, g_qkw);
    cudaGetSymbolAddress((void**)&avn, g_avn);
    cudaGetSymbolAddress((void**)&ctx, g_ctx);
    cudaGetSymbolAddress((void**)&o1,  g_o1);
    cudaGetSymbolAddress((void**)&h1,  g_h1);

    // 1. token means
    mean_kernel<<<Bb*Dm*Tt, 224>>>(x);

    // 2. qp = (q @ wq^T + bq) * 0.125
    gemm_tc<true><<<dim3(12,13,1), 256>>>(q, w_in, b_in, qp,
        BN, Dm, Dm, Dm, Dm, Dm, 0,0,0,0, 0.125f, 0);

    // 3. qkw[.,h,:] = qp_h @ wk_h   (batched heads, K=64)
    gemm_tc<false><<<dim3(12,13,NH), 256>>>(qp, w_in + (size_t)Dm*Dm, nullptr, qkw,
        BN, Dm, HD, Dm, Dm, NH*Dm, HD, HD*Dm, Dm, 0, 1.f, 0);

    // 4. fused attention (conflict-free strides)
    {
        static const size_t smem = 25664 * sizeof(float);
        cudaFuncSetAttribute(attn5, cudaFuncAttributeMaxDynamicSharedMemorySize, (int)smem);
        attn5<<<BN, 384, smem>>>(x);
    }

    // 5. ctx_h = avn_h @ wv_h^T + bv_h   (batched heads)
    gemm_tc<true><<<dim3(1,13,NH), 256>>>(avn, w_in + (size_t)2*Dm*Dm, b_in + 2*Dm, ctx,
        BN, HD, Dm, NH*Dm, Dm, Dm, Dm, HD*Dm, HD, HD, 1.f, 0);

    // 6. o1 = ctx @ w_out^T + b_out
    gemm_tc<true><<<dim3(12,13,1), 256>>>(ctx, w_out, b_out, o1,
        BN, Dm, Dm, Dm, Dm, Dm, 0,0,0,0, 1.f, 0);

    // 7. h1 = silu(o1 @ w_fc1^T + b_fc1)
    gemm_tc<true><<<dim3(48,13,1), 256>>>(o1, w_fc1, b_fc1, h1,
        BN, FFD, Dm, Dm, Dm, FFD, 0,0,0,0, 1.f, 1);

    // 8. y = h1 @ w_fc2^T + b_fc2
    gemm_tc<true><<<dim3(12,13,1), 256>>>(h1, w_fc2, b_fc2, y,
        BN, Dm, FFD, FFD, FFD, Dm, 0,0,0,0, 1.f, 0);
}

// round 8
// speedup vs baseline: 4.6721x; 1.0084x over previous
#include <cuda_runtime.h>
#include <math.h>
#include <stdint.h>
#include <mma.h>

using namespace nvcuda;

#define Bb   4
#define Dm   768
#define Tt   14
#define Np   196
#define NH   12
#define HD   64
#define FFD  3072
#define BN   (Bb*Np)       // 784
#define HW   224
#define CHW  (HW*HW)       // 50176

#define TLD  772           // padded tile/qkw row stride (772 % 32 == 4, 16B-aligned rows)
#define DLD  20            // Dpart leading dim
#define ELD  20            // e_hr leading dim

// ---------------- scratch ----------------
__device__ float g_q  [BN*Dm];
__device__ float g_qp [BN*Dm];
__device__ float g_qkw[BN*NH*Dm];
__device__ float g_avn[BN*NH*Dm];
__device__ float g_ctx[BN*Dm];
__device__ float g_o1 [BN*Dm];
__device__ float g_h1 [BN*FFD];

__device__ __forceinline__ void cp_async16(uint32_t dst, const void* src) {
    asm volatile("cp.async.cg.shared.global [%0], [%1], 16;" :: "r"(dst), "l"(src));
}

// ---------------- kernel 1: token means ----------------
__global__ void mean_kernel(const float* __restrict__ x) {
    int bid = blockIdx.x;
    int t1 = bid % Tt;
    int dd = (bid / Tt) % Dm;
    int b  = bid / (Tt * Dm);
    const float* xp = x + ((size_t)b*Dm + dd)*CHW + (size_t)t1*16*HW;
    int j = threadIdx.x;
    float s = 0.f;
    #pragma unroll
    for (int r = 0; r < 16; r++) s += xp[(size_t)r*HW + j];
    __shared__ float cs[224];
    cs[j] = s;
    __syncthreads();
    if (j < Tt) {
        float t = 0.f;
        #pragma unroll
        for (int k = 0; k < 16; k++) t += cs[j*16 + k];
        g_q[((size_t)b*Np + t1*Tt + j)*Dm + dd] = t * (1.0f/256.0f);
    }
}

// ---------------- tf32 tensor-core GEMM, cp.async double-buffered (unchanged) ----------------
template<bool TRANSB>
__global__ __launch_bounds__(256) void gemm_tc(
    const float* __restrict__ A, const float* __restrict__ Bm,
    const float* __restrict__ bias, float* __restrict__ C,
    int M, int N, int K, int lda, int ldb, int ldc,
    int sAh, int sBh, int sCh, int sBiasH,
    float gamma, int silu)
{
    int h = blockIdx.z;
    A  += (size_t)h * sAh;
    Bm += (size_t)h * sBh;
    C  += (size_t)h * sCh;
    const float* biasp = bias ? bias + (size_t)h * sBiasH : nullptr;

    __shared__ float sbuf[2*4608];
    uint32_t sb = (uint32_t)__cvta_generic_to_shared(sbuf);

    int m0 = blockIdx.y * 64, n0 = blockIdx.x * 64;
    int tid = threadIdx.x;
    int warpId = tid >> 5;
    int wm = warpId >> 1;
    int wn = warpId & 1;

    wmma::fragment<wmma::accumulator, 16, 16, 8, float> cf[2];
    wmma::fill_fragment(cf[0], 0.f);
    wmma::fill_fragment(cf[1], 0.f);

    const int nk = K >> 5;

    auto issue = [&](int it, int s) {
        int k0 = it * 32;
        uint32_t base = sb + (uint32_t)(s*4608*4);
        #pragma unroll
        for (int i = 0; i < 2; i++) {
            int idx = tid + 256*i;
            int row = idx >> 3, seg = idx & 7;
            int m = m0 + row; if (m >= M) m = M - 1;
            cp_async16(base + (uint32_t)((row*36 + seg*4)*4),
                       A + (size_t)m*lda + k0 + seg*4);
        }
        uint32_t bbase = base + 2304*4;
        if (TRANSB) {
            #pragma unroll
            for (int i = 0; i < 2; i++) {
                int idx = tid + 256*i;
                int nn = idx >> 3, seg = idx & 7;
                int ng = n0 + nn; if (ng >= N) ng = N - 1;
                cp_async16(bbase + (uint32_t)((nn*36 + seg*4)*4),
                           Bm + (size_t)ng*ldb + k0 + seg*4);
            }
        } else {
            #pragma unroll
            for (int i = 0; i < 2; i++) {
                int idx = tid + 256*i;
                int kk = idx >> 4, seg = idx & 15;
                int nb = n0 + seg*4; if (nb >= N) nb = 0;
                cp_async16(bbase + (uint32_t)((kk*68 + seg*4)*4),
                           Bm + (size_t)(k0+kk)*ldb + nb);
            }
        }
        asm volatile("cp.async.commit_group;");
    };

    issue(0, 0);

    for (int it = 0; it < nk; it++) {
        int s = it & 1;
        if (it + 1 < nk) {
            issue(it+1, s^1);
            asm volatile("cp.async.wait_group 1;");
        } else {
            asm volatile("cp.async.wait_group 0;");
        }
        __syncthreads();

        float (*As)[36]  = (float(*)[36])(sbuf + s*4608);
        float (*BsT)[36] = (float(*)[36])(sbuf + s*4608 + 2304);
        float (*BsR)[68] = (float(*)[68])(sbuf + s*4608 + 2304);

        #pragma unroll
        for (int ks = 0; ks < 4; ks++) {
            wmma::fragment<wmma::matrix_a, 16, 16, 8, wmma::precision::tf32, wmma::row_major> af;
            wmma::load_matrix_sync(af, &As[wm*16][ks*8], 36);
            #pragma unroll
            for (int e = 0; e < af.num_elements; e++) af.x[e] = wmma::__float_to_tf32(af.x[e]);
            #pragma unroll
            for (int j = 0; j < 2; j++) {
                if (TRANSB) {
                    wmma::fragment<wmma::matrix_b, 16, 16, 8, wmma::precision::tf32, wmma::col_major> bf;
                    wmma::load_matrix_sync(bf, &BsT[wn*32 + j*16][ks*8], 36);
                    #pragma unroll
                    for (int e = 0; e < bf.num_elements; e++) bf.x[e] = wmma::__float_to_tf32(bf.x[e]);
                    wmma::mma_sync(cf[j], af, bf, cf[j]);
                } else {
                    wmma::fragment<wmma::matrix_b, 16, 16, 8, wmma::precision::tf32, wmma::row_major> bf;
                    wmma::load_matrix_sync(bf, &BsR[ks*8][wn*32 + j*16], 68);
                    #pragma unroll
                    for (int e = 0; e < bf.num_elements; e++) bf.x[e] = wmma::__float_to_tf32(bf.x[e]);
                    wmma::mma_sync(cf[j], af, bf, cf[j]);
                }
            }
        }
        __syncthreads();
    }

    float (*Cs)[68] = (float(*)[68])sbuf;
    wmma::store_matrix_sync(&Cs[wm*16][wn*32],      cf[0], 68, wmma::mem_row_major);
    wmma::store_matrix_sync(&Cs[wm*16][wn*32 + 16], cf[1], 68, wmma::mem_row_major);
    __syncthreads();

    #pragma unroll
    for (int i = 0; i < 4; i++) {
        int e = tid + 256*i;
        int row = e >> 4, seg = e & 15;
        int m = m0 + row, nbase = n0 + seg*4;
        if (m >= M || nbase >= N) continue;
        float4 v = *(const float4*)&Cs[row][seg*4];
        if (biasp) {
            float4 bv = *(const float4*)(biasp + nbase);
            v.x += bv.x; v.y += bv.y; v.z += bv.z; v.w += bv.w;
        }
        v.x *= gamma; v.y *= gamma; v.z *= gamma; v.w *= gamma;
        if (silu) {
            v.x = v.x/(1.f+__expf(-v.x)); v.y = v.y/(1.f+__expf(-v.y));
            v.z = v.z/(1.f+__expf(-v.z)); v.w = v.w/(1.f+__expf(-v.w));
        }
        *(float4*)(C + (size_t)m*ldc + nbase) = v;
    }
}

// ---------------- fused attention v6: tensor-core scores AND AV, true double buffer ----------------
// smem (floats): qkw_s 12*772=9264 | tile0 16*772=12352 | tile1 12352 | Dpart 3840 | e_s 192 | e_hr 320 | denom 16
// total 38336 floats = 153,344 B -> 1 CTA/SM, DRAM hidden by cp.async prefetch.
__global__ __launch_bounds__(384, 1) void attn6(const float* __restrict__ x) {
    extern __shared__ float sm[];
    float* qkw_s = sm;                   // [h][TLD]
    float* tile0 = sm + 9264;
    float* tile1 = sm + 21616;
    float* Dpart = sm + 33968;           // [w][16][DLD]
    float* e_s   = sm + 37808;           // [r][12]  (denominator path, fp32)
    float* e_hr  = sm + 38000;           // [h(16)][ELD] (A matrix for AV)
    float* denom = sm + 38320;           // 16

    int bn = blockIdx.x;
    int b = bn / Np, n = bn % Np;
    int t1 = n / Tt, t2 = n % Tt;
    const float* xp = x + (size_t)b*Dm*CHW + (size_t)(t1*16)*HW + t2*16;

    int tid = threadIdx.x, w = tid >> 5;
    uint32_t st0 = (uint32_t)__cvta_generic_to_shared(tile0);
    uint32_t st1 = (uint32_t)__cvta_generic_to_shared(tile1);

    auto issue_chunk = [&](int lc, uint32_t stp) {
        #pragma unroll
        for (int j = 0; j < 8; j++) {
            int chunk = tid + 384*j;             // 0..3071 float4s
            int idx16 = chunk*4;
            int r = idx16 / 768, cc = idx16 - r*768;
            int flat = lc*12288 + idx16;
            int dd = flat >> 8, g1 = (flat >> 4) & 15, g2 = flat & 15;
            cp_async16(stp + (uint32_t)((r*TLD + cc)*4), xp + (size_t)dd*CHW + g1*HW + g2);
        }
        asm volatile("cp.async.commit_group;");
    };

    issue_chunk(0, st0);

    // stage qkw: 12 heads x 768, padded stride (overlaps chunk-0 fetch)
    {
        const float4* src = (const float4*)(g_qkw + (size_t)bn*(NH*Dm));
        #pragma unroll
        for (int i = 0; i < 6; i++) {
            int idx = tid + 384*i;
            int h = idx / 192, rem = idx - h*192;
            *(float4*)(qkw_s + h*TLD + rem*4) = src[idx];
        }
    }
    if (tid < 320) e_hr[tid] = 0.f;      // pad heads 12..15 stay zero
    if (tid < NH) denom[tid] = 0.f;

    // persistent AV accumulators: warp w owns output cols [w*64, w*64+64)
    wmma::fragment<wmma::accumulator, 16, 16, 8, float> av[4];
    #pragma unroll
    for (int ct = 0; ct < 4; ct++) wmma::fill_fragment(av[ct], 0.f);

    for (int lc = 0; lc < 16; lc++) {
        float* cur = (lc & 1) ? tile1 : tile0;
        if (lc < 15) {
            issue_chunk(lc+1, (lc & 1) ? st0 : st1);
            asm volatile("cp.async.wait_group 1;");
        } else {
            asm volatile("cp.async.wait_group 0;");
        }
        __syncthreads();

        // scores via wmma: warp w handles k-slice [64w, 64w+64)
        {
            wmma::fragment<wmma::accumulator, 16, 16, 8, float> d;
            wmma::fill_fragment(d, 0.f);
            #pragma unroll
            for (int ks = 0; ks < 8; ks++) {
                int k = w*64 + ks*8;
                wmma::fragment<wmma::matrix_a, 16, 16, 8, wmma::precision::tf32, wmma::row_major> af;
                wmma::load_matrix_sync(af, cur + k, TLD);
                #pragma unroll
                for (int e = 0; e < af.num_elements; e++) af.x[e] = wmma::__float_to_tf32(af.x[e]);
                wmma::fragment<wmma::matrix_b, 16, 16, 8, wmma::precision::tf32, wmma::col_major> bf;
                wmma::load_matrix_sync(bf, qkw_s + k, TLD);
                #pragma unroll
                for (int e = 0; e < bf.num_elements; e++) bf.x[e] = wmma::__float_to_tf32(bf.x[e]);
                wmma::mma_sync(d, af, bf, d);
            }
            wmma::store_matrix_sync(Dpart + w*16*DLD, d, DLD, wmma::mem_row_major);
        }
        __syncthreads();

        // reduce partials + exp; write both denominator form and transposed A form
        if (tid < 192) {
            int r = tid / 12, h = tid - r*12;
            float s = 0.f;
            #pragma unroll
            for (int w2 = 0; w2 < 12; w2++) s += Dpart[w2*16*DLD + r*DLD + h];
            float e = __expf(s);
            e_s[r*12 + h] = e;
            e_hr[h*ELD + r] = e;
        }
        __syncthreads();

        if (tid < NH) {
            float dsum = 0.f;
            #pragma unroll
            for (int r = 0; r < 16; r++) dsum += e_s[r*12 + tid];
            denom[tid] += dsum;
        }

        // AV via wmma: D[16hpad x 64cols] += E[16h x 16r] @ tile[16r x 64cols]
        {
            wmma::fragment<wmma::matrix_a, 16, 16, 8, wmma::precision::tf32, wmma::row_major> ea0, ea1;
            wmma::load_matrix_sync(ea0, e_hr,     ELD);   // A[:, r=0..7]
            wmma::load_matrix_sync(ea1, e_hr + 8, ELD);   // A[:, r=8..15]
            #pragma unroll
            for (int e = 0; e < ea0.num_elements; e++) ea0.x[e] = wmma::__float_to_tf32(ea0.x[e]);
            #pragma unroll
            for (int e = 0; e < ea1.num_elements; e++) ea1.x[e] = wmma::__float_to_tf32(ea1.x[e]);
            #pragma unroll
            for (int ct = 0; ct < 4; ct++) {
                int col = w*64 + ct*16;
                wmma::fragment<wmma::matrix_b, 16, 16, 8, wmma::precision::tf32, wmma::row_major> vb;
                wmma::load_matrix_sync(vb, cur + col, TLD);          // rows 0..7
                #pragma unroll
                for (int e = 0; e < vb.num_elements; e++) vb.x[e] = wmma::__float_to_tf32(vb.x[e]);
                wmma::mma_sync(av[ct], ea0, vb, av[ct]);
                wmma::load_matrix_sync(vb, cur + 8*TLD + col, TLD);  // rows 8..15
                #pragma unroll
                for (int e = 0; e < vb.num_elements; e++) vb.x[e] = wmma::__float_to_tf32(vb.x[e]);
                wmma::mma_sync(av[ct], ea1, vb, av[ct]);
            }
        }
        // no trailing sync needed: next iteration's top sync orders everything
    }

    // store AV accumulators to smem staging (reuse qkw_s/tile0 region: 16 x TLD)
    __syncthreads();
    #pragma unroll
    for (int ct = 0; ct < 4; ct++)
        wmma::store_matrix_sync(sm + w*64 + ct*16, av[ct], TLD, wmma::mem_row_major);
    __syncthreads();

    float4 d0 = *(const float4*)(denom);
    float4 d1 = *(const float4*)(denom + 4);
    float4 d2 = *(const float4*)(denom + 8);
    float inv[NH] = {1.f/d0.x, 1.f/d0.y, 1.f/d0.z, 1.f/d0.w,
                     1.f/d1.x, 1.f/d1.y, 1.f/d1.z, 1.f/d1.w,
                     1.f/d2.x, 1.f/d2.y, 1.f/d2.z, 1.f/d2.w};
    #pragma unroll
    for (int h = 0; h < NH; h++) {
        float2 v = *(const float2*)(sm + h*TLD + tid*2);
        float2 o = make_float2(v.x*inv[h], v.y*inv[h]);
        *(float2*)(g_avn + (size_t)bn*(NH*Dm) + h*768 + tid*2) = o;
    }
}

// ---------------- host ----------------
extern "C" void kernel_launch(void* const* d_in, const int* in_sizes, int n_in,
                              void* d_out, int out_size)
{
    const float* x     = (const float*)d_in[0];
    const float* w_in  = (const float*)d_in[1];
    const float* b_in  = (const float*)d_in[2];
    const float* w_out = (const float*)d_in[3];
    const float* b_out = (const float*)d_in[4];
    const float* w_fc1 = (const float*)d_in[5];
    const float* b_fc1 = (const float*)d_in[6];
    const float* w_fc2 = (const float*)d_in[7];
    const float* b_fc2 = (const float*)d_in[8];
    float* y = (float*)d_out;

    float *q, *qp, *qkw, *avn, *ctx, *o1, *h1;
    cudaGetSymbolAddress((void**)&q,   g_q);
    cudaGetSymbolAddress((void**)&qp,  g_qp);
    cudaGetSymbolAddress((void**)&qkw, g_qkw);
    cudaGetSymbolAddress((void**)&avn, g_avn);
    cudaGetSymbolAddress((void**)&ctx, g_ctx);
    cudaGetSymbolAddress((void**)&o1,  g_o1);
    cudaGetSymbolAddress((void**)&h1,  g_h1);

    // 1. token means
    mean_kernel<<<Bb*Dm*Tt, 224>>>(x);

    // 2. qp = (q @ wq^T + bq) * 0.125
    gemm_tc<true><<<dim3(12,13,1), 256>>>(q, w_in, b_in, qp,
        BN, Dm, Dm, Dm, Dm, Dm, 0,0,0,0, 0.125f, 0);

    // 3. qkw[.,h,:] = qp_h @ wk_h   (batched heads, K=64)
    gemm_tc<false><<<dim3(12,13,NH), 256>>>(qp, w_in + (size_t)Dm*Dm, nullptr, qkw,
        BN, Dm, HD, Dm, Dm, NH*Dm, HD, HD*Dm, Dm, 0, 1.f, 0);

    // 4. fused attention (tensor-core scores + AV, double-buffered)
    {
        static const size_t smem = 38336 * sizeof(float);
        cudaFuncSetAttribute(attn6, cudaFuncAttributeMaxDynamicSharedMemorySize, (int)smem);
        attn6<<<BN, 384, smem>>>(x);
    }

    // 5. ctx_h = avn_h @ wv_h^T + bv_h   (batched heads)
    gemm_tc<true><<<dim3(1,13,NH), 256>>>(avn, w_in + (size_t)2*Dm*Dm, b_in + 2*Dm, ctx,
        BN, HD, Dm, NH*Dm, Dm, Dm, Dm, HD*Dm, HD, HD, 1.f, 0);

    // 6. o1 = ctx @ w_out^T + b_out
    gemm_tc<true><<<dim3(12,13,1), 256>>>(ctx, w_out, b_out, o1,
        BN, Dm, Dm, Dm, Dm, Dm, 0,0,0,0, 1.f, 0);

    // 7. h1 = silu(o1 @ w_fc1^T + b_fc1)
    gemm_tc<true><<<dim3(48,13,1), 256>>>(o1, w_fc1, b_fc1, h1,
        BN, FFD, Dm, Dm, Dm, FFD, 0,0,0,0, 1.f, 1);

    // 8. y = h1 @ w_fc2^T + b_fc2
    gemm_tc<true><<<dim3(12,13,1), 256>>>(h1, w_fc2, b_fc2, y,
        BN, Dm, FFD, FFD, FFD, Dm, 0,0,0,0, 1.f, 0);
}

// round 9
// speedup vs baseline: 8.7252x; 1.8675x over previous
#include <cuda_runtime.h>
#include <cuda_fp16.h>
#include <math.h>
#include <stdint.h>
#include <mma.h>

using namespace nvcuda;

#define Bb   4
#define Dm   768
#define Tt   14
#define Np   196
#define NH   12
#define HD   64
#define FFD  3072
#define BN   (Bb*Np)       // 784
#define HW   224
#define CHW  (HW*HW)       // 50176

#define TLDH 776           // fp16 tile stride: 776*2=1552B; (1552/4)%32=4 -> conflict-free; %16=0
#define DLD  20            // Dpart fp32 leading dim
#define ELDH 24            // e_hr fp16 leading dim

// ---------------- scratch ----------------
__device__ __half g_xh [(size_t)Bb*Dm*CHW];   // x in fp16 (produced by mean_kernel)
__device__ __half g_qh [BN*Dm];
__device__ __half g_qph[BN*Dm];
__device__ __half g_qkwh[BN*NH*Dm];
__device__ __half g_avnh[BN*NH*Dm];
__device__ __half g_ctxh[BN*Dm];
__device__ __half g_o1h[BN*Dm];
__device__ __half g_h1h[BN*FFD];
// concatenated fp16 weights: w_in | w_out | w_fc1 | w_fc2
#define W_IN_OFF   0
#define W_OUT_OFF  (3*Dm*Dm)
#define W_FC1_OFF  (W_OUT_OFF + Dm*Dm)
#define W_FC2_OFF  (W_FC1_OFF + FFD*Dm)
__device__ __half g_wh[3*Dm*Dm + Dm*Dm + FFD*Dm + Dm*FFD];

__device__ __forceinline__ void cp_async16(uint32_t dst, const void* src) {
    asm volatile("cp.async.cg.shared.global [%0], [%1], 16;" :: "r"(dst), "l"(src));
}

// ---------------- fp32 -> fp16 convert ----------------
__global__ void f2h_kernel(const float* __restrict__ s, __half* __restrict__ d, int n) {
    int i = (blockIdx.x*256 + threadIdx.x)*4;
    if (i >= n) return;
    float4 v = *(const float4*)(s + i);
    ((__half2*)(d + i))[0] = __floats2half2_rn(v.x, v.y);
    ((__half2*)(d + i))[1] = __floats2half2_rn(v.z, v.w);
}

// ---------------- kernel 1: token means + x->fp16 ----------------
__global__ void mean_kernel(const float* __restrict__ x) {
    int bid = blockIdx.x;
    int t1 = bid % Tt;
    int dd = (bid / Tt) % Dm;
    int b  = bid / (Tt * Dm);
    size_t base = ((size_t)b*Dm + dd)*CHW + (size_t)t1*16*HW;
    const float* xp = x + base;
    __half* xo = g_xh + base;
    int j = threadIdx.x;
    float s = 0.f;
    #pragma unroll
    for (int r = 0; r < 16; r++) {
        float v = xp[(size_t)r*HW + j];
        xo[(size_t)r*HW + j] = __float2half(v);
        s += v;
    }
    __shared__ float cs[224];
    cs[j] = s;
    __syncthreads();
    if (j < Tt) {
        float t = 0.f;
        #pragma unroll
        for (int k = 0; k < 16; k++) t += cs[j*16 + k];
        g_qh[((size_t)b*Np + t1*Tt + j)*Dm + dd] = __float2half(t * (1.0f/256.0f));
    }
}

// ---------------- fp16 tensor-core GEMM, cp.async double-buffered, BK=64 ----------------
// C = gamma*(A@B(^T) + bias), optional silu. Outputs: C32 (fp32) and/or C16 (fp16), either nullable.
// TRANSB=1: B(k,n)=Bm[n*ldb+k];  TRANSB=0: B(k,n)=Bm[k*ldb+n].  blockIdx.z = head slice.
// 64x64 tile, 256 thr = 8 warps (4M x 2N), warp 16x32, wmma m16n16k16 fp16.
template<bool TRANSB>
__global__ __launch_bounds__(256) void gemm_hc(
    const __half* __restrict__ A, const __half* __restrict__ Bm,
    const float* __restrict__ bias, float* __restrict__ C32, __half* __restrict__ C16,
    int M, int N, int K, int lda, int ldb, int ldc,
    int sAh, int sBh, int sCh, int sBiasH,
    float gamma, int silu)
{
    int h = blockIdx.z;
    A  += (size_t)h * sAh;
    Bm += (size_t)h * sBh;
    const float* biasp = bias ? bias + (size_t)h * sBiasH : nullptr;

    __shared__ __half hbuf[2*2*64*72];   // [stage][A|B][64][72]
    uint32_t sb = (uint32_t)__cvta_generic_to_shared(hbuf);

    int m0 = blockIdx.y * 64, n0 = blockIdx.x * 64;
    int tid = threadIdx.x;
    int warpId = tid >> 5;
    int wm = warpId >> 1;
    int wn = warpId & 1;

    wmma::fragment<wmma::accumulator, 16, 16, 16, float> cf[2];
    wmma::fill_fragment(cf[0], 0.f);
    wmma::fill_fragment(cf[1], 0.f);

    const int nk = K >> 6;

    auto issue = [&](int it, int s) {
        int k0 = it * 64;
        uint32_t abase = sb + (uint32_t)(s * 9216 * 2);
        uint32_t bbase = abase + 4608*2;
        #pragma unroll
        for (int i = 0; i < 2; i++) {
            int idx = tid + 256*i;          // 0..511
            int row = idx >> 3, seg = idx & 7;
            int m = m0 + row; if (m >= M) m = M - 1;
            cp_async16(abase + (uint32_t)((row*72 + seg*8)*2),
                       A + (size_t)m*lda + k0 + seg*8);
        }
        if (TRANSB) {
            #pragma unroll
            for (int i = 0; i < 2; i++) {
                int idx = tid + 256*i;
                int nn = idx >> 3, seg = idx & 7;
                int ng = n0 + nn; if (ng >= N) ng = N - 1;
                cp_async16(bbase + (uint32_t)((nn*72 + seg*8)*2),
                           Bm + (size_t)ng*ldb + k0 + seg*8);
            }
        } else {
            #pragma unroll
            for (int i = 0; i < 2; i++) {
                int idx = tid + 256*i;
                int kk = idx >> 3, seg = idx & 7;
                int nb = n0 + seg*8; if (nb >= N) nb = 0;
                cp_async16(bbase + (uint32_t)((kk*72 + seg*8)*2),
                           Bm + (size_t)(k0+kk)*ldb + nb);
            }
        }
        asm volatile("cp.async.commit_group;");
    };

    issue(0, 0);

    for (int it = 0; it < nk; it++) {
        int s = it & 1;
        if (it + 1 < nk) {
            issue(it+1, s^1);
            asm volatile("cp.async.wait_group 1;");
        } else {
            asm volatile("cp.async.wait_group 0;");
        }
        __syncthreads();

        const __half* As = hbuf + s*9216;
        const __half* Bs = As + 4608;

        #pragma unroll
        for (int ks = 0; ks < 4; ks++) {
            wmma::fragment<wmma::matrix_a, 16, 16, 16, __half, wmma::row_major> af;
            wmma::load_matrix_sync(af, As + (wm*16)*72 + ks*16, 72);
            #pragma unroll
            for (int j = 0; j < 2; j++) {
                if (TRANSB) {
                    wmma::fragment<wmma::matrix_b, 16, 16, 16, __half, wmma::col_major> bf;
                    wmma::load_matrix_sync(bf, Bs + (wn*32 + j*16)*72 + ks*16, 72);
                    wmma::mma_sync(cf[j], af, bf, cf[j]);
                } else {
                    wmma::fragment<wmma::matrix_b, 16, 16, 16, __half, wmma::row_major> bf;
                    wmma::load_matrix_sync(bf, Bs + (ks*16)*72 + wn*32 + j*16, 72);
                    wmma::mma_sync(cf[j], af, bf, cf[j]);
                }
            }
        }
        __syncthreads();
    }

    // epilogue: stage fp32 in smem (reuse hbuf)
    float (*Cs)[68] = (float(*)[68])hbuf;
    wmma::store_matrix_sync(&Cs[wm*16][wn*32],      cf[0], 68, wmma::mem_row_major);
    wmma::store_matrix_sync(&Cs[wm*16][wn*32 + 16], cf[1], 68, wmma::mem_row_major);
    __syncthreads();

    #pragma unroll
    for (int i = 0; i < 4; i++) {
        int e = tid + 256*i;
        int row = e >> 4, seg = e & 15;
        int m = m0 + row, nbase = n0 + seg*4;
        if (m >= M || nbase >= N) continue;
        float4 v = *(const float4*)&Cs[row][seg*4];
        if (biasp) {
            float4 bv = *(const float4*)(biasp + nbase);
            v.x += bv.x; v.y += bv.y; v.z += bv.z; v.w += bv.w;
        }
        v.x *= gamma; v.y *= gamma; v.z *= gamma; v.w *= gamma;
        if (silu) {
            v.x = v.x/(1.f+__expf(-v.x)); v.y = v.y/(1.f+__expf(-v.y));
            v.z = v.z/(1.f+__expf(-v.z)); v.w = v.w/(1.f+__expf(-v.w));
        }
        if (C32) *(float4*)(C32 + (size_t)m*ldc + nbase + (size_t)h*sCh) = v;
        if (C16) {
            __half2 h0 = __floats2half2_rn(v.x, v.y);
            __half2 h1 = __floats2half2_rn(v.z, v.w);
            __half2* dst = (__half2*)(C16 + (size_t)m*ldc + nbase + (size_t)h*sCh);
            dst[0] = h0; dst[1] = h1;
        }
    }
}

// ---------------- fused attention v7: fp16 tiles, fp16 MMA, triple buffer ----------------
// smem bytes: qkw 18624 | tiles 3x24832 | Dpart 15360 | e_s 768 | e_hr 768 | denom 64 = 110080
__global__ __launch_bounds__(384, 1) void attn7() {
    extern __shared__ __half smh[];
    __half* qkw_s = smh;                       // [12][TLDH]
    __half* tiles = smh + 12*TLDH;             // 3 x [16][TLDH]
    float*  Dpart = (float*)(smh + 12*TLDH + 3*16*TLDH);   // [12][16][DLD]
    float*  e_s   = Dpart + 12*16*DLD;         // [r][12]
    __half* e_hr  = (__half*)(e_s + 192);      // [16][ELDH]
    float*  denom = (float*)(e_hr + 16*ELDH);  // 16

    int bn = blockIdx.x;
    int b = bn / Np, n = bn % Np;
    int t1 = n / Tt, t2 = n % Tt;
    const __half* xph = g_xh + (size_t)b*Dm*CHW + (size_t)(t1*16)*HW + t2*16;

    int tid = threadIdx.x, w = tid >> 5;

    auto issue_chunk = [&](int lc) {
        uint32_t stp = (uint32_t)__cvta_generic_to_shared(tiles + (lc % 3)*16*TLDH);
        #pragma unroll
        for (int j = 0; j < 4; j++) {
            int ch = tid + 384*j;              // 0..1535 16B chunks
            int idx8 = ch*8;                   // half index in [0,12288)
            int r = idx8 / 768, cc = idx8 - r*768;
            int flat = lc*12288 + idx8;
            int dd = flat >> 8, g1 = (flat >> 4) & 15, g2 = flat & 15;  // g2 in {0,8}
            cp_async16(stp + (uint32_t)((r*TLDH + cc)*2), xph + (size_t)dd*CHW + g1*HW + g2);
        }
        asm volatile("cp.async.commit_group;");
    };

    issue_chunk(0);
    issue_chunk(1);

    // stage qkw (12x768 fp16, padded stride) — overlaps chunk fetches
    {
        const __half* src = g_qkwh + (size_t)bn*(NH*Dm);
        #pragma unroll
        for (int i = 0; i < 3; i++) {
            int idx = tid + 384*i;             // 0..1151 16B chunks
            int hh = idx / 96, rem = idx - hh*96;
            *(float4*)(qkw_s + hh*TLDH + rem*8) = *(const float4*)(src + idx*8);
        }
    }
    if (tid < 16*ELDH) e_hr[tid] = __float2half(0.f);
    if (tid < NH) denom[tid] = 0.f;

    wmma::fragment<wmma::accumulator, 16, 16, 16, float> av[4];
    #pragma unroll
    for (int ct = 0; ct < 4; ct++) wmma::fill_fragment(av[ct], 0.f);

    for (int lc = 0; lc < 16; lc++) {
        const __half* cur = tiles + (lc % 3)*16*TLDH;
        if (lc < 15) asm volatile("cp.async.wait_group 1;");
        else         asm volatile("cp.async.wait_group 0;");
        __syncthreads();   // chunk lc ready; also proves chunk lc-1 fully consumed by all warps
        if (lc + 2 <= 15) issue_chunk(lc + 2);   // safe: targets buffer of lc-1

        // scores: warp w handles k-slice [64w, 64w+64), fp16 mma k16
        {
            wmma::fragment<wmma::accumulator, 16, 16, 16, float> d;
            wmma::fill_fragment(d, 0.f);
            #pragma unroll
            for (int ks = 0; ks < 4; ks++) {
                int k = w*64 + ks*16;
                wmma::fragment<wmma::matrix_a, 16, 16, 16, __half, wmma::row_major> af;
                wmma::load_matrix_sync(af, cur + k, TLDH);
                // B cols 12..15 alias past qkw_s into tiles (defined, never used)
                wmma::fragment<wmma::matrix_b, 16, 16, 16, __half, wmma::col_major> bf;
                wmma::load_matrix_sync(bf, qkw_s + k, TLDH);
                wmma::mma_sync(d, af, bf, d);
            }
            wmma::store_matrix_sync(Dpart + w*16*DLD, d, DLD, wmma::mem_row_major);
        }
        __syncthreads();

        // reduce partials + exp
        if (tid < 192) {
            int r = tid / 12, hh = tid - r*12;
            float s = 0.f;
            #pragma unroll
            for (int w2 = 0; w2 < 12; w2++) s += Dpart[w2*16*DLD + r*DLD + hh];
            float e = __expf(s);
            e_s[r*12 + hh] = e;
            e_hr[hh*ELDH + r] = __float2half(e);
        }
        __syncthreads();

        if (tid < NH) {
            float dsum = 0.f;
            #pragma unroll
            for (int r = 0; r < 16; r++) dsum += e_s[r*12 + tid];
            denom[tid] += dsum;
        }

        // AV: av[16hpad x 64cols] += E[16h x 16r] @ cur[16r x 64cols]  (one k16 mma per col-tile)
        {
            wmma::fragment<wmma::matrix_a, 16, 16, 16, __half, wmma::row_major> ef;
            wmma::load_matrix_sync(ef, e_hr, ELDH);
            #pragma unroll
            for (int ct = 0; ct < 4; ct++) {
                wmma::fragment<wmma::matrix_b, 16, 16, 16, __half, wmma::row_major> vb;
                wmma::load_matrix_sync(vb, cur + w*64 + ct*16, TLDH);
                wmma::mma_sync(av[ct], ef, vb, av[ct]);
            }
        }
        // ordering for reuse of cur's buffer is provided by the top-of-loop syncs
    }

    // stage AV accumulators to smem (fp32, reuse front of smem), normalize, write fp16
    __syncthreads();
    float* stage = (float*)smh;                // [16][772]
    #pragma unroll
    for (int ct = 0; ct < 4; ct++)
        wmma::store_matrix_sync(stage + w*64 + ct*16, av[ct], 772, wmma::mem_row_major);
    __syncthreads();

    float4 d0 = *(const float4*)(denom);
    float4 d1 = *(const float4*)(denom + 4);
    float4 d2 = *(const float4*)(denom + 8);
    float inv[NH] = {1.f/d0.x, 1.f/d0.y, 1.f/d0.z, 1.f/d0.w,
                     1.f/d1.x, 1.f/d1.y, 1.f/d1.z, 1.f/d1.w,
                     1.f/d2.x, 1.f/d2.y, 1.f/d2.z, 1.f/d2.w};
    #pragma unroll
    for (int hh = 0; hh < NH; hh++) {
        float a = stage[hh*772 + tid*2]     * inv[hh];
        float c = stage[hh*772 + tid*2 + 1] * inv[hh];
        *(__half2*)(g_avnh + (size_t)bn*(NH*Dm) + hh*768 + tid*2) = __floats2half2_rn(a, c);
    }
}

// ---------------- host ----------------
extern "C" void kernel_launch(void* const* d_in, const int* in_sizes, int n_in,
                              void* d_out, int out_size)
{
    const float* x     = (const float*)d_in[0];
    const float* w_in  = (const float*)d_in[1];
    const float* b_in  = (const float*)d_in[2];
    const float* w_out = (const float*)d_in[3];
    const float* b_out = (const float*)d_in[4];
    const float* w_fc1 = (const float*)d_in[5];
    const float* b_fc1 = (const float*)d_in[6];
    const float* w_fc2 = (const float*)d_in[7];
    const float* b_fc2 = (const float*)d_in[8];
    float* y = (float*)d_out;

    __half *qh, *qph, *qkwh, *avnh, *ctxh, *o1h, *h1h, *wh;
    cudaGetSymbolAddress((void**)&qh,   g_qh);
    cudaGetSymbolAddress((void**)&qph,  g_qph);
    cudaGetSymbolAddress((void**)&qkwh, g_qkwh);
    cudaGetSymbolAddress((void**)&avnh, g_avnh);
    cudaGetSymbolAddress((void**)&ctxh, g_ctxh);
    cudaGetSymbolAddress((void**)&o1h,  g_o1h);
    cudaGetSymbolAddress((void**)&h1h,  g_h1h);
    cudaGetSymbolAddress((void**)&wh,   g_wh);

    // 0. weight conversions (independent)
    f2h_kernel<<<(3*Dm*Dm/4 + 255)/256, 256>>>(w_in,  wh + W_IN_OFF,  3*Dm*Dm);
    f2h_kernel<<<(Dm*Dm/4   + 255)/256, 256>>>(w_out, wh + W_OUT_OFF, Dm*Dm);
    f2h_kernel<<<(FFD*Dm/4  + 255)/256, 256>>>(w_fc1, wh + W_FC1_OFF, FFD*Dm);
    f2h_kernel<<<(Dm*FFD/4  + 255)/256, 256>>>(w_fc2, wh + W_FC2_OFF, Dm*FFD);

    // 1. token means + x->fp16
    mean_kernel<<<Bb*Dm*Tt, 224>>>(x);

    // 2. qp = (q @ wq^T + bq) * 0.125   -> fp16
    gemm_hc<true><<<dim3(12,13,1), 256>>>(qh, wh + W_IN_OFF, b_in, nullptr, qph,
        BN, Dm, Dm, Dm, Dm, Dm, 0,0,0,0, 0.125f, 0);

    // 3. qkw[.,h,:] = qp_h @ wk_h  (batched heads, K=64) -> fp16
    gemm_hc<false><<<dim3(12,13,NH), 256>>>(qph, wh + W_IN_OFF + Dm*Dm, nullptr, nullptr, qkwh,
        BN, Dm, HD, Dm, Dm, NH*Dm, HD, HD*Dm, Dm, 0, 1.f, 0);

    // 4. fused attention -> avn fp16
    {
        static const size_t smem = 110080;
        cudaFuncSetAttribute(attn7, cudaFuncAttributeMaxDynamicSharedMemorySize, (int)smem);
        attn7<<<BN, 384, smem>>>();
    }

    // 5. ctx_h = avn_h @ wv_h^T + bv_h  (batched heads) -> fp16
    gemm_hc<true><<<dim3(1,13,NH), 256>>>(avnh, wh + W_IN_OFF + 2*Dm*Dm, b_in + 2*Dm, nullptr, ctxh,
        BN, HD, Dm, NH*Dm, Dm, Dm, Dm, HD*Dm, HD, HD, 1.f, 0);

    // 6. o1 = ctx @ w_out^T + b_out -> fp16
    gemm_hc<true><<<dim3(12,13,1), 256>>>(ctxh, wh + W_OUT_OFF, b_out, nullptr, o1h,
        BN, Dm, Dm, Dm, Dm, Dm, 0,0,0,0, 1.f, 0);

    // 7. h1 = silu(o1 @ w_fc1^T + b_fc1) -> fp16
    gemm_hc<true><<<dim3(48,13,1), 256>>>(o1h, wh + W_FC1_OFF, b_fc1, nullptr, h1h,
        BN, FFD, Dm, Dm, Dm, FFD, 0,0,0,0, 1.f, 1);

    // 8. y = h1 @ w_fc2^T + b_fc2 -> fp32 output
    gemm_hc<true><<<dim3(12,13,1), 256>>>(h1h, wh + W_FC2_OFF, b_fc2, y, nullptr,
        BN, Dm, FFD, FFD, FFD, Dm, 0,0,0,0, 1.f, 0);
}

// round 10
// speedup vs baseline: 8.9605x; 1.0270x over previous
#include <cuda_runtime.h>
#include <cuda_fp16.h>
#include <math.h>
#include <stdint.h>
#include <mma.h>

using namespace nvcuda;

#define Bb   4
#define Dm   768
#define Tt   14
#define Np   196
#define NH   12
#define HD   64
#define FFD  3072
#define BN   (Bb*Np)       // 784
#define HW   224
#define CHW  (HW*HW)       // 50176
#define MP   896           // padded M for 128-tiles (7*128)

#define TLDH 776
#define DLD  20
#define ELDH 24

// ---------------- scratch ----------------
__device__ __half g_xh [(size_t)Bb*Dm*CHW];
__device__ __half g_qh [BN*Dm];
__device__ __half g_qph[BN*Dm];
__device__ __half g_qkwh[BN*NH*Dm];
__device__ __half g_avnh[BN*NH*Dm];
__device__ __half g_ctxh[BN*Dm];
__device__ __half g_o1h[BN*Dm];
__device__ __half g_h1h[BN*FFD];
__device__ float  g_part[(size_t)MP*FFD];       // split-K partials / raw fp32 GEMM out
// concatenated fp16 weights
#define W_IN_OFF   0
#define W_OUT_OFF  (3*Dm*Dm)                    // 1769472
#define W_FC1_OFF  (W_OUT_OFF + Dm*Dm)          // 2359296
#define W_FC2_OFF  (W_FC1_OFF + FFD*Dm)         // 4718592
#define W_TOTAL    (W_FC2_OFF + Dm*FFD)         // 7077888
__device__ __half g_wh[W_TOTAL];

__device__ __forceinline__ void cp_async16(uint32_t dst, const void* src) {
    asm volatile("cp.async.cg.shared.global [%0], [%1], 16;" :: "r"(dst), "l"(src));
}

// ---------------- fused fp32->fp16 weight conversion ----------------
__global__ void f2h_all(const float* __restrict__ s0, const float* __restrict__ s1,
                        const float* __restrict__ s2, const float* __restrict__ s3,
                        __half* __restrict__ d) {
    int i = (blockIdx.x*256 + threadIdx.x)*4;
    if (i >= W_TOTAL) return;
    const float* s; int off;
    if      (i < W_OUT_OFF) { s = s0; off = 0; }
    else if (i < W_FC1_OFF) { s = s1; off = W_OUT_OFF; }
    else if (i < W_FC2_OFF) { s = s2; off = W_FC1_OFF; }
    else                    { s = s3; off = W_FC2_OFF; }
    float4 v = *(const float4*)(s + (i - off));
    ((__half2*)(d + i))[0] = __floats2half2_rn(v.x, v.y);
    ((__half2*)(d + i))[1] = __floats2half2_rn(v.z, v.w);
}

// ---------------- token means + x->fp16 ----------------
__global__ void mean_kernel(const float* __restrict__ x) {
    int bid = blockIdx.x;
    int t1 = bid % Tt;
    int dd = (bid / Tt) % Dm;
    int b  = bid / (Tt * Dm);
    size_t base = ((size_t)b*Dm + dd)*CHW + (size_t)t1*16*HW;
    const float* xp = x + base;
    __half* xo = g_xh + base;
    int j = threadIdx.x;
    float s = 0.f;
    #pragma unroll
    for (int r = 0; r < 16; r++) {
        float v = xp[(size_t)r*HW + j];
        xo[(size_t)r*HW + j] = __float2half(v);
        s += v;
    }
    __shared__ float cs[224];
    cs[j] = s;
    __syncthreads();
    if (j < Tt) {
        float t = 0.f;
        #pragma unroll
        for (int k = 0; k < 16; k++) t += cs[j*16 + k];
        g_qh[((size_t)b*Np + t1*Tt + j)*Dm + dd] = __float2half(t * (1.0f/256.0f));
    }
}

// ---------------- 128x128 fp16 GEMM (TRANSB), raw fp32 partial output, split-K via z ----------------
// P[z][MP][N] += A[m,kslice] @ B[n,kslice]^T   (no bias/act here; epi_kernel finishes)
__global__ __launch_bounds__(256) void gemm128(
    const __half* __restrict__ A, const __half* __restrict__ Bm,
    float* __restrict__ P, int M, int N, int K, int lda, int ldb, int KS)
{
    extern __shared__ __half dbuf[];     // 2 stages x (A 128x72 | B 128x72) halfs
    uint32_t sb = (uint32_t)__cvta_generic_to_shared(dbuf);

    int m0 = blockIdx.y * 128, n0 = blockIdx.x * 128;
    int z = blockIdx.z;
    int Ksub = K / KS;
    int kbase = z * Ksub;
    int tid = threadIdx.x;
    int warpId = tid >> 5;
    int wm = warpId >> 2;      // 0..1 -> rows wm*64
    int wn = warpId & 3;       // 0..3 -> cols wn*32

    wmma::fragment<wmma::accumulator, 16, 16, 16, float> acc[4][2];
    #pragma unroll
    for (int i = 0; i < 4; i++)
        #pragma unroll
        for (int j = 0; j < 2; j++) wmma::fill_fragment(acc[i][j], 0.f);

    const int nk = Ksub >> 6;

    auto issue = [&](int it, int s) {
        int k0 = kbase + it*64;
        uint32_t abase = sb + (uint32_t)(s * 18432 * 2);
        uint32_t bbase = abase + 9216*2;
        #pragma unroll
        for (int i = 0; i < 4; i++) {
            int idx = tid + 256*i;           // 0..1023
            int row = idx >> 3, seg = idx & 7;
            int m = m0 + row; if (m >= M) m = M - 1;
            cp_async16(abase + (uint32_t)((row*72 + seg*8)*2),
                       A + (size_t)m*lda + k0 + seg*8);
        }
        #pragma unroll
        for (int i = 0; i < 4; i++) {
            int idx = tid + 256*i;
            int nn = idx >> 3, seg = idx & 7;
            int ng = n0 + nn; if (ng >= N) ng = N - 1;
            cp_async16(bbase + (uint32_t)((nn*72 + seg*8)*2),
                       Bm + (size_t)ng*ldb + k0 + seg*8);
        }
        asm volatile("cp.async.commit_group;");
    };

    issue(0, 0);

    for (int it = 0; it < nk; it++) {
        int s = it & 1;
        if (it + 1 < nk) {
            issue(it+1, s^1);
            asm volatile("cp.async.wait_group 1;");
        } else {
            asm volatile("cp.async.wait_group 0;");
        }
        __syncthreads();

        const __half* As = dbuf + s*18432;
        const __half* Bs = As + 9216;

        #pragma unroll
        for (int ks = 0; ks < 4; ks++) {
            wmma::fragment<wmma::matrix_b, 16, 16, 16, __half, wmma::col_major> bf[2];
            #pragma unroll
            for (int j = 0; j < 2; j++)
                wmma::load_matrix_sync(bf[j], Bs + (wn*32 + j*16)*72 + ks*16, 72);
            #pragma unroll
            for (int i = 0; i < 4; i++) {
                wmma::fragment<wmma::matrix_a, 16, 16, 16, __half, wmma::row_major> af;
                wmma::load_matrix_sync(af, As + (wm*64 + i*16)*72 + ks*16, 72);
                #pragma unroll
                for (int j = 0; j < 2; j++)
                    wmma::mma_sync(acc[i][j], af, bf[j], acc[i][j]);
            }
        }
        __syncthreads();
    }

    // direct fp32 fragment store to padded partial buffer (rows up to MP-1 always in-bounds)
    float* base = P + (size_t)z*MP*N;
    #pragma unroll
    for (int i = 0; i < 4; i++)
        #pragma unroll
        for (int j = 0; j < 2; j++)
            wmma::store_matrix_sync(base + (size_t)(m0 + wm*64 + i*16)*N + n0 + wn*32 + j*16,
                                    acc[i][j], N, wmma::mem_row_major);
}

// ---------------- GEMM epilogue: sum split-K partials + bias, gamma, silu -> fp16/fp32 ----------------
__global__ void epi_kernel(const float* __restrict__ P, const float* __restrict__ bias,
                           float* __restrict__ out32, __half* __restrict__ out16,
                           int MN, int N, int KS, float gamma, int silu)
{
    int i = (blockIdx.x*256 + threadIdx.x)*4;
    if (i >= MN) return;
    int c = i % N;
    float4 s = *(const float4*)(P + i);
    for (int ks = 1; ks < KS; ks++) {
        const float* pp = P + (size_t)ks*MP*N + i;
        float4 p = *(const float4*)pp;
        s.x += p.x; s.y += p.y; s.z += p.z; s.w += p.w;
    }
    float4 bv = *(const float4*)(bias + c);
    s.x = (s.x + bv.x)*gamma; s.y = (s.y + bv.y)*gamma;
    s.z = (s.z + bv.z)*gamma; s.w = (s.w + bv.w)*gamma;
    if (silu) {
        s.x = s.x/(1.f+__expf(-s.x)); s.y = s.y/(1.f+__expf(-s.y));
        s.z = s.z/(1.f+__expf(-s.z)); s.w = s.w/(1.f+__expf(-s.w));
    }
    if (out32) *(float4*)(out32 + i) = s;
    if (out16) {
        ((__half2*)(out16 + i))[0] = __floats2half2_rn(s.x, s.y);
        ((__half2*)(out16 + i))[1] = __floats2half2_rn(s.z, s.w);
    }
}

// ---------------- 64x64 fp16 GEMM (kept for qkw / ctx, batched heads) ----------------
template<bool TRANSB>
__global__ __launch_bounds__(256) void gemm_hc(
    const __half* __restrict__ A, const __half* __restrict__ Bm,
    const float* __restrict__ bias, float* __restrict__ C32, __half* __restrict__ C16,
    int M, int N, int K, int lda, int ldb, int ldc,
    int sAh, int sBh, int sCh, int sBiasH,
    float gamma, int silu)
{
    int h = blockIdx.z;
    A  += (size_t)h * sAh;
    Bm += (size_t)h * sBh;
    const float* biasp = bias ? bias + (size_t)h * sBiasH : nullptr;

    __shared__ __half hbuf[2*2*64*72];
    uint32_t sb = (uint32_t)__cvta_generic_to_shared(hbuf);

    int m0 = blockIdx.y * 64, n0 = blockIdx.x * 64;
    int tid = threadIdx.x;
    int warpId = tid >> 5;
    int wm = warpId >> 1;
    int wn = warpId & 1;

    wmma::fragment<wmma::accumulator, 16, 16, 16, float> cf[2];
    wmma::fill_fragment(cf[0], 0.f);
    wmma::fill_fragment(cf[1], 0.f);

    const int nk = K >> 6;

    auto issue = [&](int it, int s) {
        int k0 = it * 64;
        uint32_t abase = sb + (uint32_t)(s * 9216 * 2);
        uint32_t bbase = abase + 4608*2;
        #pragma unroll
        for (int i = 0; i < 2; i++) {
            int idx = tid + 256*i;
            int row = idx >> 3, seg = idx & 7;
            int m = m0 + row; if (m >= M) m = M - 1;
            cp_async16(abase + (uint32_t)((row*72 + seg*8)*2),
                       A + (size_t)m*lda + k0 + seg*8);
        }
        if (TRANSB) {
            #pragma unroll
            for (int i = 0; i < 2; i++) {
                int idx = tid + 256*i;
                int nn = idx >> 3, seg = idx & 7;
                int ng = n0 + nn; if (ng >= N) ng = N - 1;
                cp_async16(bbase + (uint32_t)((nn*72 + seg*8)*2),
                           Bm + (size_t)ng*ldb + k0 + seg*8);
            }
        } else {
            #pragma unroll
            for (int i = 0; i < 2; i++) {
                int idx = tid + 256*i;
                int kk = idx >> 3, seg = idx & 7;
                int nb = n0 + seg*8; if (nb >= N) nb = 0;
                cp_async16(bbase + (uint32_t)((kk*72 + seg*8)*2),
                           Bm + (size_t)(k0+kk)*ldb + nb);
            }
        }
        asm volatile("cp.async.commit_group;");
    };

    issue(0, 0);

    for (int it = 0; it < nk; it++) {
        int s = it & 1;
        if (it + 1 < nk) {
            issue(it+1, s^1);
            asm volatile("cp.async.wait_group 1;");
        } else {
            asm volatile("cp.async.wait_group 0;");
        }
        __syncthreads();

        const __half* As = hbuf + s*9216;
        const __half* Bs = As + 4608;

        #pragma unroll
        for (int ks = 0; ks < 4; ks++) {
            wmma::fragment<wmma::matrix_a, 16, 16, 16, __half, wmma::row_major> af;
            wmma::load_matrix_sync(af, As + (wm*16)*72 + ks*16, 72);
            #pragma unroll
            for (int j = 0; j < 2; j++) {
                if (TRANSB) {
                    wmma::fragment<wmma::matrix_b, 16, 16, 16, __half, wmma::col_major> bf;
                    wmma::load_matrix_sync(bf, Bs + (wn*32 + j*16)*72 + ks*16, 72);
                    wmma::mma_sync(cf[j], af, bf, cf[j]);
                } else {
                    wmma::fragment<wmma::matrix_b, 16, 16, 16, __half, wmma::row_major> bf;
                    wmma::load_matrix_sync(bf, Bs + (ks*16)*72 + wn*32 + j*16, 72);
                    wmma::mma_sync(cf[j], af, bf, cf[j]);
                }
            }
        }
        __syncthreads();
    }

    float (*Cs)[68] = (float(*)[68])hbuf;
    wmma::store_matrix_sync(&Cs[wm*16][wn*32],      cf[0], 68, wmma::mem_row_major);
    wmma::store_matrix_sync(&Cs[wm*16][wn*32 + 16], cf[1], 68, wmma::mem_row_major);
    __syncthreads();

    #pragma unroll
    for (int i = 0; i < 4; i++) {
        int e = tid + 256*i;
        int row = e >> 4, seg = e & 15;
        int m = m0 + row, nbase = n0 + seg*4;
        if (m >= M || nbase >= N) continue;
        float4 v = *(const float4*)&Cs[row][seg*4];
        if (biasp) {
            float4 bv = *(const float4*)(biasp + nbase);
            v.x += bv.x; v.y += bv.y; v.z += bv.z; v.w += bv.w;
        }
        v.x *= gamma; v.y *= gamma; v.z *= gamma; v.w *= gamma;
        if (silu) {
            v.x = v.x/(1.f+__expf(-v.x)); v.y = v.y/(1.f+__expf(-v.y));
            v.z = v.z/(1.f+__expf(-v.z)); v.w = v.w/(1.f+__expf(-v.w));
        }
        if (C32) *(float4*)(C32 + (size_t)m*ldc + nbase + (size_t)h*sCh) = v;
        if (C16) {
            __half2 h0 = __floats2half2_rn(v.x, v.y);
            __half2 h1 = __floats2half2_rn(v.z, v.w);
            __half2* dst = (__half2*)(C16 + (size_t)m*ldc + nbase + (size_t)h*sCh);
            dst[0] = h0; dst[1] = h1;
        }
    }
}

// ---------------- fused attention v7 (unchanged from R9) ----------------
__global__ __launch_bounds__(384, 1) void attn7() {
    extern __shared__ __half smh[];
    __half* qkw_s = smh;
    __half* tiles = smh + 12*TLDH;
    float*  Dpart = (float*)(smh + 12*TLDH + 3*16*TLDH);
    float*  e_s   = Dpart + 12*16*DLD;
    __half* e_hr  = (__half*)(e_s + 192);
    float*  denom = (float*)(e_hr + 16*ELDH);

    int bn = blockIdx.x;
    int b = bn / Np, n = bn % Np;
    int t1 = n / Tt, t2 = n % Tt;
    const __half* xph = g_xh + (size_t)b*Dm*CHW + (size_t)(t1*16)*HW + t2*16;

    int tid = threadIdx.x, w = tid >> 5;

    auto issue_chunk = [&](int lc) {
        uint32_t stp = (uint32_t)__cvta_generic_to_shared(tiles + (lc % 3)*16*TLDH);
        #pragma unroll
        for (int j = 0; j < 4; j++) {
            int ch = tid + 384*j;
            int idx8 = ch*8;
            int r = idx8 / 768, cc = idx8 - r*768;
            int flat = lc*12288 + idx8;
            int dd = flat >> 8, g1 = (flat >> 4) & 15, g2 = flat & 15;
            cp_async16(stp + (uint32_t)((r*TLDH + cc)*2), xph + (size_t)dd*CHW + g1*HW + g2);
        }
        asm volatile("cp.async.commit_group;");
    };

    issue_chunk(0);
    issue_chunk(1);

    {
        const __half* src = g_qkwh + (size_t)bn*(NH*Dm);
        #pragma unroll
        for (int i = 0; i < 3; i++) {
            int idx = tid + 384*i;
            int hh = idx / 96, rem = idx - hh*96;
            *(float4*)(qkw_s + hh*TLDH + rem*8) = *(const float4*)(src + idx*8);
        }
    }
    if (tid < 16*ELDH) e_hr[tid] = __float2half(0.f);
    if (tid < NH) denom[tid] = 0.f;

    wmma::fragment<wmma::accumulator, 16, 16, 16, float> av[4];
    #pragma unroll
    for (int ct = 0; ct < 4; ct++) wmma::fill_fragment(av[ct], 0.f);

    for (int lc = 0; lc < 16; lc++) {
        const __half* cur = tiles + (lc % 3)*16*TLDH;
        if (lc < 15) asm volatile("cp.async.wait_group 1;");
        else         asm volatile("cp.async.wait_group 0;");
        __syncthreads();
        if (lc + 2 <= 15) issue_chunk(lc + 2);

        {
            wmma::fragment<wmma::accumulator, 16, 16, 16, float> d;
            wmma::fill_fragment(d, 0.f);
            #pragma unroll
            for (int ks = 0; ks < 4; ks++) {
                int k = w*64 + ks*16;
                wmma::fragment<wmma::matrix_a, 16, 16, 16, __half, wmma::row_major> af;
                wmma::load_matrix_sync(af, cur + k, TLDH);
                wmma::fragment<wmma::matrix_b, 16, 16, 16, __half, wmma::col_major> bf;
                wmma::load_matrix_sync(bf, qkw_s + k, TLDH);
                wmma::mma_sync(d, af, bf, d);
            }
            wmma::store_matrix_sync(Dpart + w*16*DLD, d, DLD, wmma::mem_row_major);
        }
        __syncthreads();

        if (tid < 192) {
            int r = tid / 12, hh = tid - r*12;
            float s = 0.f;
            #pragma unroll
            for (int w2 = 0; w2 < 12; w2++) s += Dpart[w2*16*DLD + r*DLD + hh];
            float e = __expf(s);
            e_s[r*12 + hh] = e;
            e_hr[hh*ELDH + r] = __float2half(e);
        }
        __syncthreads();

        if (tid < NH) {
            float dsum = 0.f;
            #pragma unroll
            for (int r = 0; r < 16; r++) dsum += e_s[r*12 + tid];
            denom[tid] += dsum;
        }

        {
            wmma::fragment<wmma::matrix_a, 16, 16, 16, __half, wmma::row_major> ef;
            wmma::load_matrix_sync(ef, e_hr, ELDH);
            #pragma unroll
            for (int ct = 0; ct < 4; ct++) {
                wmma::fragment<wmma::matrix_b, 16, 16, 16, __half, wmma::row_major> vb;
                wmma::load_matrix_sync(vb, cur + w*64 + ct*16, TLDH);
                wmma::mma_sync(av[ct], ef, vb, av[ct]);
            }
        }
    }

    __syncthreads();
    float* stage = (float*)smh;
    #pragma unroll
    for (int ct = 0; ct < 4; ct++)
        wmma::store_matrix_sync(stage + w*64 + ct*16, av[ct], 772, wmma::mem_row_major);
    __syncthreads();

    float4 d0 = *(const float4*)(denom);
    float4 d1 = *(const float4*)(denom + 4);
    float4 d2 = *(const float4*)(denom + 8);
    float inv[NH] = {1.f/d0.x, 1.f/d0.y, 1.f/d0.z, 1.f/d0.w,
                     1.f/d1.x, 1.f/d1.y, 1.f/d1.z, 1.f/d1.w,
                     1.f/d2.x, 1.f/d2.y, 1.f/d2.z, 1.f/d2.w};
    #pragma unroll
    for (int hh = 0; hh < NH; hh++) {
        float a = stage[hh*772 + tid*2]     * inv[hh];
        float c = stage[hh*772 + tid*2 + 1] * inv[hh];
        *(__half2*)(g_avnh + (size_t)bn*(NH*Dm) + hh*768 + tid*2) = __floats2half2_rn(a, c);
    }
}

// ---------------- host ----------------
extern "C" void kernel_launch(void* const* d_in, const int* in_sizes, int n_in,
                              void* d_out, int out_size)
{
    const float* x     = (const float*)d_in[0];
    const float* w_in  = (const float*)d_in[1];
    const float* b_in  = (const float*)d_in[2];
    const float* w_out = (const float*)d_in[3];
    const float* b_out = (const float*)d_in[4];
    const float* w_fc1 = (const float*)d_in[5];
    const float* b_fc1 = (const float*)d_in[6];
    const float* w_fc2 = (const float*)d_in[7];
    const float* b_fc2 = (const float*)d_in[8];
    float* y = (float*)d_out;

    __half *qh, *qph, *qkwh, *avnh, *ctxh, *o1h, *h1h, *wh;
    float *part;
    cudaGetSymbolAddress((void**)&qh,   g_qh);
    cudaGetSymbolAddress((void**)&qph,  g_qph);
    cudaGetSymbolAddress((void**)&qkwh, g_qkwh);
    cudaGetSymbolAddress((void**)&avnh, g_avnh);
    cudaGetSymbolAddress((void**)&ctxh, g_ctxh);
    cudaGetSymbolAddress((void**)&o1h,  g_o1h);
    cudaGetSymbolAddress((void**)&h1h,  g_h1h);
    cudaGetSymbolAddress((void**)&wh,   g_wh);
    cudaGetSymbolAddress((void**)&part, g_part);

    const int GSMEM = 2*18432*2;   // gemm128 dynamic smem bytes (73728)
    cudaFuncSetAttribute(gemm128, cudaFuncAttributeMaxDynamicSharedMemorySize, GSMEM);

    // 0. fused weight conversion
    f2h_all<<<(W_TOTAL/4 + 255)/256, 256>>>(w_in, w_out, w_fc1, w_fc2, wh);

    // 1. token means + x->fp16
    mean_kernel<<<Bb*Dm*Tt, 224>>>(x);

    // 2. qp = (q @ wq^T + bq) * 0.125   (128-tile, split-K 4)
    gemm128<<<dim3(6,7,4), 256, GSMEM>>>(qh, wh + W_IN_OFF, part, BN, Dm, Dm, Dm, Dm, 4);
    epi_kernel<<<(BN*Dm/4 + 255)/256, 256>>>(part, b_in, nullptr, qph, BN*Dm, Dm, 4, 0.125f, 0);

    // 3. qkw[.,h,:] = qp_h @ wk_h  (batched heads, K=64)
    gemm_hc<false><<<dim3(12,13,NH), 256>>>(qph, wh + W_IN_OFF + Dm*Dm, nullptr, nullptr, qkwh,
        BN, Dm, HD, Dm, Dm, NH*Dm, HD, HD*Dm, Dm, 0, 1.f, 0);

    // 4. fused attention
    {
        static const size_t smem = 110080;
        cudaFuncSetAttribute(attn7, cudaFuncAttributeMaxDynamicSharedMemorySize, (int)smem);
        attn7<<<BN, 384, smem>>>();
    }

    // 5. ctx_h = avn_h @ wv_h^T + bv_h  (batched heads)
    gemm_hc<true><<<dim3(1,13,NH), 256>>>(avnh, wh + W_IN_OFF + 2*Dm*Dm, b_in + 2*Dm, nullptr, ctxh,
        BN, HD, Dm, NH*Dm, Dm, Dm, Dm, HD*Dm, HD, HD, 1.f, 0);

    // 6. o1 = ctx @ w_out^T + b_out   (128-tile, split-K 4)
    gemm128<<<dim3(6,7,4), 256, GSMEM>>>(ctxh, wh + W_OUT_OFF, part, BN, Dm, Dm, Dm, Dm, 4);
    epi_kernel<<<(BN*Dm/4 + 255)/256, 256>>>(part, b_out, nullptr, o1h, BN*Dm, Dm, 4, 1.f, 0);

    // 7. h1 = silu(o1 @ w_fc1^T + b_fc1)   (128-tile, no split)
    gemm128<<<dim3(24,7,1), 256, GSMEM>>>(o1h, wh + W_FC1_OFF, part, BN, FFD, Dm, Dm, Dm, 1);
    epi_kernel<<<(BN*FFD/4 + 255)/256, 256>>>(part, b_fc1, nullptr, h1h, BN*FFD, FFD, 1, 1.f, 1);

    // 8. y = h1 @ w_fc2^T + b_fc2   (128-tile, split-K 4, fp32 out)
    gemm128<<<dim3(6,7,4), 256, GSMEM>>>(h1h, wh + W_FC2_OFF, part, BN, Dm, FFD, FFD, FFD, 4);
    epi_kernel<<<(BN*Dm/4 + 255)/256, 256>>>(part, b_fc2, y, nullptr, BN*Dm, Dm, 4, 1.f, 0);
}

// round 12
// speedup vs baseline: 9.4083x; 1.0500x over previous
#include <cuda_runtime.h>
#include <cuda_fp16.h>
#include <math.h>
#include <stdint.h>
#include <mma.h>

using namespace nvcuda;

#define Bb   4
#define Dm   768
#define Tt   14
#define Np   196
#define NH   12
#define HD   64
#define FFD  3072
#define BN   (Bb*Np)       // 784
#define HW   224
#define CHW  (HW*HW)       // 50176
#define MP   896           // padded M for 128-tiles

#define TLDH 776           // padded fp16 tile stride (conflict-free, 16B-aligned)
#define DLD  20
#define ELDH 24

// ---------------- scratch ----------------
__device__ __half g_xh [(size_t)Bb*Dm*CHW];
__device__ __half g_qh [BN*Dm];
__device__ __half g_qph[BN*Dm];
__device__ __half g_qkwh[BN*NH*Dm];
__device__ __half g_avnh[BN*NH*Dm];
__device__ __half g_ctxh[BN*Dm];
__device__ __half g_o1h[BN*Dm];
__device__ __half g_h1h[BN*FFD];
__device__ float  g_part[(size_t)4*MP*Dm];      // split-K partials (KS<=4, N=768)
#define W_IN_OFF   0
#define W_OUT_OFF  (3*Dm*Dm)
#define W_FC1_OFF  (W_OUT_OFF + Dm*Dm)
#define W_FC2_OFF  (W_FC1_OFF + FFD*Dm)
#define W_TOTAL    (W_FC2_OFF + Dm*FFD)
__device__ __half g_wh[W_TOTAL];

__device__ __forceinline__ void cp_async16(uint32_t dst, const void* src) {
    asm volatile("cp.async.cg.shared.global [%0], [%1], 16;" :: "r"(dst), "l"(src));
}

// ---------------- fused fp32->fp16 weight conversion ----------------
__global__ void f2h_all(const float* __restrict__ s0, const float* __restrict__ s1,
                        const float* __restrict__ s2, const float* __restrict__ s3,
                        __half* __restrict__ d) {
    int i = (blockIdx.x*256 + threadIdx.x)*4;
    if (i >= W_TOTAL) return;
    const float* s; int off;
    if      (i < W_OUT_OFF) { s = s0; off = 0; }
    else if (i < W_FC1_OFF) { s = s1; off = W_OUT_OFF; }
    else if (i < W_FC2_OFF) { s = s2; off = W_FC1_OFF; }
    else                    { s = s3; off = W_FC2_OFF; }
    float4 v = *(const float4*)(s + (i - off));
    ((__half2*)(d + i))[0] = __floats2half2_rn(v.x, v.y);
    ((__half2*)(d + i))[1] = __floats2half2_rn(v.z, v.w);
}

// ---------------- token means + x->fp16 ----------------
__global__ void mean_kernel(const float* __restrict__ x) {
    int bid = blockIdx.x;
    int t1 = bid % Tt;
    int dd = (bid / Tt) % Dm;
    int b  = bid / (Tt * Dm);
    size_t base = ((size_t)b*Dm + dd)*CHW + (size_t)t1*16*HW;
    const float* xp = x + base;
    __half* xo = g_xh + base;
    int j = threadIdx.x;
    float s = 0.f;
    #pragma unroll
    for (int r = 0; r < 16; r++) {
        float v = xp[(size_t)r*HW + j];
        xo[(size_t)r*HW + j] = __float2half(v);
        s += v;
    }
    __shared__ float cs[224];
    cs[j] = s;
    __syncthreads();
    if (j < Tt) {
        float t = 0.f;
        #pragma unroll
        for (int k = 0; k < 16; k++) t += cs[j*16 + k];
        g_qh[((size_t)b*Np + t1*Tt + j)*Dm + dd] = __float2half(t * (1.0f/256.0f));
    }
}

// ---------------- 128x128 fp16 GEMM (TRANSB) ----------------
// bias==null: raw fp32 partials to P[z][MP][N] (split-K via z).
// bias!=null (KS must be 1): fused bias(+silu) epilogue -> fp16 out16.
__global__ __launch_bounds__(256) void gemm128(
    const __half* __restrict__ A, const __half* __restrict__ Bm,
    float* __restrict__ P, int M, int N, int K, int lda, int ldb, int KS,
    const float* __restrict__ bias, __half* __restrict__ out16, int silu)
{
    extern __shared__ __half dbuf[];
    uint32_t sb = (uint32_t)__cvta_generic_to_shared(dbuf);

    int m0 = blockIdx.y * 128, n0 = blockIdx.x * 128;
    int z = blockIdx.z;
    int Ksub = K / KS;
    int kbase = z * Ksub;
    int tid = threadIdx.x;
    int warpId = tid >> 5;
    int wm = warpId >> 2;
    int wn = warpId & 3;

    wmma::fragment<wmma::accumulator, 16, 16, 16, float> acc[4][2];
    #pragma unroll
    for (int i = 0; i < 4; i++)
        #pragma unroll
        for (int j = 0; j < 2; j++) wmma::fill_fragment(acc[i][j], 0.f);

    const int nk = Ksub >> 6;

    auto issue = [&](int it, int s) {
        int k0 = kbase + it*64;
        uint32_t abase = sb + (uint32_t)(s * 18432 * 2);
        uint32_t bbase = abase + 9216*2;
        #pragma unroll
        for (int i = 0; i < 4; i++) {
            int idx = tid + 256*i;
            int row = idx >> 3, seg = idx & 7;
            int m = m0 + row; if (m >= M) m = M - 1;
            cp_async16(abase + (uint32_t)((row*72 + seg*8)*2),
                       A + (size_t)m*lda + k0 + seg*8);
        }
        #pragma unroll
        for (int i = 0; i < 4; i++) {
            int idx = tid + 256*i;
            int nn = idx >> 3, seg = idx & 7;
            int ng = n0 + nn; if (ng >= N) ng = N - 1;
            cp_async16(bbase + (uint32_t)((nn*72 + seg*8)*2),
                       Bm + (size_t)ng*ldb + k0 + seg*8);
        }
        asm volatile("cp.async.commit_group;");
    };

    issue(0, 0);

    for (int it = 0; it < nk; it++) {
        int s = it & 1;
        if (it + 1 < nk) {
            issue(it+1, s^1);
            asm volatile("cp.async.wait_group 1;");
        } else {
            asm volatile("cp.async.wait_group 0;");
        }
        __syncthreads();

        const __half* As = dbuf + s*18432;
        const __half* Bs = As + 9216;

        #pragma unroll
        for (int ks = 0; ks < 4; ks++) {
            wmma::fragment<wmma::matrix_b, 16, 16, 16, __half, wmma::col_major> bf[2];
            #pragma unroll
            for (int j = 0; j < 2; j++)
                wmma::load_matrix_sync(bf[j], Bs + (wn*32 + j*16)*72 + ks*16, 72);
            #pragma unroll
            for (int i = 0; i < 4; i++) {
                wmma::fragment<wmma::matrix_a, 16, 16, 16, __half, wmma::row_major> af;
                wmma::load_matrix_sync(af, As + (wm*64 + i*16)*72 + ks*16, 72);
                #pragma unroll
                for (int j = 0; j < 2; j++)
                    wmma::mma_sync(acc[i][j], af, bf[j], acc[i][j]);
            }
        }
        __syncthreads();
    }

    if (!bias) {
        float* base = P + (size_t)z*MP*N;
        #pragma unroll
        for (int i = 0; i < 4; i++)
            #pragma unroll
            for (int j = 0; j < 2; j++)
                wmma::store_matrix_sync(base + (size_t)(m0 + wm*64 + i*16)*N + n0 + wn*32 + j*16,
                                        acc[i][j], N, wmma::mem_row_major);
    } else {
        // fused epilogue: stage fp32 in smem, bias + (silu) -> fp16
        float* Cs = (float*)dbuf;          // [128][132] = 67584B <= 73728B
        #pragma unroll
        for (int i = 0; i < 4; i++)
            #pragma unroll
            for (int j = 0; j < 2; j++)
                wmma::store_matrix_sync(Cs + (wm*64 + i*16)*132 + wn*32 + j*16,
                                        acc[i][j], 132, wmma::mem_row_major);
        __syncthreads();
        #pragma unroll
        for (int i = 0; i < 16; i++) {
            int e = tid + 256*i;           // 0..4095 -> 128 rows x 32 segs
            int row = e >> 5, seg = e & 31;
            int m = m0 + row, nb = n0 + seg*4;
            if (m >= M || nb >= N) continue;
            float4 v = *(const float4*)(Cs + row*132 + seg*4);
            float4 bv = *(const float4*)(bias + nb);
            v.x += bv.x; v.y += bv.y; v.z += bv.z; v.w += bv.w;
            if (silu) {
                v.x = v.x/(1.f+__expf(-v.x)); v.y = v.y/(1.f+__expf(-v.y));
                v.z = v.z/(1.f+__expf(-v.z)); v.w = v.w/(1.f+__expf(-v.w));
            }
            __half2* dst = (__half2*)(out16 + (size_t)m*N + nb);
            dst[0] = __floats2half2_rn(v.x, v.y);
            dst[1] = __floats2half2_rn(v.z, v.w);
        }
    }
}

// ---------------- split-K epilogue ----------------
__global__ void epi_kernel(const float* __restrict__ P, const float* __restrict__ bias,
                           float* __restrict__ out32, __half* __restrict__ out16,
                           int MN, int N, int KS, float gamma, int silu)
{
    int i = (blockIdx.x*256 + threadIdx.x)*4;
    if (i >= MN) return;
    int c = i % N;
    float4 s = *(const float4*)(P + i);
    for (int ks = 1; ks < KS; ks++) {
        float4 p = *(const float4*)(P + (size_t)ks*MP*N + i);
        s.x += p.x; s.y += p.y; s.z += p.z; s.w += p.w;
    }
    float4 bv = *(const float4*)(bias + c);
    s.x = (s.x + bv.x)*gamma; s.y = (s.y + bv.y)*gamma;
    s.z = (s.z + bv.z)*gamma; s.w = (s.w + bv.w)*gamma;
    if (silu) {
        s.x = s.x/(1.f+__expf(-s.x)); s.y = s.y/(1.f+__expf(-s.y));
        s.z = s.z/(1.f+__expf(-s.z)); s.w = s.w/(1.f+__expf(-s.w));
    }
    if (out32) *(float4*)(out32 + i) = s;
    if (out16) {
        ((__half2*)(out16 + i))[0] = __floats2half2_rn(s.x, s.y);
        ((__half2*)(out16 + i))[1] = __floats2half2_rn(s.z, s.w);
    }
}

// ---------------- 64x64 fp16 GEMM (qkw / ctx, batched heads) ----------------
template<bool TRANSB>
__global__ __launch_bounds__(256) void gemm_hc(
    const __half* __restrict__ A, const __half* __restrict__ Bm,
    const float* __restrict__ bias, float* __restrict__ C32, __half* __restrict__ C16,
    int M, int N, int K, int lda, int ldb, int ldc,
    int sAh, int sBh, int sCh, int sBiasH,
    float gamma, int silu)
{
    int h = blockIdx.z;
    A  += (size_t)h * sAh;
    Bm += (size_t)h * sBh;
    const float* biasp = bias ? bias + (size_t)h * sBiasH : nullptr;

    __shared__ __half hbuf[2*2*64*72];
    uint32_t sb = (uint32_t)__cvta_generic_to_shared(hbuf);

    int m0 = blockIdx.y * 64, n0 = blockIdx.x * 64;
    int tid = threadIdx.x;
    int warpId = tid >> 5;
    int wm = warpId >> 1;
    int wn = warpId & 1;

    wmma::fragment<wmma::accumulator, 16, 16, 16, float> cf[2];
    wmma::fill_fragment(cf[0], 0.f);
    wmma::fill_fragment(cf[1], 0.f);

    const int nk = K >> 6;

    auto issue = [&](int it, int s) {
        int k0 = it * 64;
        uint32_t abase = sb + (uint32_t)(s * 9216 * 2);
        uint32_t bbase = abase + 4608*2;
        #pragma unroll
        for (int i = 0; i < 2; i++) {
            int idx = tid + 256*i;
            int row = idx >> 3, seg = idx & 7;
            int m = m0 + row; if (m >= M) m = M - 1;
            cp_async16(abase + (uint32_t)((row*72 + seg*8)*2),
                       A + (size_t)m*lda + k0 + seg*8);
        }
        if (TRANSB) {
            #pragma unroll
            for (int i = 0; i < 2; i++) {
                int idx = tid + 256*i;
                int nn = idx >> 3, seg = idx & 7;
                int ng = n0 + nn; if (ng >= N) ng = N - 1;
                cp_async16(bbase + (uint32_t)((nn*72 + seg*8)*2),
                           Bm + (size_t)ng*ldb + k0 + seg*8);
            }
        } else {
            #pragma unroll
            for (int i = 0; i < 2; i++) {
                int idx = tid + 256*i;
                int kk = idx >> 3, seg = idx & 7;
                int nb = n0 + seg*8; if (nb >= N) nb = 0;
                cp_async16(bbase + (uint32_t)((kk*72 + seg*8)*2),
                           Bm + (size_t)(k0+kk)*ldb + nb);
            }
        }
        asm volatile("cp.async.commit_group;");
    };

    issue(0, 0);

    for (int it = 0; it < nk; it++) {
        int s = it & 1;
        if (it + 1 < nk) {
            issue(it+1, s^1);
            asm volatile("cp.async.wait_group 1;");
        } else {
            asm volatile("cp.async.wait_group 0;");
        }
        __syncthreads();

        const __half* As = hbuf + s*9216;
        const __half* Bs = As + 4608;

        #pragma unroll
        for (int ks = 0; ks < 4; ks++) {
            wmma::fragment<wmma::matrix_a, 16, 16, 16, __half, wmma::row_major> af;
            wmma::load_matrix_sync(af, As + (wm*16)*72 + ks*16, 72);
            #pragma unroll
            for (int j = 0; j < 2; j++) {
                if (TRANSB) {
                    wmma::fragment<wmma::matrix_b, 16, 16, 16, __half, wmma::col_major> bf;
                    wmma::load_matrix_sync(bf, Bs + (wn*32 + j*16)*72 + ks*16, 72);
                    wmma::mma_sync(cf[j], af, bf, cf[j]);
                } else {
                    wmma::fragment<wmma::matrix_b, 16, 16, 16, __half, wmma::row_major> bf;
                    wmma::load_matrix_sync(bf, Bs + (ks*16)*72 + wn*32 + j*16, 72);
                    wmma::mma_sync(cf[j], af, bf, cf[j]);
                }
            }
        }
        __syncthreads();
    }

    float (*Cs)[68] = (float(*)[68])hbuf;
    wmma::store_matrix_sync(&Cs[wm*16][wn*32],      cf[0], 68, wmma::mem_row_major);
    wmma::store_matrix_sync(&Cs[wm*16][wn*32 + 16], cf[1], 68, wmma::mem_row_major);
    __syncthreads();

    #pragma unroll
    for (int i = 0; i < 4; i++) {
        int e = tid + 256*i;
        int row = e >> 4, seg = e & 15;
        int m = m0 + row, nbase = n0 + seg*4;
        if (m >= M || nbase >= N) continue;
        float4 v = *(const float4*)&Cs[row][seg*4];
        if (biasp) {
            float4 bv = *(const float4*)(biasp + nbase);
            v.x += bv.x; v.y += bv.y; v.z += bv.z; v.w += bv.w;
        }
        v.x *= gamma; v.y *= gamma; v.z *= gamma; v.w *= gamma;
        if (silu) {
            v.x = v.x/(1.f+__expf(-v.x)); v.y = v.y/(1.f+__expf(-v.y));
            v.z = v.z/(1.f+__expf(-v.z)); v.w = v.w/(1.f+__expf(-v.w));
        }
        if (C32) *(float4*)(C32 + (size_t)m*ldc + nbase + (size_t)h*sCh) = v;
        if (C16) {
            __half2* dst = (__half2*)(C16 + (size_t)m*ldc + nbase + (size_t)h*sCh);
            dst[0] = __floats2half2_rn(v.x, v.y);
            dst[1] = __floats2half2_rn(v.z, v.w);
        }
    }
}

// ---------------- fused attention v7b: fp16 tiles+MMA, triple buffer, 2 CTAs/SM ----------------
// smem bytes: qkw 18624 | tiles 3x24832 | Dpart 15360 | e_s 768 | e_hr 768 | denom 64 = 110080
// 2 CTAs x 110080 = 220160 B fits the 228KB SM budget -> occupancy doubles vs R9.
__global__ __launch_bounds__(384, 2) void attn7() {
    extern __shared__ __half smh[];
    __half* qkw_s = smh;
    __half* tiles = smh + 12*TLDH;
    float*  Dpart = (float*)(smh + 12*TLDH + 3*16*TLDH);
    float*  e_s   = Dpart + 12*16*DLD;
    __half* e_hr  = (__half*)(e_s + 192);
    float*  denom = (float*)(e_hr + 16*ELDH);

    int bn = blockIdx.x;
    int b = bn / Np, n = bn % Np;
    int t1 = n / Tt, t2 = n % Tt;
    const __half* xph = g_xh + (size_t)b*Dm*CHW + (size_t)(t1*16)*HW + t2*16;

    int tid = threadIdx.x, w = tid >> 5;

    auto issue_chunk = [&](int lc) {
        uint32_t stp = (uint32_t)__cvta_generic_to_shared(tiles + (lc % 3)*16*TLDH);
        #pragma unroll
        for (int j = 0; j < 4; j++) {
            int ch = tid + 384*j;
            int idx8 = ch*8;
            int r = idx8 / 768, cc = idx8 - r*768;
            int flat = lc*12288 + idx8;
            int dd = flat >> 8, g1 = (flat >> 4) & 15, g2 = flat & 15;
            cp_async16(stp + (uint32_t)((r*TLDH + cc)*2), xph + (size_t)dd*CHW + g1*HW + g2);
        }
        asm volatile("cp.async.commit_group;");
    };

    issue_chunk(0);
    issue_chunk(1);

    {
        const __half* src = g_qkwh + (size_t)bn*(NH*Dm);
        #pragma unroll
        for (int i = 0; i < 3; i++) {
            int idx = tid + 384*i;
            int hh = idx / 96, rem = idx - hh*96;
            *(float4*)(qkw_s + hh*TLDH + rem*8) = *(const float4*)(src + idx*8);
        }
    }
    if (tid < 16*ELDH) e_hr[tid] = __float2half(0.f);
    if (tid < NH) denom[tid] = 0.f;

    wmma::fragment<wmma::accumulator, 16, 16, 16, float> av[4];
    #pragma unroll
    for (int ct = 0; ct < 4; ct++) wmma::fill_fragment(av[ct], 0.f);

    for (int lc = 0; lc < 16; lc++) {
        const __half* cur = tiles + (lc % 3)*16*TLDH;
        if (lc < 15) asm volatile("cp.async.wait_group 1;");
        else         asm volatile("cp.async.wait_group 0;");
        __syncthreads();
        if (lc + 2 <= 15) issue_chunk(lc + 2);

        {
            wmma::fragment<wmma::accumulator, 16, 16, 16, float> d;
            wmma::fill_fragment(d, 0.f);
            #pragma unroll
            for (int ks = 0; ks < 4; ks++) {
                int k = w*64 + ks*16;
                wmma::fragment<wmma::matrix_a, 16, 16, 16, __half, wmma::row_major> af;
                wmma::load_matrix_sync(af, cur + k, TLDH);
                wmma::fragment<wmma::matrix_b, 16, 16, 16, __half, wmma::col_major> bf;
                wmma::load_matrix_sync(bf, qkw_s + k, TLDH);
                wmma::mma_sync(d, af, bf, d);
            }
            wmma::store_matrix_sync(Dpart + w*16*DLD, d, DLD, wmma::mem_row_major);
        }
        __syncthreads();

        if (tid < 192) {
            int r = tid / 12, hh = tid - r*12;
            float s = 0.f;
            #pragma unroll
            for (int w2 = 0; w2 < 12; w2++) s += Dpart[w2*16*DLD + r*DLD + hh];
            float e = __expf(s);
            e_s[r*12 + hh] = e;
            e_hr[hh*ELDH + r] = __float2half(e);
        }
        __syncthreads();

        if (tid < NH) {
            float dsum = 0.f;
            #pragma unroll
            for (int r = 0; r < 16; r++) dsum += e_s[r*12 + tid];
            denom[tid] += dsum;
        }

        {
            wmma::fragment<wmma::matrix_a, 16, 16, 16, __half, wmma::row_major> ef;
            wmma::load_matrix_sync(ef, e_hr, ELDH);
            #pragma unroll
            for (int ct = 0; ct < 4; ct++) {
                wmma::fragment<wmma::matrix_b, 16, 16, 16, __half, wmma::row_major> vb;
                wmma::load_matrix_sync(vb, cur + w*64 + ct*16, TLDH);
                wmma::mma_sync(av[ct], ef, vb, av[ct]);
            }
        }
    }

    __syncthreads();
    float* stage = (float*)smh;                // [16][772]
    #pragma unroll
    for (int ct = 0; ct < 4; ct++)
        wmma::store_matrix_sync(stage + w*64 + ct*16, av[ct], 772, wmma::mem_row_major);
    __syncthreads();

    float4 d0 = *(const float4*)(denom);
    float4 d1 = *(const float4*)(denom + 4);
    float4 d2 = *(const float4*)(denom + 8);
    float inv[NH] = {1.f/d0.x, 1.f/d0.y, 1.f/d0.z, 1.f/d0.w,
                     1.f/d1.x, 1.f/d1.y, 1.f/d1.z, 1.f/d1.w,
                     1.f/d2.x, 1.f/d2.y, 1.f/d2.z, 1.f/d2.w};
    #pragma unroll
    for (int hh = 0; hh < NH; hh++) {
        float a = stage[hh*772 + tid*2]     * inv[hh];
        float c = stage[hh*772 + tid*2 + 1] * inv[hh];
        *(__half2*)(g_avnh + (size_t)bn*(NH*Dm) + hh*768 + tid*2) = __floats2half2_rn(a, c);
    }
}

// ---------------- host ----------------
extern "C" void kernel_launch(void* const* d_in, const int* in_sizes, int n_in,
                              void* d_out, int out_size)
{
    const float* x     = (const float*)d_in[0];
    const float* w_in  = (const float*)d_in[1];
    const float* b_in  = (const float*)d_in[2];
    const float* w_out = (const float*)d_in[3];
    const float* b_out = (const float*)d_in[4];
    const float* w_fc1 = (const float*)d_in[5];
    const float* b_fc1 = (const float*)d_in[6];
    const float* w_fc2 = (const float*)d_in[7];
    const float* b_fc2 = (const float*)d_in[8];
    float* y = (float*)d_out;

    __half *qh, *qph, *qkwh, *avnh, *ctxh, *o1h, *h1h, *wh;
    float *part;
    cudaGetSymbolAddress((void**)&qh,   g_qh);
    cudaGetSymbolAddress((void**)&qph,  g_qph);
    cudaGetSymbolAddress((void**)&qkwh, g_qkwh);
    cudaGetSymbolAddress((void**)&avnh, g_avnh);
    cudaGetSymbolAddress((void**)&ctxh, g_ctxh);
    cudaGetSymbolAddress((void**)&o1h,  g_o1h);
    cudaGetSymbolAddress((void**)&h1h,  g_h1h);
    cudaGetSymbolAddress((void**)&wh,   g_wh);
    cudaGetSymbolAddress((void**)&part, g_part);

    const int GSMEM = 2*18432*2;
    cudaFuncSetAttribute(gemm128, cudaFuncAttributeMaxDynamicSharedMemorySize, GSMEM);

    // 0. weight conversion
    f2h_all<<<(W_TOTAL/4 + 255)/256, 256>>>(w_in, w_out, w_fc1, w_fc2, wh);

    // 1. token means + x->fp16
    mean_kernel<<<Bb*Dm*Tt, 224>>>(x);

    // 2. qp = (q @ wq^T + bq)*0.125  (split-K 4)
    gemm128<<<dim3(6,7,4), 256, GSMEM>>>(qh, wh + W_IN_OFF, part, BN, Dm, Dm, Dm, Dm, 4,
                                         nullptr, nullptr, 0);
    epi_kernel<<<(BN*Dm/4 + 255)/256, 256>>>(part, b_in, nullptr, qph, BN*Dm, Dm, 4, 0.125f, 0);

    // 3. qkw  (batched heads, K=64)
    gemm_hc<false><<<dim3(12,13,NH), 256>>>(qph, wh + W_IN_OFF + Dm*Dm, nullptr, nullptr, qkwh,
        BN, Dm, HD, Dm, Dm, NH*Dm, HD, HD*Dm, Dm, 0, 1.f, 0);

    // 4. fused attention (launch index 5 -> gets profiled by -s 5 -c 1)
    {
        static const size_t smem = 110080;
        cudaFuncSetAttribute(attn7, cudaFuncAttributeMaxDynamicSharedMemorySize, (int)smem);
        attn7<<<BN, 384, smem>>>();
    }

    // 5. ctx  (batched heads)
    gemm_hc<true><<<dim3(1,13,NH), 256>>>(avnh, wh + W_IN_OFF + 2*Dm*Dm, b_in + 2*Dm, nullptr, ctxh,
        BN, HD, Dm, NH*Dm, Dm, Dm, Dm, HD*Dm, HD, HD, 1.f, 0);

    // 6. o1 = ctx @ w_out^T + b_out  (split-K 4)
    gemm128<<<dim3(6,7,4), 256, GSMEM>>>(ctxh, wh + W_OUT_OFF, part, BN, Dm, Dm, Dm, Dm, 4,
                                         nullptr, nullptr, 0);
    epi_kernel<<<(BN*Dm/4 + 255)/256, 256>>>(part, b_out, nullptr, o1h, BN*Dm, Dm, 4, 1.f, 0);

    // 7. h1 = silu(o1 @ w_fc1^T + b_fc1)  — fused epilogue
    gemm128<<<dim3(24,7,1), 256, GSMEM>>>(o1h, wh + W_FC1_OFF, part, BN, FFD, Dm, Dm, Dm, 1,
                                          b_fc1, h1h, 1);

    // 8. y = h1 @ w_fc2^T + b_fc2  (split-K 4, fp32 out)
    gemm128<<<dim3(6,7,4), 256, GSMEM>>>(h1h, wh + W_FC2_OFF, part, BN, Dm, FFD, FFD, FFD, 4,
                                         nullptr, nullptr, 0);
    epi_kernel<<<(BN*Dm/4 + 255)/256, 256>>>(part, b_fc2, y, nullptr, BN*Dm, Dm, 4, 1.f, 0);
}

// round 13
// speedup vs baseline: 9.6747x; 1.0283x over previous
#include <cuda_runtime.h>
#include <cuda_fp16.h>
#include <math.h>
#include <stdint.h>
#include <mma.h>

using namespace nvcuda;

#define Bb   4
#define Dm   768
#define Tt   14
#define Np   196
#define NH   12
#define HD   64
#define FFD  3072
#define BN   (Bb*Np)       // 784
#define HW   224
#define CHW  (HW*HW)       // 50176
#define MP   896           // padded M for 128-tiles

#define TLDH 776           // padded fp16 tile stride (conflict-free, 16B-aligned)
#define DLD  20
#define ELDH 24

// ---------------- scratch ----------------
__device__ __half g_xh [(size_t)Bb*Dm*CHW];
__device__ __half g_qh [BN*Dm];
__device__ __half g_qph[BN*Dm];
__device__ __half g_qkwh[BN*NH*Dm];
__device__ __half g_avnh[BN*NH*Dm];
__device__ __half g_ctxh[BN*Dm];
__device__ __half g_o1h[BN*Dm];
__device__ __half g_h1h[BN*FFD];
__device__ float  g_part[(size_t)4*MP*Dm];      // split-K partials (fc2 only)
#define W_IN_OFF   0
#define W_OUT_OFF  (3*Dm*Dm)
#define W_FC1_OFF  (W_OUT_OFF + Dm*Dm)
#define W_FC2_OFF  (W_FC1_OFF + FFD*Dm)
#define W_TOTAL    (W_FC2_OFF + Dm*FFD)
__device__ __half g_wh[W_TOTAL];

__device__ __forceinline__ void cp_async16(uint32_t dst, const void* src) {
    asm volatile("cp.async.cg.shared.global [%0], [%1], 16;" :: "r"(dst), "l"(src));
}

// ---------------- fused fp32->fp16 weight conversion ----------------
__global__ void f2h_all(const float* __restrict__ s0, const float* __restrict__ s1,
                        const float* __restrict__ s2, const float* __restrict__ s3,
                        __half* __restrict__ d) {
    int i = (blockIdx.x*256 + threadIdx.x)*4;
    if (i >= W_TOTAL) return;
    const float* s; int off;
    if      (i < W_OUT_OFF) { s = s0; off = 0; }
    else if (i < W_FC1_OFF) { s = s1; off = W_OUT_OFF; }
    else if (i < W_FC2_OFF) { s = s2; off = W_FC1_OFF; }
    else                    { s = s3; off = W_FC2_OFF; }
    float4 v = *(const float4*)(s + (i - off));
    ((__half2*)(d + i))[0] = __floats2half2_rn(v.x, v.y);
    ((__half2*)(d + i))[1] = __floats2half2_rn(v.z, v.w);
}

// ---------------- token means + x->fp16, vectorized ----------------
// block = (b, dd, t1), 224 threads: thread t = (rowgroup rg = t/56, quad qi = t%56).
// 4 x LDG.128 + 4 x STG.64 per thread (was 16 x LDG.32 + 16 x STG.16).
__global__ void mean_kernel(const float* __restrict__ x) {
    int bid = blockIdx.x;
    int t1 = bid % Tt;
    int dd = (bid / Tt) % Dm;
    int b  = bid / (Tt * Dm);
    size_t base = ((size_t)b*Dm + dd)*CHW + (size_t)t1*16*HW;
    const float4* xp = (const float4*)(x + base);   // 56 float4 per row
    __half* xo = g_xh + base;

    int t  = threadIdx.x;      // 0..223
    int qi = t % 56;
    int rg = t / 56;           // 0..3

    float4 acc = make_float4(0.f, 0.f, 0.f, 0.f);
    #pragma unroll
    for (int k = 0; k < 4; k++) {
        int r = rg*4 + k;
        float4 v = xp[r*56 + qi];
        acc.x += v.x; acc.y += v.y; acc.z += v.z; acc.w += v.w;
        __half2 h0 = __floats2half2_rn(v.x, v.y);
        __half2 h1 = __floats2half2_rn(v.z, v.w);
        uint2 u;
        u.x = *(uint32_t*)&h0;
        u.y = *(uint32_t*)&h1;
        *(uint2*)(xo + (size_t)r*HW + qi*4) = u;
    }

    __shared__ float4 ps[224];
    __shared__ float qsum[56];
    ps[t] = acc;
    __syncthreads();
    if (t < 56) {
        float s = 0.f;
        #pragma unroll
        for (int r2 = 0; r2 < 4; r2++) {
            float4 v = ps[r2*56 + t];
            s += v.x + v.y + v.z + v.w;
        }
        qsum[t] = s;
    }
    __syncthreads();
    if (t < Tt) {
        float s = qsum[4*t] + qsum[4*t+1] + qsum[4*t+2] + qsum[4*t+3];
        g_qh[((size_t)b*Np + t1*Tt + t)*Dm + dd] = __float2half(s * (1.0f/256.0f));
    }
}

// ---------------- 128x128 fp16 GEMM (TRANSB) ----------------
// bias==null: raw fp32 partials to P[z][MP][N] (split-K via z).
// bias!=null (KS must be 1): fused bias(+silu) epilogue -> fp16 out16.
__global__ __launch_bounds__(256) void gemm128(
    const __half* __restrict__ A, const __half* __restrict__ Bm,
    float* __restrict__ P, int M, int N, int K, int lda, int ldb, int KS,
    const float* __restrict__ bias, __half* __restrict__ out16, int silu)
{
    extern __shared__ __half dbuf[];
    uint32_t sb = (uint32_t)__cvta_generic_to_shared(dbuf);

    int m0 = blockIdx.y * 128, n0 = blockIdx.x * 128;
    int z = blockIdx.z;
    int Ksub = K / KS;
    int kbase = z * Ksub;
    int tid = threadIdx.x;
    int warpId = tid >> 5;
    int wm = warpId >> 2;
    int wn = warpId & 3;

    wmma::fragment<wmma::accumulator, 16, 16, 16, float> acc[4][2];
    #pragma unroll
    for (int i = 0; i < 4; i++)
        #pragma unroll
        for (int j = 0; j < 2; j++) wmma::fill_fragment(acc[i][j], 0.f);

    const int nk = Ksub >> 6;

    auto issue = [&](int it, int s) {
        int k0 = kbase + it*64;
        uint32_t abase = sb + (uint32_t)(s * 18432 * 2);
        uint32_t bbase = abase + 9216*2;
        #pragma unroll
        for (int i = 0; i < 4; i++) {
            int idx = tid + 256*i;
            int row = idx >> 3, seg = idx & 7;
            int m = m0 + row; if (m >= M) m = M - 1;
            cp_async16(abase + (uint32_t)((row*72 + seg*8)*2),
                       A + (size_t)m*lda + k0 + seg*8);
        }
        #pragma unroll
        for (int i = 0; i < 4; i++) {
            int idx = tid + 256*i;
            int nn = idx >> 3, seg = idx & 7;
            int ng = n0 + nn; if (ng >= N) ng = N - 1;
            cp_async16(bbase + (uint32_t)((nn*72 + seg*8)*2),
                       Bm + (size_t)ng*ldb + k0 + seg*8);
        }
        asm volatile("cp.async.commit_group;");
    };

    issue(0, 0);

    for (int it = 0; it < nk; it++) {
        int s = it & 1;
        if (it + 1 < nk) {
            issue(it+1, s^1);
            asm volatile("cp.async.wait_group 1;");
        } else {
            asm volatile("cp.async.wait_group 0;");
        }
        __syncthreads();

        const __half* As = dbuf + s*18432;
        const __half* Bs = As + 9216;

        #pragma unroll
        for (int ks = 0; ks < 4; ks++) {
            wmma::fragment<wmma::matrix_b, 16, 16, 16, __half, wmma::col_major> bf[2];
            #pragma unroll
            for (int j = 0; j < 2; j++)
                wmma::load_matrix_sync(bf[j], Bs + (wn*32 + j*16)*72 + ks*16, 72);
            #pragma unroll
            for (int i = 0; i < 4; i++) {
                wmma::fragment<wmma::matrix_a, 16, 16, 16, __half, wmma::row_major> af;
                wmma::load_matrix_sync(af, As + (wm*64 + i*16)*72 + ks*16, 72);
                #pragma unroll
                for (int j = 0; j < 2; j++)
                    wmma::mma_sync(acc[i][j], af, bf[j], acc[i][j]);
            }
        }
        __syncthreads();
    }

    if (!bias) {
        float* base = P + (size_t)z*MP*N;
        #pragma unroll
        for (int i = 0; i < 4; i++)
            #pragma unroll
            for (int j = 0; j < 2; j++)
                wmma::store_matrix_sync(base + (size_t)(m0 + wm*64 + i*16)*N + n0 + wn*32 + j*16,
                                        acc[i][j], N, wmma::mem_row_major);
    } else {
        float* Cs = (float*)dbuf;          // [128][132]
        #pragma unroll
        for (int i = 0; i < 4; i++)
            #pragma unroll
            for (int j = 0; j < 2; j++)
                wmma::store_matrix_sync(Cs + (wm*64 + i*16)*132 + wn*32 + j*16,
                                        acc[i][j], 132, wmma::mem_row_major);
        __syncthreads();
        #pragma unroll
        for (int i = 0; i < 16; i++) {
            int e = tid + 256*i;
            int row = e >> 5, seg = e & 31;
            int m = m0 + row, nb = n0 + seg*4;
            if (m >= M || nb >= N) continue;
            float4 v = *(const float4*)(Cs + row*132 + seg*4);
            float4 bv = *(const float4*)(bias + nb);
            v.x += bv.x; v.y += bv.y; v.z += bv.z; v.w += bv.w;
            if (silu) {
                v.x = v.x/(1.f+__expf(-v.x)); v.y = v.y/(1.f+__expf(-v.y));
                v.z = v.z/(1.f+__expf(-v.z)); v.w = v.w/(1.f+__expf(-v.w));
            }
            __half2* dst = (__half2*)(out16 + (size_t)m*N + nb);
            dst[0] = __floats2half2_rn(v.x, v.y);
            dst[1] = __floats2half2_rn(v.z, v.w);
        }
    }
}

// ---------------- split-K epilogue (fc2 only) ----------------
__global__ void epi_kernel(const float* __restrict__ P, const float* __restrict__ bias,
                           float* __restrict__ out32, __half* __restrict__ out16,
                           int MN, int N, int KS, float gamma, int silu)
{
    int i = (blockIdx.x*256 + threadIdx.x)*4;
    if (i >= MN) return;
    int c = i % N;
    float4 s = *(const float4*)(P + i);
    for (int ks = 1; ks < KS; ks++) {
        float4 p = *(const float4*)(P + (size_t)ks*MP*N + i);
        s.x += p.x; s.y += p.y; s.z += p.z; s.w += p.w;
    }
    float4 bv = *(const float4*)(bias + c);
    s.x = (s.x + bv.x)*gamma; s.y = (s.y + bv.y)*gamma;
    s.z = (s.z + bv.z)*gamma; s.w = (s.w + bv.w)*gamma;
    if (silu) {
        s.x = s.x/(1.f+__expf(-s.x)); s.y = s.y/(1.f+__expf(-s.y));
        s.z = s.z/(1.f+__expf(-s.z)); s.w = s.w/(1.f+__expf(-s.w));
    }
    if (out32) *(float4*)(out32 + i) = s;
    if (out16) {
        ((__half2*)(out16 + i))[0] = __floats2half2_rn(s.x, s.y);
        ((__half2*)(out16 + i))[1] = __floats2half2_rn(s.z, s.w);
    }
}

// ---------------- 64x64 fp16 GEMM (qp / qkw / ctx / o1; fused epilogue) ----------------
template<bool TRANSB>
__global__ __launch_bounds__(256) void gemm_hc(
    const __half* __restrict__ A, const __half* __restrict__ Bm,
    const float* __restrict__ bias, float* __restrict__ C32, __half* __restrict__ C16,
    int M, int N, int K, int lda, int ldb, int ldc,
    int sAh, int sBh, int sCh, int sBiasH,
    float gamma, int silu)
{
    int h = blockIdx.z;
    A  += (size_t)h * sAh;
    Bm += (size_t)h * sBh;
    const float* biasp = bias ? bias + (size_t)h * sBiasH : nullptr;

    __shared__ __half hbuf[2*2*64*72];
    uint32_t sb = (uint32_t)__cvta_generic_to_shared(hbuf);

    int m0 = blockIdx.y * 64, n0 = blockIdx.x * 64;
    int tid = threadIdx.x;
    int warpId = tid >> 5;
    int wm = warpId >> 1;
    int wn = warpId & 1;

    wmma::fragment<wmma::accumulator, 16, 16, 16, float> cf[2];
    wmma::fill_fragment(cf[0], 0.f);
    wmma::fill_fragment(cf[1], 0.f);

    const int nk = K >> 6;

    auto issue = [&](int it, int s) {
        int k0 = it * 64;
        uint32_t abase = sb + (uint32_t)(s * 9216 * 2);
        uint32_t bbase = abase + 4608*2;
        #pragma unroll
        for (int i = 0; i < 2; i++) {
            int idx = tid + 256*i;
            int row = idx >> 3, seg = idx & 7;
            int m = m0 + row; if (m >= M) m = M - 1;
            cp_async16(abase + (uint32_t)((row*72 + seg*8)*2),
                       A + (size_t)m*lda + k0 + seg*8);
        }
        if (TRANSB) {
            #pragma unroll
            for (int i = 0; i < 2; i++) {
                int idx = tid + 256*i;
                int nn = idx >> 3, seg = idx & 7;
                int ng = n0 + nn; if (ng >= N) ng = N - 1;
                cp_async16(bbase + (uint32_t)((nn*72 + seg*8)*2),
                           Bm + (size_t)ng*ldb + k0 + seg*8);
            }
        } else {
            #pragma unroll
            for (int i = 0; i < 2; i++) {
                int idx = tid + 256*i;
                int kk = idx >> 3, seg = idx & 7;
                int nb = n0 + seg*8; if (nb >= N) nb = 0;
                cp_async16(bbase + (uint32_t)((kk*72 + seg*8)*2),
                           Bm + (size_t)(k0+kk)*ldb + nb);
            }
        }
        asm volatile("cp.async.commit_group;");
    };

    issue(0, 0);

    for (int it = 0; it < nk; it++) {
        int s = it & 1;
        if (it + 1 < nk) {
            issue(it+1, s^1);
            asm volatile("cp.async.wait_group 1;");
        } else {
            asm volatile("cp.async.wait_group 0;");
        }
        __syncthreads();

        const __half* As = hbuf + s*9216;
        const __half* Bs = As + 4608;

        #pragma unroll
        for (int ks = 0; ks < 4; ks++) {
            wmma::fragment<wmma::matrix_a, 16, 16, 16, __half, wmma::row_major> af;
            wmma::load_matrix_sync(af, As + (wm*16)*72 + ks*16, 72);
            #pragma unroll
            for (int j = 0; j < 2; j++) {
                if (TRANSB) {
                    wmma::fragment<wmma::matrix_b, 16, 16, 16, __half, wmma::col_major> bf;
                    wmma::load_matrix_sync(bf, Bs + (wn*32 + j*16)*72 + ks*16, 72);
                    wmma::mma_sync(cf[j], af, bf, cf[j]);
                } else {
                    wmma::fragment<wmma::matrix_b, 16, 16, 16, __half, wmma::row_major> bf;
                    wmma::load_matrix_sync(bf, Bs + (ks*16)*72 + wn*32 + j*16, 72);
                    wmma::mma_sync(cf[j], af, bf, cf[j]);
                }
            }
        }
        __syncthreads();
    }

    float (*Cs)[68] = (float(*)[68])hbuf;
    wmma::store_matrix_sync(&Cs[wm*16][wn*32],      cf[0], 68, wmma::mem_row_major);
    wmma::store_matrix_sync(&Cs[wm*16][wn*32 + 16], cf[1], 68, wmma::mem_row_major);
    __syncthreads();

    #pragma unroll
    for (int i = 0; i < 4; i++) {
        int e = tid + 256*i;
        int row = e >> 4, seg = e & 15;
        int m = m0 + row, nbase = n0 + seg*4;
        if (m >= M || nbase >= N) continue;
        float4 v = *(const float4*)&Cs[row][seg*4];
        if (biasp) {
            float4 bv = *(const float4*)(biasp + nbase);
            v.x += bv.x; v.y += bv.y; v.z += bv.z; v.w += bv.w;
        }
        v.x *= gamma; v.y *= gamma; v.z *= gamma; v.w *= gamma;
        if (silu) {
            v.x = v.x/(1.f+__expf(-v.x)); v.y = v.y/(1.f+__expf(-v.y));
            v.z = v.z/(1.f+__expf(-v.z)); v.w = v.w/(1.f+__expf(-v.w));
        }
        if (C32) *(float4*)(C32 + (size_t)m*ldc + nbase + (size_t)h*sCh) = v;
        if (C16) {
            __half2* dst = (__half2*)(C16 + (size_t)m*ldc + nbase + (size_t)h*sCh);
            dst[0] = __floats2half2_rn(v.x, v.y);
            dst[1] = __floats2half2_rn(v.z, v.w);
        }
    }
}

// ---------------- fused attention v7b: fp16 tiles+MMA, triple buffer, 2 CTAs/SM ----------------
__global__ __launch_bounds__(384, 2) void attn7() {
    extern __shared__ __half smh[];
    __half* qkw_s = smh;
    __half* tiles = smh + 12*TLDH;
    float*  Dpart = (float*)(smh + 12*TLDH + 3*16*TLDH);
    float*  e_s   = Dpart + 12*16*DLD;
    __half* e_hr  = (__half*)(e_s + 192);
    float*  denom = (float*)(e_hr + 16*ELDH);

    int bn = blockIdx.x;
    int b = bn / Np, n = bn % Np;
    int t1 = n / Tt, t2 = n % Tt;
    const __half* xph = g_xh + (size_t)b*Dm*CHW + (size_t)(t1*16)*HW + t2*16;

    int tid = threadIdx.x, w = tid >> 5;

    auto issue_chunk = [&](int lc) {
        uint32_t stp = (uint32_t)__cvta_generic_to_shared(tiles + (lc % 3)*16*TLDH);
        #pragma unroll
        for (int j = 0; j < 4; j++) {
            int ch = tid + 384*j;
            int idx8 = ch*8;
            int r = idx8 / 768, cc = idx8 - r*768;
            int flat = lc*12288 + idx8;
            int dd = flat >> 8, g1 = (flat >> 4) & 15, g2 = flat & 15;
            cp_async16(stp + (uint32_t)((r*TLDH + cc)*2), xph + (size_t)dd*CHW + g1*HW + g2);
        }
        asm volatile("cp.async.commit_group;");
    };

    issue_chunk(0);
    issue_chunk(1);

    {
        const __half* src = g_qkwh + (size_t)bn*(NH*Dm);
        #pragma unroll
        for (int i = 0; i < 3; i++) {
            int idx = tid + 384*i;
            int hh = idx / 96, rem = idx - hh*96;
            *(float4*)(qkw_s + hh*TLDH + rem*8) = *(const float4*)(src + idx*8);
        }
    }
    if (tid < 16*ELDH) e_hr[tid] = __float2half(0.f);
    if (tid < NH) denom[tid] = 0.f;

    wmma::fragment<wmma::accumulator, 16, 16, 16, float> av[4];
    #pragma unroll
    for (int ct = 0; ct < 4; ct++) wmma::fill_fragment(av[ct], 0.f);

    for (int lc = 0; lc < 16; lc++) {
        const __half* cur = tiles + (lc % 3)*16*TLDH;
        if (lc < 15) asm volatile("cp.async.wait_group 1;");
        else         asm volatile("cp.async.wait_group 0;");
        __syncthreads();
        if (lc + 2 <= 15) issue_chunk(lc + 2);

        {
            wmma::fragment<wmma::accumulator, 16, 16, 16, float> d;
            wmma::fill_fragment(d, 0.f);
            #pragma unroll
            for (int ks = 0; ks < 4; ks++) {
                int k = w*64 + ks*16;
                wmma::fragment<wmma::matrix_a, 16, 16, 16, __half, wmma::row_major> af;
                wmma::load_matrix_sync(af, cur + k, TLDH);
                wmma::fragment<wmma::matrix_b, 16, 16, 16, __half, wmma::col_major> bf;
                wmma::load_matrix_sync(bf, qkw_s + k, TLDH);
                wmma::mma_sync(d, af, bf, d);
            }
            wmma::store_matrix_sync(Dpart + w*16*DLD, d, DLD, wmma::mem_row_major);
        }
        __syncthreads();

        if (tid < 192) {
            int r = tid / 12, hh = tid - r*12;
            float s = 0.f;
            #pragma unroll
            for (int w2 = 0; w2 < 12; w2++) s += Dpart[w2*16*DLD + r*DLD + hh];
            float e = __expf(s);
            e_s[r*12 + hh] = e;
            e_hr[hh*ELDH + r] = __float2half(e);
        }
        __syncthreads();

        if (tid < NH) {
            float dsum = 0.f;
            #pragma unroll
            for (int r = 0; r < 16; r++) dsum += e_s[r*12 + tid];
            denom[tid] += dsum;
        }

        {
            wmma::fragment<wmma::matrix_a, 16, 16, 16, __half, wmma::row_major> ef;
            wmma::load_matrix_sync(ef, e_hr, ELDH);
            #pragma unroll
            for (int ct = 0; ct < 4; ct++) {
                wmma::fragment<wmma::matrix_b, 16, 16, 16, __half, wmma::row_major> vb;
                wmma::load_matrix_sync(vb, cur + w*64 + ct*16, TLDH);
                wmma::mma_sync(av[ct], ef, vb, av[ct]);
            }
        }
    }

    __syncthreads();
    float* stage = (float*)smh;                // [16][772]
    #pragma unroll
    for (int ct = 0; ct < 4; ct++)
        wmma::store_matrix_sync(stage + w*64 + ct*16, av[ct], 772, wmma::mem_row_major);
    __syncthreads();

    float4 d0 = *(const float4*)(denom);
    float4 d1 = *(const float4*)(denom + 4);
    float4 d2 = *(const float4*)(denom + 8);
    float inv[NH] = {1.f/d0.x, 1.f/d0.y, 1.f/d0.z, 1.f/d0.w,
                     1.f/d1.x, 1.f/d1.y, 1.f/d1.z, 1.f/d1.w,
                     1.f/d2.x, 1.f/d2.y, 1.f/d2.z, 1.f/d2.w};
    #pragma unroll
    for (int hh = 0; hh < NH; hh++) {
        float a = stage[hh*772 + tid*2]     * inv[hh];
        float c = stage[hh*772 + tid*2 + 1] * inv[hh];
        *(__half2*)(g_avnh + (size_t)bn*(NH*Dm) + hh*768 + tid*2) = __floats2half2_rn(a, c);
    }
}

// ---------------- host ----------------
extern "C" void kernel_launch(void* const* d_in, const int* in_sizes, int n_in,
                              void* d_out, int out_size)
{
    const float* x     = (const float*)d_in[0];
    const float* w_in  = (const float*)d_in[1];
    const float* b_in  = (const float*)d_in[2];
    const float* w_out = (const float*)d_in[3];
    const float* b_out = (const float*)d_in[4];
    const float* w_fc1 = (const float*)d_in[5];
    const float* b_fc1 = (const float*)d_in[6];
    const float* w_fc2 = (const float*)d_in[7];
    const float* b_fc2 = (const float*)d_in[8];
    float* y = (float*)d_out;

    __half *qh, *qph, *qkwh, *avnh, *ctxh, *o1h, *h1h, *wh;
    float *part;
    cudaGetSymbolAddress((void**)&qh,   g_qh);
    cudaGetSymbolAddress((void**)&qph,  g_qph);
    cudaGetSymbolAddress((void**)&qkwh, g_qkwh);
    cudaGetSymbolAddress((void**)&avnh, g_avnh);
    cudaGetSymbolAddress((void**)&ctxh, g_ctxh);
    cudaGetSymbolAddress((void**)&o1h,  g_o1h);
    cudaGetSymbolAddress((void**)&h1h,  g_h1h);
    cudaGetSymbolAddress((void**)&wh,   g_wh);
    cudaGetSymbolAddress((void**)&part, g_part);

    const int GSMEM = 2*18432*2;
    cudaFuncSetAttribute(gemm128, cudaFuncAttributeMaxDynamicSharedMemorySize, GSMEM);

    // 0. weight conversion
    f2h_all<<<(W_TOTAL/4 + 255)/256, 256>>>(w_in, w_out, w_fc1, w_fc2, wh);

    // 1. token means + x->fp16 (vectorized)
    mean_kernel<<<Bb*Dm*Tt, 224>>>(x);

    // 2. qp = (q @ wq^T + bq)*0.125  (fused epilogue, no split-K)
    gemm_hc<true><<<dim3(12,13,1), 256>>>(qh, wh + W_IN_OFF, b_in, nullptr, qph,
        BN, Dm, Dm, Dm, Dm, Dm, 0,0,0,0, 0.125f, 0);

    // 3. qkw  (batched heads, K=64)
    gemm_hc<false><<<dim3(12,13,NH), 256>>>(qph, wh + W_IN_OFF + Dm*Dm, nullptr, nullptr, qkwh,
        BN, Dm, HD, Dm, Dm, NH*Dm, HD, HD*Dm, Dm, 0, 1.f, 0);

    // 4. fused attention
    {
        static const size_t smem = 110080;
        cudaFuncSetAttribute(attn7, cudaFuncAttributeMaxDynamicSharedMemorySize, (int)smem);
        attn7<<<BN, 384, smem>>>();
    }

    // 5. ctx  (batched heads)
    gemm_hc<true><<<dim3(1,13,NH), 256>>>(avnh, wh + W_IN_OFF + 2*Dm*Dm, b_in + 2*Dm, nullptr, ctxh,
        BN, HD, Dm, NH*Dm, Dm, Dm, Dm, HD*Dm, HD, HD, 1.f, 0);

    // 6. o1 = ctx @ w_out^T + b_out  (fused epilogue)
    gemm_hc<true><<<dim3(12,13,1), 256>>>(ctxh, wh + W_OUT_OFF, b_out, nullptr, o1h,
        BN, Dm, Dm, Dm, Dm, Dm, 0,0,0,0, 1.f, 0);

    // 7. h1 = silu(o1 @ w_fc1^T + b_fc1)  — gemm128 fused epilogue
    gemm128<<<dim3(24,7,1), 256, GSMEM>>>(o1h, wh + W_FC1_OFF, part, BN, FFD, Dm, Dm, Dm, 1,
                                          b_fc1, h1h, 1);

    // 8. y = h1 @ w_fc2^T + b_fc2  (split-K 4, fp32 out)
    gemm128<<<dim3(6,7,4), 256, GSMEM>>>(h1h, wh + W_FC2_OFF, part, BN, Dm, FFD, FFD, FFD, 4,
                                         nullptr, nullptr, 0);
    epi_kernel<<<(BN*Dm/4 + 255)/256, 256>>>(part, b_fc2, y, nullptr, BN*Dm, Dm, 4, 1.f, 0);
}

// round 14
// speedup vs baseline: 9.9330x; 1.0267x over previous
#include <cuda_runtime.h>
#include <cuda_fp16.h>
#include <math.h>
#include <stdint.h>
#include <mma.h>

using namespace nvcuda;

#define Bb   4
#define Dm   768
#define Tt   14
#define Np   196
#define NH   12
#define HD   64
#define FFD  3072
#define BN   (Bb*Np)       // 784
#define HW   224
#define CHW  (HW*HW)       // 50176
#define MP   896           // padded M for 128-tiles

#define TLDH 776           // padded fp16 tile stride (conflict-free, 16B-aligned)
#define DLD  20
#define ELDH 24

// ---------------- scratch ----------------
__device__ __half g_xh [(size_t)Bb*Dm*CHW];
__device__ __half g_qh [BN*Dm];
__device__ __half g_qph[BN*Dm];
__device__ __half g_qkwh[BN*NH*Dm];
__device__ __half g_avnh[BN*NH*Dm];
__device__ __half g_ctxh[BN*Dm];
__device__ __half g_o1h[BN*Dm];
__device__ __half g_h1h[BN*FFD];
__device__ float  g_part[(size_t)4*MP*Dm];      // split-K partials (fc2 only)
#define W_IN_OFF   0
#define W_OUT_OFF  (3*Dm*Dm)
#define W_FC1_OFF  (W_OUT_OFF + Dm*Dm)
#define W_FC2_OFF  (W_FC1_OFF + FFD*Dm)
#define W_TOTAL    (W_FC2_OFF + Dm*FFD)
__device__ __half g_wh[W_TOTAL];

#define MEAN_BLOCKS (Bb*Dm*Tt)                   // 43008
#define F2H_CHUNKS  (W_TOTAL/4)                  // 1769472
#define F2H_BLOCKS  ((F2H_CHUNKS + 223)/224)     // 7900

__device__ __forceinline__ void cp_async16(uint32_t dst, const void* src) {
    asm volatile("cp.async.cg.shared.global [%0], [%1], 16;" :: "r"(dst), "l"(src));
}

// ---------------- fused prep: token means + x->fp16 + weight conversion ----------------
// blocks [0, MEAN_BLOCKS): mean work;  blocks [MEAN_BLOCKS, ...): f2h work (overlapped).
__global__ void prep_kernel(const float* __restrict__ x,
                            const float* __restrict__ s0, const float* __restrict__ s1,
                            const float* __restrict__ s2, const float* __restrict__ s3,
                            __half* __restrict__ wd) {
    int bid = blockIdx.x;
    if (bid >= MEAN_BLOCKS) {
        // ---- f2h part ----
        int chunk = (bid - MEAN_BLOCKS)*224 + threadIdx.x;
        int i = chunk*4;
        if (i >= W_TOTAL) return;
        const float* s; int off;
        if      (i < W_OUT_OFF) { s = s0; off = 0; }
        else if (i < W_FC1_OFF) { s = s1; off = W_OUT_OFF; }
        else if (i < W_FC2_OFF) { s = s2; off = W_FC1_OFF; }
        else                    { s = s3; off = W_FC2_OFF; }
        float4 v = *(const float4*)(s + (i - off));
        ((__half2*)(wd + i))[0] = __floats2half2_rn(v.x, v.y);
        ((__half2*)(wd + i))[1] = __floats2half2_rn(v.z, v.w);
        return;
    }
    // ---- mean part ----
    int t1 = bid % Tt;
    int dd = (bid / Tt) % Dm;
    int b  = bid / (Tt * Dm);
    size_t base = ((size_t)b*Dm + dd)*CHW + (size_t)t1*16*HW;
    const float4* xp = (const float4*)(x + base);   // 56 float4 per row
    __half* xo = g_xh + base;

    int t  = threadIdx.x;      // 0..223
    int qi = t % 56;
    int rg = t / 56;           // 0..3

    float4 acc = make_float4(0.f, 0.f, 0.f, 0.f);
    #pragma unroll
    for (int k = 0; k < 4; k++) {
        int r = rg*4 + k;
        float4 v = xp[r*56 + qi];
        acc.x += v.x; acc.y += v.y; acc.z += v.z; acc.w += v.w;
        __half2 h0 = __floats2half2_rn(v.x, v.y);
        __half2 h1 = __floats2half2_rn(v.z, v.w);
        uint2 u;
        u.x = *(uint32_t*)&h0;
        u.y = *(uint32_t*)&h1;
        *(uint2*)(xo + (size_t)r*HW + qi*4) = u;
    }

    __shared__ float4 ps[224];
    __shared__ float qsum[56];
    ps[t] = acc;
    __syncthreads();
    if (t < 56) {
        float s = 0.f;
        #pragma unroll
        for (int r2 = 0; r2 < 4; r2++) {
            float4 v = ps[r2*56 + t];
            s += v.x + v.y + v.z + v.w;
        }
        qsum[t] = s;
    }
    __syncthreads();
    if (t < Tt) {
        float s = qsum[4*t] + qsum[4*t+1] + qsum[4*t+2] + qsum[4*t+3];
        g_qh[((size_t)b*Np + t1*Tt + t)*Dm + dd] = __float2half(s * (1.0f/256.0f));
    }
}

// ---------------- 128x128 fp16 GEMM (TRANSB) ----------------
// bias==null: raw fp32 partials to P[z][MP][N] (split-K via z).
// bias!=null (KS must be 1): fused bias(+silu) epilogue -> fp16 out16.
__global__ __launch_bounds__(256) void gemm128(
    const __half* __restrict__ A, const __half* __restrict__ Bm,
    float* __restrict__ P, int M, int N, int K, int lda, int ldb, int KS,
    const float* __restrict__ bias, __half* __restrict__ out16, int silu)
{
    extern __shared__ __half dbuf[];
    uint32_t sb = (uint32_t)__cvta_generic_to_shared(dbuf);

    int m0 = blockIdx.y * 128, n0 = blockIdx.x * 128;
    int z = blockIdx.z;
    int Ksub = K / KS;
    int kbase = z * Ksub;
    int tid = threadIdx.x;
    int warpId = tid >> 5;
    int wm = warpId >> 2;
    int wn = warpId & 3;

    wmma::fragment<wmma::accumulator, 16, 16, 16, float> acc[4][2];
    #pragma unroll
    for (int i = 0; i < 4; i++)
        #pragma unroll
        for (int j = 0; j < 2; j++) wmma::fill_fragment(acc[i][j], 0.f);

    const int nk = Ksub >> 6;

    auto issue = [&](int it, int s) {
        int k0 = kbase + it*64;
        uint32_t abase = sb + (uint32_t)(s * 18432 * 2);
        uint32_t bbase = abase + 9216*2;
        #pragma unroll
        for (int i = 0; i < 4; i++) {
            int idx = tid + 256*i;
            int row = idx >> 3, seg = idx & 7;
            int m = m0 + row; if (m >= M) m = M - 1;
            cp_async16(abase + (uint32_t)((row*72 + seg*8)*2),
                       A + (size_t)m*lda + k0 + seg*8);
        }
        #pragma unroll
        for (int i = 0; i < 4; i++) {
            int idx = tid + 256*i;
            int nn = idx >> 3, seg = idx & 7;
            int ng = n0 + nn; if (ng >= N) ng = N - 1;
            cp_async16(bbase + (uint32_t)((nn*72 + seg*8)*2),
                       Bm + (size_t)ng*ldb + k0 + seg*8);
        }
        asm volatile("cp.async.commit_group;");
    };

    issue(0, 0);

    for (int it = 0; it < nk; it++) {
        int s = it & 1;
        if (it + 1 < nk) {
            issue(it+1, s^1);
            asm volatile("cp.async.wait_group 1;");
        } else {
            asm volatile("cp.async.wait_group 0;");
        }
        __syncthreads();

        const __half* As = dbuf + s*18432;
        const __half* Bs = As + 9216;

        #pragma unroll
        for (int ks = 0; ks < 4; ks++) {
            wmma::fragment<wmma::matrix_b, 16, 16, 16, __half, wmma::col_major> bf[2];
            #pragma unroll
            for (int j = 0; j < 2; j++)
                wmma::load_matrix_sync(bf[j], Bs + (wn*32 + j*16)*72 + ks*16, 72);
            #pragma unroll
            for (int i = 0; i < 4; i++) {
                wmma::fragment<wmma::matrix_a, 16, 16, 16, __half, wmma::row_major> af;
                wmma::load_matrix_sync(af, As + (wm*64 + i*16)*72 + ks*16, 72);
                #pragma unroll
                for (int j = 0; j < 2; j++)
                    wmma::mma_sync(acc[i][j], af, bf[j], acc[i][j]);
            }
        }
        __syncthreads();
    }

    if (!bias) {
        float* base = P + (size_t)z*MP*N;
        #pragma unroll
        for (int i = 0; i < 4; i++)
            #pragma unroll
            for (int j = 0; j < 2; j++)
                wmma::store_matrix_sync(base + (size_t)(m0 + wm*64 + i*16)*N + n0 + wn*32 + j*16,
                                        acc[i][j], N, wmma::mem_row_major);
    } else {
        float* Cs = (float*)dbuf;          // [128][132]
        #pragma unroll
        for (int i = 0; i < 4; i++)
            #pragma unroll
            for (int j = 0; j < 2; j++)
                wmma::store_matrix_sync(Cs + (wm*64 + i*16)*132 + wn*32 + j*16,
                                        acc[i][j], 132, wmma::mem_row_major);
        __syncthreads();
        #pragma unroll
        for (int i = 0; i < 16; i++) {
            int e = tid + 256*i;
            int row = e >> 5, seg = e & 31;
            int m = m0 + row, nb = n0 + seg*4;
            if (m >= M || nb >= N) continue;
            float4 v = *(const float4*)(Cs + row*132 + seg*4);
            float4 bv = *(const float4*)(bias + nb);
            v.x += bv.x; v.y += bv.y; v.z += bv.z; v.w += bv.w;
            if (silu) {
                v.x = v.x/(1.f+__expf(-v.x)); v.y = v.y/(1.f+__expf(-v.y));
                v.z = v.z/(1.f+__expf(-v.z)); v.w = v.w/(1.f+__expf(-v.w));
            }
            __half2* dst = (__half2*)(out16 + (size_t)m*N + nb);
            dst[0] = __floats2half2_rn(v.x, v.y);
            dst[1] = __floats2half2_rn(v.z, v.w);
        }
    }
}

// ---------------- split-K epilogue (fc2 only) ----------------
__global__ void epi_kernel(const float* __restrict__ P, const float* __restrict__ bias,
                           float* __restrict__ out32, __half* __restrict__ out16,
                           int MN, int N, int KS, float gamma, int silu)
{
    int i = (blockIdx.x*256 + threadIdx.x)*4;
    if (i >= MN) return;
    int c = i % N;
    float4 s = *(const float4*)(P + i);
    for (int ks = 1; ks < KS; ks++) {
        float4 p = *(const float4*)(P + (size_t)ks*MP*N + i);
        s.x += p.x; s.y += p.y; s.z += p.z; s.w += p.w;
    }
    float4 bv = *(const float4*)(bias + c);
    s.x = (s.x + bv.x)*gamma; s.y = (s.y + bv.y)*gamma;
    s.z = (s.z + bv.z)*gamma; s.w = (s.w + bv.w)*gamma;
    if (silu) {
        s.x = s.x/(1.f+__expf(-s.x)); s.y = s.y/(1.f+__expf(-s.y));
        s.z = s.z/(1.f+__expf(-s.z)); s.w = s.w/(1.f+__expf(-s.w));
    }
    if (out32) *(float4*)(out32 + i) = s;
    if (out16) {
        ((__half2*)(out16 + i))[0] = __floats2half2_rn(s.x, s.y);
        ((__half2*)(out16 + i))[1] = __floats2half2_rn(s.z, s.w);
    }
}

// ---------------- 64x64 fp16 GEMM (qp / qkw / ctx / o1; fused epilogue) ----------------
template<bool TRANSB>
__global__ __launch_bounds__(256) void gemm_hc(
    const __half* __restrict__ A, const __half* __restrict__ Bm,
    const float* __restrict__ bias, float* __restrict__ C32, __half* __restrict__ C16,
    int M, int N, int K, int lda, int ldb, int ldc,
    int sAh, int sBh, int sCh, int sBiasH,
    float gamma, int silu)
{
    int h = blockIdx.z;
    A  += (size_t)h * sAh;
    Bm += (size_t)h * sBh;
    const float* biasp = bias ? bias + (size_t)h * sBiasH : nullptr;

    __shared__ __half hbuf[2*2*64*72];
    uint32_t sb = (uint32_t)__cvta_generic_to_shared(hbuf);

    int m0 = blockIdx.y * 64, n0 = blockIdx.x * 64;
    int tid = threadIdx.x;
    int warpId = tid >> 5;
    int wm = warpId >> 1;
    int wn = warpId & 1;

    wmma::fragment<wmma::accumulator, 16, 16, 16, float> cf[2];
    wmma::fill_fragment(cf[0], 0.f);
    wmma::fill_fragment(cf[1], 0.f);

    const int nk = K >> 6;

    auto issue = [&](int it, int s) {
        int k0 = it * 64;
        uint32_t abase = sb + (uint32_t)(s * 9216 * 2);
        uint32_t bbase = abase + 4608*2;
        #pragma unroll
        for (int i = 0; i < 2; i++) {
            int idx = tid + 256*i;
            int row = idx >> 3, seg = idx & 7;
            int m = m0 + row; if (m >= M) m = M - 1;
            cp_async16(abase + (uint32_t)((row*72 + seg*8)*2),
                       A + (size_t)m*lda + k0 + seg*8);
        }
        if (TRANSB) {
            #pragma unroll
            for (int i = 0; i < 2; i++) {
                int idx = tid + 256*i;
                int nn = idx >> 3, seg = idx & 7;
                int ng = n0 + nn; if (ng >= N) ng = N - 1;
                cp_async16(bbase + (uint32_t)((nn*72 + seg*8)*2),
                           Bm + (size_t)ng*ldb + k0 + seg*8);
            }
        } else {
            #pragma unroll
            for (int i = 0; i < 2; i++) {
                int idx = tid + 256*i;
                int kk = idx >> 3, seg = idx & 7;
                int nb = n0 + seg*8; if (nb >= N) nb = 0;
                cp_async16(bbase + (uint32_t)((kk*72 + seg*8)*2),
                           Bm + (size_t)(k0+kk)*ldb + nb);
            }
        }
        asm volatile("cp.async.commit_group;");
    };

    issue(0, 0);

    for (int it = 0; it < nk; it++) {
        int s = it & 1;
        if (it + 1 < nk) {
            issue(it+1, s^1);
            asm volatile("cp.async.wait_group 1;");
        } else {
            asm volatile("cp.async.wait_group 0;");
        }
        __syncthreads();

        const __half* As = hbuf + s*9216;
        const __half* Bs = As + 4608;

        #pragma unroll
        for (int ks = 0; ks < 4; ks++) {
            wmma::fragment<wmma::matrix_a, 16, 16, 16, __half, wmma::row_major> af;
            wmma::load_matrix_sync(af, As + (wm*16)*72 + ks*16, 72);
            #pragma unroll
            for (int j = 0; j < 2; j++) {
                if (TRANSB) {
                    wmma::fragment<wmma::matrix_b, 16, 16, 16, __half, wmma::col_major> bf;
                    wmma::load_matrix_sync(bf, Bs + (wn*32 + j*16)*72 + ks*16, 72);
                    wmma::mma_sync(cf[j], af, bf, cf[j]);
                } else {
                    wmma::fragment<wmma::matrix_b, 16, 16, 16, __half, wmma::row_major> bf;
                    wmma::load_matrix_sync(bf, Bs + (ks*16)*72 + wn*32 + j*16, 72);
                    wmma::mma_sync(cf[j], af, bf, cf[j]);
                }
            }
        }
        __syncthreads();
    }

    float (*Cs)[68] = (float(*)[68])hbuf;
    wmma::store_matrix_sync(&Cs[wm*16][wn*32],      cf[0], 68, wmma::mem_row_major);
    wmma::store_matrix_sync(&Cs[wm*16][wn*32 + 16], cf[1], 68, wmma::mem_row_major);
    __syncthreads();

    #pragma unroll
    for (int i = 0; i < 4; i++) {
        int e = tid + 256*i;
        int row = e >> 4, seg = e & 15;
        int m = m0 + row, nbase = n0 + seg*4;
        if (m >= M || nbase >= N) continue;
        float4 v = *(const float4*)&Cs[row][seg*4];
        if (biasp) {
            float4 bv = *(const float4*)(biasp + nbase);
            v.x += bv.x; v.y += bv.y; v.z += bv.z; v.w += bv.w;
        }
        v.x *= gamma; v.y *= gamma; v.z *= gamma; v.w *= gamma;
        if (silu) {
            v.x = v.x/(1.f+__expf(-v.x)); v.y = v.y/(1.f+__expf(-v.y));
            v.z = v.z/(1.f+__expf(-v.z)); v.w = v.w/(1.f+__expf(-v.w));
        }
        if (C32) *(float4*)(C32 + (size_t)m*ldc + nbase + (size_t)h*sCh) = v;
        if (C16) {
            __half2* dst = (__half2*)(C16 + (size_t)m*ldc + nbase + (size_t)h*sCh);
            dst[0] = __floats2half2_rn(v.x, v.y);
            dst[1] = __floats2half2_rn(v.z, v.w);
        }
    }
}

// ---------------- fused attention v7c: register denominators ----------------
__global__ __launch_bounds__(384, 2) void attn7() {
    extern __shared__ __half smh[];
    __half* qkw_s = smh;
    __half* tiles = smh + 12*TLDH;
    float*  Dpart = (float*)(smh + 12*TLDH + 3*16*TLDH);
    float*  e_s   = Dpart + 12*16*DLD;           // used only for final denom reduce
    __half* e_hr  = (__half*)(e_s + 192);
    float*  denom = (float*)(e_hr + 16*ELDH);

    int bn = blockIdx.x;
    int b = bn / Np, n = bn % Np;
    int t1 = n / Tt, t2 = n % Tt;
    const __half* xph = g_xh + (size_t)b*Dm*CHW + (size_t)(t1*16)*HW + t2*16;

    int tid = threadIdx.x, w = tid >> 5;

    auto issue_chunk = [&](int lc) {
        uint32_t stp = (uint32_t)__cvta_generic_to_shared(tiles + (lc % 3)*16*TLDH);
        #pragma unroll
        for (int j = 0; j < 4; j++) {
            int ch = tid + 384*j;
            int idx8 = ch*8;
            int r = idx8 / 768, cc = idx8 - r*768;
            int flat = lc*12288 + idx8;
            int dd = flat >> 8, g1 = (flat >> 4) & 15, g2 = flat & 15;
            cp_async16(stp + (uint32_t)((r*TLDH + cc)*2), xph + (size_t)dd*CHW + g1*HW + g2);
        }
        asm volatile("cp.async.commit_group;");
    };

    issue_chunk(0);
    issue_chunk(1);

    {
        const __half* src = g_qkwh + (size_t)bn*(NH*Dm);
        #pragma unroll
        for (int i = 0; i < 3; i++) {
            int idx = tid + 384*i;
            int hh = idx / 96, rem = idx - hh*96;
            *(float4*)(qkw_s + hh*TLDH + rem*8) = *(const float4*)(src + idx*8);
        }
    }
    if (tid < 16*ELDH) e_hr[tid] = __float2half(0.f);

    float myden = 0.f;                 // per-thread denominator partial (tid<192: owns (r,hh))
    int my_r = tid / 12, my_h = tid - my_r*12;

    wmma::fragment<wmma::accumulator, 16, 16, 16, float> av[4];
    #pragma unroll
    for (int ct = 0; ct < 4; ct++) wmma::fill_fragment(av[ct], 0.f);

    for (int lc = 0; lc < 16; lc++) {
        const __half* cur = tiles + (lc % 3)*16*TLDH;
        if (lc < 15) asm volatile("cp.async.wait_group 1;");
        else         asm volatile("cp.async.wait_group 0;");
        __syncthreads();
        if (lc + 2 <= 15) issue_chunk(lc + 2);

        {
            wmma::fragment<wmma::accumulator, 16, 16, 16, float> d;
            wmma::fill_fragment(d, 0.f);
            #pragma unroll
            for (int ks = 0; ks < 4; ks++) {
                int k = w*64 + ks*16;
                wmma::fragment<wmma::matrix_a, 16, 16, 16, __half, wmma::row_major> af;
                wmma::load_matrix_sync(af, cur + k, TLDH);
                wmma::fragment<wmma::matrix_b, 16, 16, 16, __half, wmma::col_major> bf;
                wmma::load_matrix_sync(bf, qkw_s + k, TLDH);
                wmma::mma_sync(d, af, bf, d);
            }
            wmma::store_matrix_sync(Dpart + w*16*DLD, d, DLD, wmma::mem_row_major);
        }
        __syncthreads();

        if (tid < 192) {
            float s = 0.f;
            #pragma unroll
            for (int w2 = 0; w2 < 12; w2++) s += Dpart[w2*16*DLD + my_r*DLD + my_h];
            float e = __expf(s);
            myden += e;
            e_hr[my_h*ELDH + my_r] = __float2half(e);
        }
        __syncthreads();

        {
            wmma::fragment<wmma::matrix_a, 16, 16, 16, __half, wmma::row_major> ef;
            wmma::load_matrix_sync(ef, e_hr, ELDH);
            #pragma unroll
            for (int ct = 0; ct < 4; ct++) {
                wmma::fragment<wmma::matrix_b, 16, 16, 16, __half, wmma::row_major> vb;
                wmma::load_matrix_sync(vb, cur + w*64 + ct*16, TLDH);
                wmma::mma_sync(av[ct], ef, vb, av[ct]);
            }
        }
    }

    // finalize denominators
    if (tid < 192) e_s[tid] = myden;
    __syncthreads();
    if (tid < NH) {
        float d = 0.f;
        #pragma unroll
        for (int r = 0; r < 16; r++) d += e_s[r*12 + tid];
        denom[tid] = d;
    }

    // stage AV accumulators (front of smem, free now), normalize, write fp16
    float* stage = (float*)smh;                // [16][772]
    #pragma unroll
    for (int ct = 0; ct < 4; ct++)
        wmma::store_matrix_sync(stage + w*64 + ct*16, av[ct], 772, wmma::mem_row_major);
    __syncthreads();

    float4 d0 = *(const float4*)(denom);
    float4 d1 = *(const float4*)(denom + 4);
    float4 d2 = *(const float4*)(denom + 8);
    float inv[NH] = {1.f/d0.x, 1.f/d0.y, 1.f/d0.z, 1.f/d0.w,
                     1.f/d1.x, 1.f/d1.y, 1.f/d1.z, 1.f/d1.w,
                     1.f/d2.x, 1.f/d2.y, 1.f/d2.z, 1.f/d2.w};
    #pragma unroll
    for (int hh = 0; hh < NH; hh++) {
        float a = stage[hh*772 + tid*2]     * inv[hh];
        float c = stage[hh*772 + tid*2 + 1] * inv[hh];
        *(__half2*)(g_avnh + (size_t)bn*(NH*Dm) + hh*768 + tid*2) = __floats2half2_rn(a, c);
    }
}

// ---------------- host ----------------
extern "C" void kernel_launch(void* const* d_in, const int* in_sizes, int n_in,
                              void* d_out, int out_size)
{
    const float* x     = (const float*)d_in[0];
    const float* w_in  = (const float*)d_in[1];
    const float* b_in  = (const float*)d_in[2];
    const float* w_out = (const float*)d_in[3];
    const float* b_out = (const float*)d_in[4];
    const float* w_fc1 = (const float*)d_in[5];
    const float* b_fc1 = (const float*)d_in[6];
    const float* w_fc2 = (const float*)d_in[7];
    const float* b_fc2 = (const float*)d_in[8];
    float* y = (float*)d_out;

    __half *qh, *qph, *qkwh, *avnh, *ctxh, *o1h, *h1h, *wh;
    float *part;
    cudaGetSymbolAddress((void**)&qh,   g_qh);
    cudaGetSymbolAddress((void**)&qph,  g_qph);
    cudaGetSymbolAddress((void**)&qkwh, g_qkwh);
    cudaGetSymbolAddress((void**)&avnh, g_avnh);
    cudaGetSymbolAddress((void**)&ctxh, g_ctxh);
    cudaGetSymbolAddress((void**)&o1h,  g_o1h);
    cudaGetSymbolAddress((void**)&h1h,  g_h1h);
    cudaGetSymbolAddress((void**)&wh,   g_wh);
    cudaGetSymbolAddress((void**)&part, g_part);

    const int GSMEM = 2*18432*2;
    cudaFuncSetAttribute(gemm128, cudaFuncAttributeMaxDynamicSharedMemorySize, GSMEM);

    // 0+1. fused weight conversion + token means + x->fp16
    prep_kernel<<<MEAN_BLOCKS + F2H_BLOCKS, 224>>>(x, w_in, w_out, w_fc1, w_fc2, wh);

    // 2. qp = (q @ wq^T + bq)*0.125  (fused epilogue)
    gemm_hc<true><<<dim3(12,13,1), 256>>>(qh, wh + W_IN_OFF, b_in, nullptr, qph,
        BN, Dm, Dm, Dm, Dm, Dm, 0,0,0,0, 0.125f, 0);

    // 3. qkw  (batched heads, K=64)
    gemm_hc<false><<<dim3(12,13,NH), 256>>>(qph, wh + W_IN_OFF + Dm*Dm, nullptr, nullptr, qkwh,
        BN, Dm, HD, Dm, Dm, NH*Dm, HD, HD*Dm, Dm, 0, 1.f, 0);

    // 4. fused attention
    {
        static const size_t smem = 110080;
        cudaFuncSetAttribute(attn7, cudaFuncAttributeMaxDynamicSharedMemorySize, (int)smem);
        attn7<<<BN, 384, smem>>>();
    }

    // 5. ctx  (batched heads)
    gemm_hc<true><<<dim3(1,13,NH), 256>>>(avnh, wh + W_IN_OFF + 2*Dm*Dm, b_in + 2*Dm, nullptr, ctxh,
        BN, HD, Dm, NH*Dm, Dm, Dm, Dm, HD*Dm, HD, HD, 1.f, 0);

    // 6. o1 = ctx @ w_out^T + b_out  (fused epilogue)
    gemm_hc<true><<<dim3(12,13,1), 256>>>(ctxh, wh + W_OUT_OFF, b_out, nullptr, o1h,
        BN, Dm, Dm, Dm, Dm, Dm, 0,0,0,0, 1.f, 0);

    // 7. h1 = silu(o1 @ w_fc1^T + b_fc1)  — gemm128 fused epilogue
    gemm128<<<dim3(24,7,1), 256, GSMEM>>>(o1h, wh + W_FC1_OFF, part, BN, FFD, Dm, Dm, Dm, 1,
                                          b_fc1, h1h, 1);

    // 8. y = h1 @ w_fc2^T + b_fc2  (split-K 4, fp32 out)
    gemm128<<<dim3(6,7,4), 256, GSMEM>>>(h1h, wh + W_FC2_OFF, part, BN, Dm, FFD, FFD, FFD, 4,
                                         nullptr, nullptr, 0);
    epi_kernel<<<(BN*Dm/4 + 255)/256, 256>>>(part, b_fc2, y, nullptr, BN*Dm, Dm, 4, 1.f, 0);
}